// round 1
// baseline (speedup 1.0000x reference)
#include <cuda_runtime.h>
#include <math.h>

// Problem constants
#define Bsz 4
#define Tsz 2048
#define Csz 1024
#define Hsz 16
#define Dsz 64
#define M1 (Bsz * Tsz)        // 8192 rows for both GEMMs

// Scratch (static device globals; allocation-free)
__device__ float g_q[Bsz * Hsz * Tsz * Dsz];   // (B,H,T,D)
__device__ float g_k[Bsz * Hsz * Tsz * Dsz];
__device__ float g_v[Bsz * Hsz * Tsz * Dsz];
__device__ float g_y[M1 * Csz];                // (B,T,C) pre-projection

// ---------------------------------------------------------------------------
// SGEMM: C = A(MxK) @ B(KxN) + bias, 128x128 tile, BK=16, 256 thr, 8x8/thread
// MODE 0: scatter epilogue -> g_q/g_k/g_v with (B,H,T,D) layout
// MODE 1: plain row-major store to Cout
// ---------------------------------------------------------------------------
#define GBM 128
#define GBN 128
#define GBK 16

template <int MODE>
__global__ __launch_bounds__(256)
void sgemm_kernel(const float* __restrict__ A, const float* __restrict__ Bm,
                  const float* __restrict__ bias, float* __restrict__ Cout,
                  int M, int N, int K)
{
    __shared__ float As[GBK][GBM + 4];
    __shared__ float Bs[GBK][GBN + 4];

    const int tid = threadIdx.x;
    const int m0 = blockIdx.y * GBM;
    const int n0 = blockIdx.x * GBN;
    const int ty = tid >> 4;   // 0..15
    const int tx = tid & 15;   // 0..15

    float acc[8][8];
#pragma unroll
    for (int i = 0; i < 8; i++)
#pragma unroll
        for (int j = 0; j < 8; j++) acc[i][j] = 0.f;

    for (int k0 = 0; k0 < K; k0 += GBK) {
        // Load A tile 128x16 (transposed into As[k][m]) : 2 float4 per thread
#pragma unroll
        for (int r = 0; r < 2; r++) {
            int f = tid + r * 256;            // 0..511
            int row = f >> 2;
            int kq  = (f & 3) * 4;
            float4 v4 = *(const float4*)&A[(size_t)(m0 + row) * K + k0 + kq];
            As[kq + 0][row] = v4.x;
            As[kq + 1][row] = v4.y;
            As[kq + 2][row] = v4.z;
            As[kq + 3][row] = v4.w;
        }
        // Load B tile 16x128 : 2 float4 per thread
#pragma unroll
        for (int r = 0; r < 2; r++) {
            int f = tid + r * 256;
            int row = f >> 5;
            int c4  = (f & 31) * 4;
            *(float4*)&Bs[row][c4] = *(const float4*)&Bm[(size_t)(k0 + row) * N + n0 + c4];
        }
        __syncthreads();

#pragma unroll
        for (int kk = 0; kk < GBK; kk++) {
            float a[8], b[8];
#pragma unroll
            for (int i = 0; i < 8; i++) a[i] = As[kk][ty * 8 + i];
#pragma unroll
            for (int j = 0; j < 8; j++) b[j] = Bs[kk][tx * 8 + j];
#pragma unroll
            for (int i = 0; i < 8; i++)
#pragma unroll
                for (int j = 0; j < 8; j++) acc[i][j] = fmaf(a[i], b[j], acc[i][j]);
        }
        __syncthreads();
    }

    if (MODE == 0) {
        // qkv scatter: n -> (which, h, d); m -> (b, t); write (B,H,T,D)
        const int bidx = m0 >> 11;                 // tile fully inside one batch (T=2048)
        const int which = n0 >> 10;                // tile fully inside one of q/k/v (1024 cols)
        float* dst = (which == 0) ? g_q : (which == 1) ? g_k : g_v;
#pragma unroll
        for (int i = 0; i < 8; i++) {
            int m = m0 + ty * 8 + i;
            int t = m & (Tsz - 1);
#pragma unroll
            for (int j = 0; j < 8; j++) {
                int n = n0 + tx * 8 + j;
                int h = (n >> 6) & (Hsz - 1);
                int d = n & (Dsz - 1);
                float val = acc[i][j] + bias[n];
                dst[(((size_t)(bidx * Hsz + h) * Tsz) + t) * Dsz + d] = val;
            }
        }
    } else {
#pragma unroll
        for (int i = 0; i < 8; i++) {
            int m = m0 + ty * 8 + i;
#pragma unroll
            for (int j = 0; j < 8; j++) {
                int n = n0 + tx * 8 + j;
                Cout[(size_t)m * N + n] = acc[i][j] + bias[n];
            }
        }
    }
}

// ---------------------------------------------------------------------------
// RoPE (in-place on g_q, g_k). inv_freq table passed by value (host-computed
// in double -> correctly-rounded fp32, matching jnp's fp32 table to ~1 ulp).
// ---------------------------------------------------------------------------
struct RopeTab { float inv[32]; };

__global__ __launch_bounds__(256)
void rope_kernel(RopeTab tab)
{
    int idx = blockIdx.x * blockDim.x + threadIdx.x;   // over B*H*T*32
    if (idx >= Bsz * Hsz * Tsz * 32) return;
    int i  = idx & 31;
    int t  = (idx >> 5) & (Tsz - 1);
    int bh = idx >> 16;                                 // T*32 = 65536
    size_t off = ((size_t)bh * Tsz + t) * Dsz;

    float ang = (float)t * tab.inv[i];
    float c, s;
    sincosf(ang, &s, &c);

    float a0 = g_q[off + i];
    float a1 = g_q[off + i + 32];
    g_q[off + i]      = a0 * c - a1 * s;
    g_q[off + i + 32] = a1 * c + a0 * s;

    float b0 = g_k[off + i];
    float b1 = g_k[off + i + 32];
    g_k[off + i]      = b0 * c - b1 * s;
    g_k[off + i + 32] = b1 * c + b0 * s;
}

// ---------------------------------------------------------------------------
// Flash attention fp32, causal, no 1/sqrt(D) scaling.
// BM=BN=64, D=64. 256 threads, each owns a 4x4 micro tile.
// Dynamic smem: Qs[64][65] + Ks[64][65] (reused as Ps) + Vs[64][64].
// ---------------------------------------------------------------------------
#define AQS 65          // padded stride for Qs/Ks
#define ATT_SMEM ((64*65 + 64*65 + 64*64) * 4)   // 49664 bytes

__global__ __launch_bounds__(256)
void attn_kernel(float* __restrict__ y)
{
    extern __shared__ float sm[];
    float* Qs = sm;                    // 64 x 65
    float* Ks = sm + 64 * AQS;         // 64 x 65 (later reused for P)
    float* Vs = sm + 2 * 64 * AQS;     // 64 x 64

    const int tid = threadIdx.x;
    const int ty = tid >> 4;           // 0..15 : q-row group (4 rows)
    const int tx = tid & 15;           // 0..15 : col group   (4 cols)
    const int q0 = blockIdx.x * 64;
    const int bh = blockIdx.y;         // b*H + h
    const int b  = bh >> 4;
    const int h  = bh & 15;

    const size_t base = (size_t)bh * Tsz * Dsz;

    // Load Q tile (64x64) into padded smem
#pragma unroll
    for (int r = 0; r < 16; r++) {
        int idx = tid + r * 256;
        int m = idx >> 6, d = idx & 63;
        Qs[m * AQS + d] = g_q[base + (size_t)(q0 + m) * Dsz + d];
    }

    float o[4][4];
    float mrow[4], lrow[4];
#pragma unroll
    for (int i = 0; i < 4; i++) {
        mrow[i] = -INFINITY; lrow[i] = 0.f;
#pragma unroll
        for (int j = 0; j < 4; j++) o[i][j] = 0.f;
    }

    for (int js = 0; js <= q0; js += 64) {
        __syncthreads();   // previous P/V consumers done
        // Load K and V tiles (64x64 each)
#pragma unroll
        for (int r = 0; r < 16; r++) {
            int idx = tid + r * 256;
            int m = idx >> 6, d = idx & 63;
            float kv = g_k[base + (size_t)(js + m) * Dsz + d];
            float vv = g_v[base + (size_t)(js + m) * Dsz + d];
            Ks[m * AQS + d] = kv;
            Vs[m * 64 + d]  = vv;
        }
        __syncthreads();

        // S = Q @ K^T  (4x4 per thread)
        float s[4][4];
#pragma unroll
        for (int i = 0; i < 4; i++)
#pragma unroll
            for (int j = 0; j < 4; j++) s[i][j] = 0.f;

#pragma unroll 8
        for (int kk = 0; kk < 64; kk++) {
            float a[4], bq[4];
#pragma unroll
            for (int i = 0; i < 4; i++) a[i]  = Qs[(4 * ty + i) * AQS + kk];
#pragma unroll
            for (int j = 0; j < 4; j++) bq[j] = Ks[(4 * tx + j) * AQS + kk];
#pragma unroll
            for (int i = 0; i < 4; i++)
#pragma unroll
                for (int j = 0; j < 4; j++) s[i][j] = fmaf(a[i], bq[j], s[i][j]);
        }

        // Causal mask (only the diagonal tile needs it)
        if (js == q0) {
#pragma unroll
            for (int i = 0; i < 4; i++) {
                int qi = 4 * ty + i;
#pragma unroll
                for (int j = 0; j < 4; j++) {
                    int kj = 4 * tx + j;
                    if (kj > qi) s[i][j] = -INFINITY;
                }
            }
        }

        // Online softmax (row stats across the 16 lanes sharing ty = half warp)
        float p[4][4];
        float alpha[4];
#pragma unroll
        for (int i = 0; i < 4; i++) {
            float rmax = s[i][0];
#pragma unroll
            for (int j = 1; j < 4; j++) rmax = fmaxf(rmax, s[i][j]);
#pragma unroll
            for (int off = 1; off < 16; off <<= 1)
                rmax = fmaxf(rmax, __shfl_xor_sync(0xffffffffu, rmax, off));
            float nm = fmaxf(mrow[i], rmax);
            alpha[i] = expf(mrow[i] - nm);
            float rs = 0.f;
#pragma unroll
            for (int j = 0; j < 4; j++) {
                p[i][j] = expf(s[i][j] - nm);
                rs += p[i][j];
            }
#pragma unroll
            for (int off = 1; off < 16; off <<= 1)
                rs += __shfl_xor_sync(0xffffffffu, rs, off);
            lrow[i] = lrow[i] * alpha[i] + rs;
            mrow[i] = nm;
#pragma unroll
            for (int j = 0; j < 4; j++) o[i][j] *= alpha[i];
        }

        __syncthreads();   // everyone done reading Ks for S
        // Stage P into the Ks buffer
#pragma unroll
        for (int i = 0; i < 4; i++)
#pragma unroll
            for (int j = 0; j < 4; j++)
                Ks[(4 * ty + i) * AQS + 4 * tx + j] = p[i][j];
        __syncthreads();

        // O += P @ V
#pragma unroll 8
        for (int kk = 0; kk < 64; kk++) {
            float a[4];
#pragma unroll
            for (int i = 0; i < 4; i++) a[i] = Ks[(4 * ty + i) * AQS + kk];
            float4 bv = *(const float4*)&Vs[kk * 64 + 4 * tx];
            float bb[4] = {bv.x, bv.y, bv.z, bv.w};
#pragma unroll
            for (int i = 0; i < 4; i++)
#pragma unroll
                for (int j = 0; j < 4; j++) o[i][j] = fmaf(a[i], bb[j], o[i][j]);
        }
    }

    // Write y in (B,T,C) layout: col = h*64 + d
#pragma unroll
    for (int i = 0; i < 4; i++) {
        int qi = q0 + 4 * ty + i;
        float inv_l = 1.f / lrow[i];
#pragma unroll
        for (int j = 0; j < 4; j++) {
            int d = 4 * tx + j;
            g_y[((size_t)b * Tsz + qi) * Csz + h * Dsz + d] = o[i][j] * inv_l;
        }
    }
}

// ---------------------------------------------------------------------------
extern "C" void kernel_launch(void* const* d_in, const int* in_sizes, int n_in,
                              void* d_out, int out_size)
{
    const float* x     = (const float*)d_in[0];
    const float* Wqkv  = (const float*)d_in[1];
    const float* bqkv  = (const float*)d_in[2];
    const float* Wout  = (const float*)d_in[3];
    const float* bout  = (const float*)d_in[4];
    float* out = (float*)d_out;

    // 1) QKV projection with scatter epilogue into g_q/g_k/g_v
    {
        dim3 grid(3 * Csz / GBN, M1 / GBM);   // (24, 64)
        sgemm_kernel<0><<<grid, 256>>>(x, Wqkv, bqkv, nullptr, M1, 3 * Csz, Csz);
    }

    // 2) RoPE in-place on q, k
    {
        RopeTab tab;
        for (int i = 0; i < 32; i++)
            tab.inv[i] = (float)exp(-(double)(2 * i) / 64.0 * log(10000.0));
        int total = Bsz * Hsz * Tsz * 32;
        rope_kernel<<<(total + 255) / 256, 256>>>(tab);
    }

    // 3) Causal flash attention -> g_y (B,T,C)
    {
        cudaFuncSetAttribute(attn_kernel, cudaFuncAttributeMaxDynamicSharedMemorySize,
                             ATT_SMEM);
        dim3 grid(Tsz / 64, Bsz * Hsz);       // (32, 64)
        attn_kernel<<<grid, 256, ATT_SMEM>>>(nullptr);
    }

    // 4) Output projection -> d_out
    {
        float* yptr = nullptr;
        cudaGetSymbolAddress((void**)&yptr, g_y);
        dim3 grid(Csz / GBN, M1 / GBM);       // (8, 64)
        sgemm_kernel<1><<<grid, 256>>>(yptr, Wout, bout, out, M1, Csz, Csz);
    }
}

// round 3
// speedup vs baseline: 1.4155x; 1.4155x over previous
#include <cuda_runtime.h>
#include <cuda_bf16.h>
#include <math.h>
#include <stdint.h>

// Problem constants
#define Bsz 4
#define Tsz 2048
#define Csz 1024
#define Hsz 16
#define Dsz 64
#define M1 (Bsz * Tsz)        // 8192
#define K3 3072               // concatenated K: [hi | lo | hi]

// ---------------------------------------------------------------------------
// Device scratch (allocation-free)
// ---------------------------------------------------------------------------
__device__ float g_q[Bsz * Hsz * Tsz * Dsz];   // (B,H,T,D) fp32
__device__ float g_k[Bsz * Hsz * Tsz * Dsz];
__device__ float g_v[Bsz * Hsz * Tsz * Dsz];

__device__ __nv_bfloat16 g_xc[M1 * K3];          // x concat [Ah|Al|Ah]
__device__ __nv_bfloat16 g_yc[M1 * K3];          // attn out concat
__device__ __nv_bfloat16 g_wq[3 * Csz * K3];     // W_qkv^T concat [Bh|Bh|Bl], [N=3072][K3]
__device__ __nv_bfloat16 g_wo[Csz * K3];         // W_out^T concat,            [N=1024][K3]

// ---------------------------------------------------------------------------
__device__ __forceinline__ uint32_t smem_u32(const void* p) {
    uint32_t a;
    asm("{ .reg .u64 t; cvta.to.shared.u64 t, %1; cvt.u32.u64 %0, t; }" : "=r"(a) : "l"(p));
    return a;
}

__device__ __forceinline__ void split2(float v, __nv_bfloat16& hi, __nv_bfloat16& lo) {
    hi = __float2bfloat16(v);
    lo = __float2bfloat16(v - __bfloat162float(hi));
}

// ---------------------------------------------------------------------------
// Conversions
// ---------------------------------------------------------------------------
// x [M][1024] fp32 -> g_xc [M][3072] bf16 = [hi | lo | hi]
__global__ __launch_bounds__(256)
void split_x_kernel(const float* __restrict__ in, __nv_bfloat16* __restrict__ outc)
{
    int i = (blockIdx.x * blockDim.x + threadIdx.x) * 4;
    if (i >= M1 * Csz) return;
    int m = i >> 10;
    int j = i & 1023;
    float4 v = *(const float4*)&in[i];
    __nv_bfloat16 h0, l0, h1, l1, h2, l2, h3, l3;
    split2(v.x, h0, l0); split2(v.y, h1, l1); split2(v.z, h2, l2); split2(v.w, h3, l3);
    __nv_bfloat162 hA(h0, h1), hB(h2, h3), lA(l0, l1), lB(l2, l3);
    __nv_bfloat16* row = outc + (size_t)m * K3;
    *(__nv_bfloat162*)&row[j]            = hA; *(__nv_bfloat162*)&row[j + 2]        = hB;
    *(__nv_bfloat162*)&row[1024 + j]     = lA; *(__nv_bfloat162*)&row[1024 + j + 2] = lB;
    *(__nv_bfloat162*)&row[2048 + j]     = hA; *(__nv_bfloat162*)&row[2048 + j + 2] = hB;
}

// W [K=1024][N] row-major -> Wt [N][3072] = [hi | hi | lo]
__global__ __launch_bounds__(256)
void transpose_split_kernel(const float* __restrict__ W, __nv_bfloat16* __restrict__ Wt, int N)
{
    __shared__ float ts[32][33];
    int k0 = blockIdx.y * 32, n0 = blockIdx.x * 32;
    int ty = threadIdx.x >> 5, tx = threadIdx.x & 31;
#pragma unroll
    for (int r = 0; r < 4; r++) {
        int row = ty + r * 8;
        ts[row][tx] = W[(size_t)(k0 + row) * N + n0 + tx];
    }
    __syncthreads();
#pragma unroll
    for (int r = 0; r < 4; r++) {
        int row = ty + r * 8;                    // local n
        float v = ts[tx][row];
        __nv_bfloat16 h, l; split2(v, h, l);
        __nv_bfloat16* dst = Wt + (size_t)(n0 + row) * K3 + k0 + tx;
        dst[0]    = h;
        dst[1024] = h;
        dst[2048] = l;
    }
}

// ---------------------------------------------------------------------------
// HMMA GEMM:  C(M x N) = A'[M][K3] @ B'[N][K3]^T + bias
// BM=128 BN=128 BK=32, 256 thr (8 warps 4x2), warp tile 32x64.
// MODE 0: scatter -> g_q/g_k/g_v (B,H,T,D);  MODE 1: row-major -> Cout.
// ---------------------------------------------------------------------------
#define ROWB 80                 // 64B data + 16B pad per 32-bf16 row
#define TILEB (128 * ROWB)      // 10240 B

#define LDM_X4(r0, r1, r2, r3, addr) \
    asm volatile("ldmatrix.sync.aligned.m8n8.x4.shared.b16 {%0,%1,%2,%3}, [%4];" \
                 : "=r"(r0), "=r"(r1), "=r"(r2), "=r"(r3) : "r"(addr))

#define MMA16816(c0, c1, c2, c3, a0, a1, a2, a3, b0, b1) \
    asm volatile("mma.sync.aligned.m16n8k16.row.col.f32.bf16.bf16.f32 " \
                 "{%0,%1,%2,%3}, {%4,%5,%6,%7}, {%8,%9}, {%0,%1,%2,%3};" \
                 : "+f"(c0), "+f"(c1), "+f"(c2), "+f"(c3) \
                 : "r"(a0), "r"(a1), "r"(a2), "r"(a3), "r"(b0), "r"(b1))

template <int MODE>
__global__ __launch_bounds__(256)
void hmma_gemm_kernel(const __nv_bfloat16* __restrict__ A, const __nv_bfloat16* __restrict__ Bt,
                      const float* __restrict__ bias, float* __restrict__ Cout, int Ntot)
{
    __shared__ char sA[2][TILEB];
    __shared__ char sB[2][TILEB];

    const int tid = threadIdx.x;
    const int lane = tid & 31;
    const int wid = tid >> 5;
    const int wm = wid >> 1;            // 0..3
    const int wn = wid & 1;             // 0..1
    const int m0 = blockIdx.y * 128;
    const int n0 = blockIdx.x * 128;

    const uint32_t sA0 = smem_u32(sA[0]), sA1 = smem_u32(sA[1]);
    const uint32_t sB0 = smem_u32(sB[0]), sB1 = smem_u32(sB[1]);

    // global load mapping: 2 chunks of 16B per tile per thread
    const int r0 = tid >> 2;            // 0..63
    const int c0 = tid & 3;
    const int r1 = r0 + 64;

    // ldmatrix per-lane base offsets
    const uint32_t lrow = lane & 15;
    const uint32_t lhalf = (lane >> 4) * 16;

    float acc[2][8][4];
#pragma unroll
    for (int i = 0; i < 2; i++)
#pragma unroll
        for (int j = 0; j < 8; j++)
#pragma unroll
            for (int q = 0; q < 4; q++) acc[i][j][q] = 0.f;

    const int nk = K3 / 32;             // 96

    // prologue: load tile 0
    {
        const __nv_bfloat16* Ab = A + (size_t)m0 * K3;
        const __nv_bfloat16* Bb = Bt + (size_t)n0 * K3;
        float4 a0v = *(const float4*)(Ab + (size_t)r0 * K3 + c0 * 8);
        float4 a1v = *(const float4*)(Ab + (size_t)r1 * K3 + c0 * 8);
        float4 b0v = *(const float4*)(Bb + (size_t)r0 * K3 + c0 * 8);
        float4 b1v = *(const float4*)(Bb + (size_t)r1 * K3 + c0 * 8);
        *(float4*)(sA[0] + r0 * ROWB + c0 * 16) = a0v;
        *(float4*)(sA[0] + r1 * ROWB + c0 * 16) = a1v;
        *(float4*)(sB[0] + r0 * ROWB + c0 * 16) = b0v;
        *(float4*)(sB[0] + r1 * ROWB + c0 * 16) = b1v;
    }
    __syncthreads();

    for (int kt = 0; kt < nk; kt++) {
        float4 a0v, a1v, b0v, b1v;
        const bool more = (kt + 1) < nk;
        if (more) {
            const __nv_bfloat16* Ab = A + (size_t)m0 * K3 + (kt + 1) * 32;
            const __nv_bfloat16* Bb = Bt + (size_t)n0 * K3 + (kt + 1) * 32;
            a0v = *(const float4*)(Ab + (size_t)r0 * K3 + c0 * 8);
            a1v = *(const float4*)(Ab + (size_t)r1 * K3 + c0 * 8);
            b0v = *(const float4*)(Bb + (size_t)r0 * K3 + c0 * 8);
            b1v = *(const float4*)(Bb + (size_t)r1 * K3 + c0 * 8);
        }

        const uint32_t aBase = (kt & 1) ? sA1 : sA0;
        const uint32_t bBase = (kt & 1) ? sB1 : sB0;

#pragma unroll
        for (int ks = 0; ks < 2; ks++) {
            uint32_t af[2][4];
#pragma unroll
            for (int i = 0; i < 2; i++) {
                uint32_t ad = aBase + (wm * 32 + i * 16 + lrow) * ROWB + ks * 32 + lhalf;
                LDM_X4(af[i][0], af[i][1], af[i][2], af[i][3], ad);
            }
            uint32_t bf[4][4];
#pragma unroll
            for (int j2 = 0; j2 < 4; j2++) {
                uint32_t bd = bBase + (wn * 64 + j2 * 16 + lrow) * ROWB + ks * 32 + lhalf;
                LDM_X4(bf[j2][0], bf[j2][1], bf[j2][2], bf[j2][3], bd);
            }
#pragma unroll
            for (int i = 0; i < 2; i++)
#pragma unroll
                for (int j = 0; j < 8; j++) {
                    int j2 = j >> 1, o = j & 1;
                    MMA16816(acc[i][j][0], acc[i][j][1], acc[i][j][2], acc[i][j][3],
                             af[i][0], af[i][1], af[i][2], af[i][3],
                             bf[j2][o], bf[j2][o + 2]);
                }
        }

        if (more) {
            __syncthreads();
            char* dstA = (kt & 1) ? sA[0] : sA[1];
            char* dstB = (kt & 1) ? sB[0] : sB[1];
            *(float4*)(dstA + r0 * ROWB + c0 * 16) = a0v;
            *(float4*)(dstA + r1 * ROWB + c0 * 16) = a1v;
            *(float4*)(dstB + r0 * ROWB + c0 * 16) = b0v;
            *(float4*)(dstB + r1 * ROWB + c0 * 16) = b1v;
            __syncthreads();
        }
    }

    // Epilogue
    const int mwb = m0 + wm * 32 + (lane >> 2);
    const int nwb = n0 + wn * 64 + 2 * (lane & 3);
#pragma unroll
    for (int i = 0; i < 2; i++) {
#pragma unroll
        for (int j = 0; j < 8; j++) {
            int n = nwb + j * 8;
            float bx = bias[n], by = bias[n + 1];
#pragma unroll
            for (int half = 0; half < 2; half++) {
                int m = mwb + i * 16 + half * 8;
                float vx = acc[i][j][half * 2 + 0] + bx;
                float vy = acc[i][j][half * 2 + 1] + by;
                if (MODE == 1) {
                    *(float2*)&Cout[(size_t)m * Csz + n] = make_float2(vx, vy);
                } else {
                    int b = m >> 11;
                    int t = m & (Tsz - 1);
                    int which = n >> 10;
                    int nn = n & 1023;
                    int h = nn >> 6, d = nn & 63;
                    float* dst = (which == 0) ? g_q : (which == 1) ? g_k : g_v;
                    *(float2*)&dst[(((size_t)(b * Hsz + h) * Tsz) + t) * Dsz + d] =
                        make_float2(vx, vy);
                }
            }
        }
    }
}

// ---------------------------------------------------------------------------
// RoPE (in-place on g_q, g_k)
// ---------------------------------------------------------------------------
struct RopeTab { float inv[32]; };

__global__ __launch_bounds__(256)
void rope_kernel(RopeTab tab)
{
    int idx = blockIdx.x * blockDim.x + threadIdx.x;
    if (idx >= Bsz * Hsz * Tsz * 32) return;
    int i  = idx & 31;
    int t  = (idx >> 5) & (Tsz - 1);
    int bh = idx >> 16;
    size_t off = ((size_t)bh * Tsz + t) * Dsz;

    float ang = (float)t * tab.inv[i];
    float c, s;
    sincosf(ang, &s, &c);

    float a0 = g_q[off + i];
    float a1 = g_q[off + i + 32];
    g_q[off + i]      = a0 * c - a1 * s;
    g_q[off + i + 32] = a1 * c + a0 * s;

    float b0 = g_k[off + i];
    float b1 = g_k[off + i + 32];
    g_k[off + i]      = b0 * c - b1 * s;
    g_k[off + i + 32] = b1 * c + b0 * s;
}

// ---------------------------------------------------------------------------
// Flash attention fp32, causal. BM=BN=64, D=64, 256 thr, 4x4 micro-tile.
// Epilogue writes concat bf16 split of y into g_yc.
// ---------------------------------------------------------------------------
#define AQS 65
#define ATT_SMEM ((64*65 + 64*65 + 64*64) * 4)

__global__ __launch_bounds__(256)
void attn_kernel()
{
    extern __shared__ float sm[];
    float* Qs = sm;
    float* Ks = sm + 64 * AQS;
    float* Vs = sm + 2 * 64 * AQS;

    const int tid = threadIdx.x;
    const int ty = tid >> 4;
    const int tx = tid & 15;
    const int q0 = blockIdx.x * 64;
    const int bh = blockIdx.y;
    const int b  = bh >> 4;
    const int h  = bh & 15;

    const size_t base = (size_t)bh * Tsz * Dsz;

#pragma unroll
    for (int r = 0; r < 16; r++) {
        int idx = tid + r * 256;
        int m = idx >> 6, d = idx & 63;
        Qs[m * AQS + d] = g_q[base + (size_t)(q0 + m) * Dsz + d];
    }

    float o[4][4];
    float mrow[4], lrow[4];
#pragma unroll
    for (int i = 0; i < 4; i++) {
        mrow[i] = -INFINITY; lrow[i] = 0.f;
#pragma unroll
        for (int j = 0; j < 4; j++) o[i][j] = 0.f;
    }

    for (int js = 0; js <= q0; js += 64) {
        __syncthreads();
#pragma unroll
        for (int r = 0; r < 16; r++) {
            int idx = tid + r * 256;
            int m = idx >> 6, d = idx & 63;
            Ks[m * AQS + d] = g_k[base + (size_t)(js + m) * Dsz + d];
            Vs[m * 64 + d]  = g_v[base + (size_t)(js + m) * Dsz + d];
        }
        __syncthreads();

        float s[4][4];
#pragma unroll
        for (int i = 0; i < 4; i++)
#pragma unroll
            for (int j = 0; j < 4; j++) s[i][j] = 0.f;

#pragma unroll 8
        for (int kk = 0; kk < 64; kk++) {
            float a[4], bq[4];
#pragma unroll
            for (int i = 0; i < 4; i++) a[i]  = Qs[(4 * ty + i) * AQS + kk];
#pragma unroll
            for (int j = 0; j < 4; j++) bq[j] = Ks[(4 * tx + j) * AQS + kk];
#pragma unroll
            for (int i = 0; i < 4; i++)
#pragma unroll
                for (int j = 0; j < 4; j++) s[i][j] = fmaf(a[i], bq[j], s[i][j]);
        }

        if (js == q0) {
#pragma unroll
            for (int i = 0; i < 4; i++) {
                int qi = 4 * ty + i;
#pragma unroll
                for (int j = 0; j < 4; j++) {
                    int kj = 4 * tx + j;
                    if (kj > qi) s[i][j] = -INFINITY;
                }
            }
        }

        float p[4][4];
        float alpha[4];
#pragma unroll
        for (int i = 0; i < 4; i++) {
            float rmax = s[i][0];
#pragma unroll
            for (int j = 1; j < 4; j++) rmax = fmaxf(rmax, s[i][j]);
#pragma unroll
            for (int off = 1; off < 16; off <<= 1)
                rmax = fmaxf(rmax, __shfl_xor_sync(0xffffffffu, rmax, off));
            float nm = fmaxf(mrow[i], rmax);
            alpha[i] = expf(mrow[i] - nm);
            float rs = 0.f;
#pragma unroll
            for (int j = 0; j < 4; j++) {
                p[i][j] = expf(s[i][j] - nm);
                rs += p[i][j];
            }
#pragma unroll
            for (int off = 1; off < 16; off <<= 1)
                rs += __shfl_xor_sync(0xffffffffu, rs, off);
            lrow[i] = lrow[i] * alpha[i] + rs;
            mrow[i] = nm;
#pragma unroll
            for (int j = 0; j < 4; j++) o[i][j] *= alpha[i];
        }

        __syncthreads();
#pragma unroll
        for (int i = 0; i < 4; i++)
#pragma unroll
            for (int j = 0; j < 4; j++)
                Ks[(4 * ty + i) * AQS + 4 * tx + j] = p[i][j];
        __syncthreads();

#pragma unroll 8
        for (int kk = 0; kk < 64; kk++) {
            float a[4];
#pragma unroll
            for (int i = 0; i < 4; i++) a[i] = Ks[(4 * ty + i) * AQS + kk];
            float4 bv = *(const float4*)&Vs[kk * 64 + 4 * tx];
            float bb[4] = {bv.x, bv.y, bv.z, bv.w};
#pragma unroll
            for (int i = 0; i < 4; i++)
#pragma unroll
                for (int j = 0; j < 4; j++) o[i][j] = fmaf(a[i], bb[j], o[i][j]);
        }
    }

#pragma unroll
    for (int i = 0; i < 4; i++) {
        int qi = q0 + 4 * ty + i;
        float inv_l = 1.f / lrow[i];
        __nv_bfloat16* yrow = g_yc + ((size_t)b * Tsz + qi) * K3 + h * Dsz;
#pragma unroll
        for (int j = 0; j < 4; j++) {
            int d = 4 * tx + j;
            float val = o[i][j] * inv_l;
            __nv_bfloat16 hv, lv; split2(val, hv, lv);
            yrow[d]        = hv;
            yrow[d + 1024] = lv;
            yrow[d + 2048] = hv;
        }
    }
}

// ---------------------------------------------------------------------------
extern "C" void kernel_launch(void* const* d_in, const int* in_sizes, int n_in,
                              void* d_out, int out_size)
{
    const float* x    = (const float*)d_in[0];
    const float* Wqkv = (const float*)d_in[1];
    const float* bqkv = (const float*)d_in[2];
    const float* Wout = (const float*)d_in[3];
    const float* bout = (const float*)d_in[4];
    float* out = (float*)d_out;

    __nv_bfloat16 *xc, *yc, *wq, *wo;
    cudaGetSymbolAddress((void**)&xc, g_xc);
    cudaGetSymbolAddress((void**)&yc, g_yc);
    cudaGetSymbolAddress((void**)&wq, g_wq);
    cudaGetSymbolAddress((void**)&wo, g_wo);

    // 0) conversions
    {
        int n = M1 * Csz;
        split_x_kernel<<<(n / 4 + 255) / 256, 256>>>(x, xc);
        dim3 g1(3 * Csz / 32, Csz / 32);
        transpose_split_kernel<<<g1, 256>>>(Wqkv, wq, 3 * Csz);
        dim3 g2(Csz / 32, Csz / 32);
        transpose_split_kernel<<<g2, 256>>>(Wout, wo, Csz);
    }

    // 1) QKV projection (HMMA bf16x3) -> q/k/v scatter
    {
        dim3 grid(3 * Csz / 128, M1 / 128);   // (24, 64)
        hmma_gemm_kernel<0><<<grid, 256>>>(xc, wq, bqkv, nullptr, 3 * Csz);
    }

    // 2) RoPE in-place
    {
        RopeTab tab;
        for (int i = 0; i < 32; i++)
            tab.inv[i] = (float)exp(-(double)(2 * i) / 64.0 * log(10000.0));
        int total = Bsz * Hsz * Tsz * 32;
        rope_kernel<<<(total + 255) / 256, 256>>>(tab);
    }

    // 3) Causal flash attention -> g_yc concat split
    {
        cudaFuncSetAttribute(attn_kernel, cudaFuncAttributeMaxDynamicSharedMemorySize, ATT_SMEM);
        dim3 grid(Tsz / 64, Bsz * Hsz);
        attn_kernel<<<grid, 256, ATT_SMEM>>>();
    }

    // 4) Output projection (HMMA bf16x3) -> d_out
    {
        dim3 grid(Csz / 128, M1 / 128);       // (8, 64)
        hmma_gemm_kernel<1><<<grid, 256>>>(yc, wo, bout, out, Csz);
    }
}

// round 4
// speedup vs baseline: 2.1178x; 1.4961x over previous
#include <cuda_runtime.h>
#include <cuda_bf16.h>
#include <math.h>
#include <stdint.h>

// Problem constants
#define Bsz 4
#define Tsz 2048
#define Csz 1024
#define Hsz 16
#define Dsz 64
#define M1 (Bsz * Tsz)        // 8192
#define K3 3072               // concatenated K: [hi | lo | hi]

// ---------------------------------------------------------------------------
// Device scratch (allocation-free)
// ---------------------------------------------------------------------------
__device__ __nv_bfloat16 g_qh[Bsz * Hsz * Tsz * Dsz];  // (B,H,T,D)
__device__ __nv_bfloat16 g_ql[Bsz * Hsz * Tsz * Dsz];
__device__ __nv_bfloat16 g_kh[Bsz * Hsz * Tsz * Dsz];
__device__ __nv_bfloat16 g_kl[Bsz * Hsz * Tsz * Dsz];
__device__ __nv_bfloat16 g_vth[Bsz * Hsz * Dsz * Tsz]; // (B,H,D,T) transposed
__device__ __nv_bfloat16 g_vtl[Bsz * Hsz * Dsz * Tsz];

__device__ __nv_bfloat16 g_xc[M1 * K3];          // x concat [Ah|Al|Ah]
__device__ __nv_bfloat16 g_yc[M1 * K3];          // attn out concat
__device__ __nv_bfloat16 g_wq[3 * Csz * K3];     // W_qkv^T concat [Bh|Bh|Bl]
__device__ __nv_bfloat16 g_wo[Csz * K3];         // W_out^T concat

// ---------------------------------------------------------------------------
__device__ __forceinline__ uint32_t smem_u32(const void* p) {
    uint32_t a;
    asm("{ .reg .u64 t; cvta.to.shared.u64 t, %1; cvt.u32.u64 %0, t; }" : "=r"(a) : "l"(p));
    return a;
}

__device__ __forceinline__ void split2(float v, __nv_bfloat16& hi, __nv_bfloat16& lo) {
    hi = __float2bfloat16(v);
    lo = __float2bfloat16(v - __bfloat162float(hi));
}

__device__ __forceinline__ void packsplit(float x, float y, uint32_t& h, uint32_t& l) {
    __nv_bfloat16 hx = __float2bfloat16(x), hy = __float2bfloat16(y);
    float lx = x - __bfloat162float(hx);
    float ly = y - __bfloat162float(hy);
    __nv_bfloat162 hv(hx, hy);
    __nv_bfloat162 lv = __floats2bfloat162_rn(lx, ly);
    h = *(uint32_t*)&hv;
    l = *(uint32_t*)&lv;
}

struct RopeTab { float inv[32]; };

// ---------------------------------------------------------------------------
// Conversions
// ---------------------------------------------------------------------------
__global__ __launch_bounds__(256)
void split_x_kernel(const float* __restrict__ in, __nv_bfloat16* __restrict__ outc)
{
    int i = (blockIdx.x * blockDim.x + threadIdx.x) * 4;
    if (i >= M1 * Csz) return;
    int m = i >> 10;
    int j = i & 1023;
    float4 v = *(const float4*)&in[i];
    __nv_bfloat16 h0, l0, h1, l1, h2, l2, h3, l3;
    split2(v.x, h0, l0); split2(v.y, h1, l1); split2(v.z, h2, l2); split2(v.w, h3, l3);
    __nv_bfloat162 hA(h0, h1), hB(h2, h3), lA(l0, l1), lB(l2, l3);
    __nv_bfloat16* row = outc + (size_t)m * K3;
    *(__nv_bfloat162*)&row[j]            = hA; *(__nv_bfloat162*)&row[j + 2]        = hB;
    *(__nv_bfloat162*)&row[1024 + j]     = lA; *(__nv_bfloat162*)&row[1024 + j + 2] = lB;
    *(__nv_bfloat162*)&row[2048 + j]     = hA; *(__nv_bfloat162*)&row[2048 + j + 2] = hB;
}

__global__ __launch_bounds__(256)
void transpose_split_kernel(const float* __restrict__ W, __nv_bfloat16* __restrict__ Wt, int N)
{
    __shared__ float ts[32][33];
    int k0 = blockIdx.y * 32, n0 = blockIdx.x * 32;
    int ty = threadIdx.x >> 5, tx = threadIdx.x & 31;
#pragma unroll
    for (int r = 0; r < 4; r++) {
        int row = ty + r * 8;
        ts[row][tx] = W[(size_t)(k0 + row) * N + n0 + tx];
    }
    __syncthreads();
#pragma unroll
    for (int r = 0; r < 4; r++) {
        int row = ty + r * 8;
        float v = ts[tx][row];
        __nv_bfloat16 h, l; split2(v, h, l);
        __nv_bfloat16* dst = Wt + (size_t)(n0 + row) * K3 + k0 + tx;
        dst[0]    = h;
        dst[1024] = h;
        dst[2048] = l;
    }
}

// ---------------------------------------------------------------------------
// HMMA macros
// ---------------------------------------------------------------------------
#define LDM_X4(r0, r1, r2, r3, addr) \
    asm volatile("ldmatrix.sync.aligned.m8n8.x4.shared.b16 {%0,%1,%2,%3}, [%4];" \
                 : "=r"(r0), "=r"(r1), "=r"(r2), "=r"(r3) : "r"(addr))

#define MMA16816(c0, c1, c2, c3, a0, a1, a2, a3, b0, b1) \
    asm volatile("mma.sync.aligned.m16n8k16.row.col.f32.bf16.bf16.f32 " \
                 "{%0,%1,%2,%3}, {%4,%5,%6,%7}, {%8,%9}, {%0,%1,%2,%3};" \
                 : "+f"(c0), "+f"(c1), "+f"(c2), "+f"(c3) \
                 : "r"(a0), "r"(a1), "r"(a2), "r"(a3), "r"(b0), "r"(b1))

// ---------------------------------------------------------------------------
// HMMA GEMM: BM=128 BN=128 BK=32, 256 thr (8 warps 4x2), warp tile 32x64.
// MODE 0: fused RoPE + split -> q/k (B,H,T,D), v -> transposed (B,H,D,T)
// MODE 1: row-major fp32 -> Cout
// ---------------------------------------------------------------------------
#define ROWB 80
#define TILEB (128 * ROWB)      // 10240
#define TRS 272                 // trans row stride bytes (136 bf16)

template <int MODE>
__global__ __launch_bounds__(256)
void hmma_gemm_kernel(const __nv_bfloat16* __restrict__ A, const __nv_bfloat16* __restrict__ Bt,
                      const float* __restrict__ bias, float* __restrict__ Cout,
                      RopeTab tab)
{
    __shared__ char smem_all[4 * TILEB];   // 40960 B

    const int tid = threadIdx.x;
    const int lane = tid & 31;
    const int wid = tid >> 5;
    const int wm = wid >> 1;            // 0..3
    const int wn = wid & 1;             // 0..1
    const int m0 = blockIdx.y * 128;
    const int n0 = blockIdx.x * 128;

    char* sAp[2] = { smem_all, smem_all + TILEB };
    char* sBp[2] = { smem_all + 2 * TILEB, smem_all + 3 * TILEB };
    const uint32_t sA0 = smem_u32(sAp[0]), sA1 = smem_u32(sAp[1]);
    const uint32_t sB0 = smem_u32(sBp[0]), sB1 = smem_u32(sBp[1]);

    const int r0 = tid >> 2;
    const int c0 = tid & 3;
    const int r1 = r0 + 64;

    const uint32_t lrow = lane & 15;
    const uint32_t lhalf = (lane >> 4) * 16;

    float acc[2][8][4];
#pragma unroll
    for (int i = 0; i < 2; i++)
#pragma unroll
        for (int j = 0; j < 8; j++)
#pragma unroll
            for (int q = 0; q < 4; q++) acc[i][j][q] = 0.f;

    const int nk = K3 / 32;             // 96

    {
        const __nv_bfloat16* Ab = A + (size_t)m0 * K3;
        const __nv_bfloat16* Bb = Bt + (size_t)n0 * K3;
        *(float4*)(sAp[0] + r0 * ROWB + c0 * 16) = *(const float4*)(Ab + (size_t)r0 * K3 + c0 * 8);
        *(float4*)(sAp[0] + r1 * ROWB + c0 * 16) = *(const float4*)(Ab + (size_t)r1 * K3 + c0 * 8);
        *(float4*)(sBp[0] + r0 * ROWB + c0 * 16) = *(const float4*)(Bb + (size_t)r0 * K3 + c0 * 8);
        *(float4*)(sBp[0] + r1 * ROWB + c0 * 16) = *(const float4*)(Bb + (size_t)r1 * K3 + c0 * 8);
    }
    __syncthreads();

    for (int kt = 0; kt < nk; kt++) {
        float4 a0v, a1v, b0v, b1v;
        const bool more = (kt + 1) < nk;
        if (more) {
            const __nv_bfloat16* Ab = A + (size_t)m0 * K3 + (kt + 1) * 32;
            const __nv_bfloat16* Bb = Bt + (size_t)n0 * K3 + (kt + 1) * 32;
            a0v = *(const float4*)(Ab + (size_t)r0 * K3 + c0 * 8);
            a1v = *(const float4*)(Ab + (size_t)r1 * K3 + c0 * 8);
            b0v = *(const float4*)(Bb + (size_t)r0 * K3 + c0 * 8);
            b1v = *(const float4*)(Bb + (size_t)r1 * K3 + c0 * 8);
        }

        const uint32_t aBase = (kt & 1) ? sA1 : sA0;
        const uint32_t bBase = (kt & 1) ? sB1 : sB0;

#pragma unroll
        for (int ks = 0; ks < 2; ks++) {
            uint32_t af[2][4];
#pragma unroll
            for (int i = 0; i < 2; i++) {
                uint32_t ad = aBase + (wm * 32 + i * 16 + lrow) * ROWB + ks * 32 + lhalf;
                LDM_X4(af[i][0], af[i][1], af[i][2], af[i][3], ad);
            }
            uint32_t bf[4][4];
#pragma unroll
            for (int j2 = 0; j2 < 4; j2++) {
                uint32_t bd = bBase + (wn * 64 + j2 * 16 + lrow) * ROWB + ks * 32 + lhalf;
                LDM_X4(bf[j2][0], bf[j2][1], bf[j2][2], bf[j2][3], bd);
            }
#pragma unroll
            for (int i = 0; i < 2; i++)
#pragma unroll
                for (int j = 0; j < 8; j++) {
                    int j2 = j >> 1, o = j & 1;
                    MMA16816(acc[i][j][0], acc[i][j][1], acc[i][j][2], acc[i][j][3],
                             af[i][0], af[i][1], af[i][2], af[i][3],
                             bf[j2][o], bf[j2][o + 2]);
                }
        }

        if (more) {
            __syncthreads();
            char* dstA = (kt & 1) ? sAp[0] : sAp[1];
            char* dstB = (kt & 1) ? sBp[0] : sBp[1];
            *(float4*)(dstA + r0 * ROWB + c0 * 16) = a0v;
            *(float4*)(dstA + r1 * ROWB + c0 * 16) = a1v;
            *(float4*)(dstB + r0 * ROWB + c0 * 16) = b0v;
            *(float4*)(dstB + r1 * ROWB + c0 * 16) = b1v;
            __syncthreads();
        }
    }

    // ---------------- Epilogue ----------------
    if (MODE == 1) {
        const int mwb = m0 + wm * 32 + (lane >> 2);
        const int nwb = n0 + wn * 64 + 2 * (lane & 3);
#pragma unroll
        for (int i = 0; i < 2; i++)
#pragma unroll
            for (int j = 0; j < 8; j++) {
                int n = nwb + j * 8;
                float bx = bias[n], by = bias[n + 1];
#pragma unroll
                for (int half = 0; half < 2; half++) {
                    int m = mwb + i * 16 + half * 8;
                    *(float2*)&Cout[(size_t)m * Csz + n] =
                        make_float2(acc[i][j][half * 2] + bx, acc[i][j][half * 2 + 1] + by);
                }
            }
        return;
    }

    // MODE 0
    const int which = n0 >> 10;
    if (which < 2) {
        // q or k: fused RoPE, store split bf16 to (B,H,T,D)
        __nv_bfloat16* GH = (which == 0) ? g_qh : g_kh;
        __nv_bfloat16* GL = (which == 0) ? g_ql : g_kl;
        const int b = m0 >> 11;
        const int hh = ((n0 + wn * 64) & 1023) >> 6;
        const int bh = b * Hsz + hh;
        const int dbase = 2 * (lane & 3);
#pragma unroll
        for (int i = 0; i < 2; i++) {
#pragma unroll
            for (int half = 0; half < 2; half++) {
                int m = m0 + wm * 32 + (lane >> 2) + i * 16 + half * 8;
                int t = m & (Tsz - 1);
                size_t baseo = ((size_t)bh * Tsz + t) * Dsz;
#pragma unroll
                for (int j = 0; j < 4; j++) {
                    int n = n0 + wn * 64 + dbase + j * 8;
                    int d = n & 63;                      // 0..30, even
                    float lowx  = acc[i][j][half * 2]     + bias[n];
                    float lowy  = acc[i][j][half * 2 + 1] + bias[n + 1];
                    float highx = acc[i][j + 4][half * 2]     + bias[n + 32];
                    float highy = acc[i][j + 4][half * 2 + 1] + bias[n + 33];
                    float c0f, s0f, c1f, s1f;
                    sincosf((float)t * tab.inv[d],     &s0f, &c0f);
                    sincosf((float)t * tab.inv[d + 1], &s1f, &c1f);
                    float nlx = lowx * c0f - highx * s0f;
                    float nhx = highx * c0f + lowx * s0f;
                    float nly = lowy * c1f - highy * s1f;
                    float nhy = highy * c1f + lowy * s1f;
                    __nv_bfloat16 hlx, llx, hly, lly, hhx, lhx, hhy, lhy;
                    split2(nlx, hlx, llx); split2(nly, hly, lly);
                    split2(nhx, hhx, lhx); split2(nhy, hhy, lhy);
                    *(__nv_bfloat162*)&GH[baseo + d]      = __nv_bfloat162(hlx, hly);
                    *(__nv_bfloat162*)&GL[baseo + d]      = __nv_bfloat162(llx, lly);
                    *(__nv_bfloat162*)&GH[baseo + d + 32] = __nv_bfloat162(hhx, hhy);
                    *(__nv_bfloat162*)&GL[baseo + d + 32] = __nv_bfloat162(lhx, lhy);
                }
            }
        }
    } else {
        // v: smem transpose, store split bf16 to (B,H,D,T)
        const int b = m0 >> 11;
        const int t0 = m0 & (Tsz - 1);
        __nv_bfloat16* trs = (__nv_bfloat16*)smem_all;
#pragma unroll
        for (int pass = 0; pass < 2; pass++) {
            __syncthreads();
#pragma unroll
            for (int i = 0; i < 2; i++)
#pragma unroll
                for (int half = 0; half < 2; half++) {
                    int ml = wm * 32 + (lane >> 2) + i * 16 + half * 8;
#pragma unroll
                    for (int j = 0; j < 8; j++) {
                        int nl = wn * 64 + 2 * (lane & 3) + j * 8;
                        float vx = acc[i][j][half * 2]     + bias[n0 + nl];
                        float vy = acc[i][j][half * 2 + 1] + bias[n0 + nl + 1];
                        __nv_bfloat16 hx, lx, hy, ly;
                        split2(vx, hx, lx); split2(vy, hy, ly);
                        trs[nl * 136 + ml]       = pass ? lx : hx;
                        trs[(nl + 1) * 136 + ml] = pass ? ly : hy;
                    }
                }
            __syncthreads();
            __nv_bfloat16* dstArr = pass ? g_vtl : g_vth;
#pragma unroll
            for (int rr = 0; rr < 8; rr++) {
                int row = (tid >> 4) + rr * 16;          // n_local 0..127
                int chunk = tid & 15;
                int n = n0 + row;
                int hh = (n & 1023) >> 6;
                int d = n & 63;
                float4 v = *(float4*)((char*)trs + row * TRS + chunk * 16);
                *(float4*)&dstArr[((size_t)(b * Hsz + hh) * Dsz + d) * Tsz + t0 + chunk * 8] = v;
            }
        }
    }
}

// ---------------------------------------------------------------------------
// HMMA flash attention, causal. BM=64 (4 warps x 16 rows), BN=64, D=64.
// Q/K/V as bf16 hi/lo; S and O via bf16x3 compensation; softmax in fp32 regs.
// ---------------------------------------------------------------------------
#define ATS 144
#define ATT_SMEM (6 * 64 * ATS)   // 55296

__global__ __launch_bounds__(128)
void attn_hmma_kernel()
{
    extern __shared__ char asmem[];
    char* qh_s = asmem;
    char* ql_s = asmem + 9216;
    char* kh_s = asmem + 18432;
    char* kl_s = asmem + 27648;
    char* vh_s = asmem + 36864;
    char* vl_s = asmem + 46080;

    const int tid = threadIdx.x;
    const int lane = tid & 31;
    const int wid = tid >> 5;          // 0..3
    const int q0 = (gridDim.x - 1 - blockIdx.x) * 64;   // heavy tiles first
    const int bh = blockIdx.y;

    const uint32_t lrow = lane & 15;
    const uint32_t lhalf = (lane >> 4) * 16;

    // Load Q tile (hi/lo)
    {
        const size_t qg = ((size_t)bh * Tsz + q0) * Dsz;
#pragma unroll
        for (int r = 0; r < 4; r++) {
            int idx = tid + r * 128;
            int row = idx >> 3, c = idx & 7;
            *(float4*)(qh_s + row * ATS + c * 16) = *(const float4*)&g_qh[qg + row * Dsz + c * 8];
            *(float4*)(ql_s + row * ATS + c * 16) = *(const float4*)&g_ql[qg + row * Dsz + c * 8];
        }
    }
    __syncthreads();

    // Preload Q fragments (row-major A operand)
    uint32_t qhf[4][4], qlf[4][4];
    {
        const uint32_t qbh = smem_u32(qh_s), qbl = smem_u32(ql_s);
#pragma unroll
        for (int ks = 0; ks < 4; ks++) {
            uint32_t ad = qbh + (wid * 16 + lrow) * ATS + ks * 32 + lhalf;
            LDM_X4(qhf[ks][0], qhf[ks][1], qhf[ks][2], qhf[ks][3], ad);
            ad = qbl + (wid * 16 + lrow) * ATS + ks * 32 + lhalf;
            LDM_X4(qlf[ks][0], qlf[ks][1], qlf[ks][2], qlf[ks][3], ad);
        }
    }

    float mrow[2] = { -INFINITY, -INFINITY };
    float lsum[2] = { 0.f, 0.f };
    float oa[8][4];
#pragma unroll
    for (int j = 0; j < 8; j++)
#pragma unroll
        for (int q = 0; q < 4; q++) oa[j][q] = 0.f;

    const uint32_t kbh = smem_u32(kh_s), kbl = smem_u32(kl_s);
    const uint32_t vbh = smem_u32(vh_s), vbl = smem_u32(vl_s);

    for (int js = 0; js <= q0; js += 64) {
        __syncthreads();
        // Load K (hi/lo) and VT (hi/lo) tiles
        {
            const size_t kg = ((size_t)bh * Tsz + js) * Dsz;
            const size_t vg = (size_t)bh * Dsz * Tsz + js;
#pragma unroll
            for (int r = 0; r < 4; r++) {
                int idx = tid + r * 128;
                int row = idx >> 3, c = idx & 7;
                *(float4*)(kh_s + row * ATS + c * 16) = *(const float4*)&g_kh[kg + row * Dsz + c * 8];
                *(float4*)(kl_s + row * ATS + c * 16) = *(const float4*)&g_kl[kg + row * Dsz + c * 8];
                *(float4*)(vh_s + row * ATS + c * 16) = *(const float4*)&g_vth[vg + (size_t)row * Tsz + c * 8];
                *(float4*)(vl_s + row * ATS + c * 16) = *(const float4*)&g_vtl[vg + (size_t)row * Tsz + c * 8];
            }
        }
        __syncthreads();

        // S = Qh Kh^T + Ql Kh^T + Qh Kl^T
        float s[8][4];
#pragma unroll
        for (int j = 0; j < 8; j++)
#pragma unroll
            for (int q = 0; q < 4; q++) s[j][q] = 0.f;

#pragma unroll
        for (int ks = 0; ks < 4; ks++) {
#pragma unroll
            for (int j2 = 0; j2 < 4; j2++) {
                uint32_t khf[4], klf[4];
                LDM_X4(khf[0], khf[1], khf[2], khf[3], kbh + (j2 * 16 + lrow) * ATS + ks * 32 + lhalf);
                LDM_X4(klf[0], klf[1], klf[2], klf[3], kbl + (j2 * 16 + lrow) * ATS + ks * 32 + lhalf);
#pragma unroll
                for (int o = 0; o < 2; o++) {
                    int j = 2 * j2 + o;
                    MMA16816(s[j][0], s[j][1], s[j][2], s[j][3],
                             qhf[ks][0], qhf[ks][1], qhf[ks][2], qhf[ks][3], khf[o], khf[o + 2]);
                    MMA16816(s[j][0], s[j][1], s[j][2], s[j][3],
                             qlf[ks][0], qlf[ks][1], qlf[ks][2], qlf[ks][3], khf[o], khf[o + 2]);
                    MMA16816(s[j][0], s[j][1], s[j][2], s[j][3],
                             qhf[ks][0], qhf[ks][1], qhf[ks][2], qhf[ks][3], klf[o], klf[o + 2]);
                }
            }
        }

        // Causal mask on the diagonal tile
        if (js == q0) {
#pragma unroll
            for (int j = 0; j < 8; j++)
#pragma unroll
                for (int q = 0; q < 4; q++) {
                    int col = js + j * 8 + 2 * (lane & 3) + (q & 1);
                    int row = q0 + wid * 16 + (lane >> 2) + (q >> 1) * 8;
                    if (col > row) s[j][q] = -INFINITY;
                }
        }

        // Online softmax (rows live in quads; reduce via shfl_xor 1,2)
#pragma unroll
        for (int h = 0; h < 2; h++) {
            float mx = -INFINITY;
#pragma unroll
            for (int j = 0; j < 8; j++)
                mx = fmaxf(mx, fmaxf(s[j][2 * h], s[j][2 * h + 1]));
            mx = fmaxf(mx, __shfl_xor_sync(0xffffffffu, mx, 1));
            mx = fmaxf(mx, __shfl_xor_sync(0xffffffffu, mx, 2));
            float nm = fmaxf(mrow[h], mx);
            float alpha = __expf(mrow[h] - nm);
            float sum = 0.f;
#pragma unroll
            for (int j = 0; j < 8; j++) {
                float p0 = __expf(s[j][2 * h] - nm);
                float p1 = __expf(s[j][2 * h + 1] - nm);
                s[j][2 * h] = p0; s[j][2 * h + 1] = p1;
                sum += p0 + p1;
            }
            sum += __shfl_xor_sync(0xffffffffu, sum, 1);
            sum += __shfl_xor_sync(0xffffffffu, sum, 2);
            lsum[h] = lsum[h] * alpha + sum;
            mrow[h] = nm;
#pragma unroll
            for (int j = 0; j < 8; j++) {
                oa[j][2 * h] *= alpha;
                oa[j][2 * h + 1] *= alpha;
            }
        }

        // O += Ph Vh + Pl Vh + Ph Vl
#pragma unroll
        for (int kt = 0; kt < 4; kt++) {
            uint32_t pah[4], pal[4];
            packsplit(s[2 * kt][0],     s[2 * kt][1],     pah[0], pal[0]);
            packsplit(s[2 * kt][2],     s[2 * kt][3],     pah[1], pal[1]);
            packsplit(s[2 * kt + 1][0], s[2 * kt + 1][1], pah[2], pal[2]);
            packsplit(s[2 * kt + 1][2], s[2 * kt + 1][3], pah[3], pal[3]);
#pragma unroll
            for (int j2 = 0; j2 < 4; j2++) {
                uint32_t vhf[4], vlf[4];
                LDM_X4(vhf[0], vhf[1], vhf[2], vhf[3], vbh + (j2 * 16 + lrow) * ATS + kt * 32 + lhalf);
                LDM_X4(vlf[0], vlf[1], vlf[2], vlf[3], vbl + (j2 * 16 + lrow) * ATS + kt * 32 + lhalf);
#pragma unroll
                for (int o = 0; o < 2; o++) {
                    int j = 2 * j2 + o;
                    MMA16816(oa[j][0], oa[j][1], oa[j][2], oa[j][3],
                             pah[0], pah[1], pah[2], pah[3], vhf[o], vhf[o + 2]);
                    MMA16816(oa[j][0], oa[j][1], oa[j][2], oa[j][3],
                             pal[0], pal[1], pal[2], pal[3], vhf[o], vhf[o + 2]);
                    MMA16816(oa[j][0], oa[j][1], oa[j][2], oa[j][3],
                             pah[0], pah[1], pah[2], pah[3], vlf[o], vlf[o + 2]);
                }
            }
        }
    }

    // Epilogue: y = O / l -> g_yc concat [hi|lo|hi]
    {
        const int b = bh >> 4, hh = bh & 15;
#pragma unroll
        for (int h = 0; h < 2; h++) {
            int t = q0 + wid * 16 + (lane >> 2) + h * 8;
            float invl = 1.f / lsum[h];
            __nv_bfloat16* yrow = g_yc + ((size_t)b * Tsz + t) * K3 + hh * Dsz;
#pragma unroll
            for (int j = 0; j < 8; j++) {
                int d = j * 8 + 2 * (lane & 3);
                float y0 = oa[j][2 * h] * invl;
                float y1 = oa[j][2 * h + 1] * invl;
                __nv_bfloat16 h0, l0, h1, l1;
                split2(y0, h0, l0); split2(y1, h1, l1);
                *(__nv_bfloat162*)&yrow[d]        = __nv_bfloat162(h0, h1);
                *(__nv_bfloat162*)&yrow[d + 1024] = __nv_bfloat162(l0, l1);
                *(__nv_bfloat162*)&yrow[d + 2048] = __nv_bfloat162(h0, h1);
            }
        }
    }
}

// ---------------------------------------------------------------------------
extern "C" void kernel_launch(void* const* d_in, const int* in_sizes, int n_in,
                              void* d_out, int out_size)
{
    const float* x    = (const float*)d_in[0];
    const float* Wqkv = (const float*)d_in[1];
    const float* bqkv = (const float*)d_in[2];
    const float* Wout = (const float*)d_in[3];
    const float* bout = (const float*)d_in[4];
    float* out = (float*)d_out;

    __nv_bfloat16 *xc, *yc, *wq, *wo;
    cudaGetSymbolAddress((void**)&xc, g_xc);
    cudaGetSymbolAddress((void**)&yc, g_yc);
    cudaGetSymbolAddress((void**)&wq, g_wq);
    cudaGetSymbolAddress((void**)&wo, g_wo);

    RopeTab tab;
    for (int i = 0; i < 32; i++)
        tab.inv[i] = (float)exp(-(double)(2 * i) / 64.0 * log(10000.0));

    // 0) conversions
    {
        int n = M1 * Csz;
        split_x_kernel<<<(n / 4 + 255) / 256, 256>>>(x, xc);
        dim3 g1(3 * Csz / 32, Csz / 32);
        transpose_split_kernel<<<g1, 256>>>(Wqkv, wq, 3 * Csz);
        dim3 g2(Csz / 32, Csz / 32);
        transpose_split_kernel<<<g2, 256>>>(Wout, wo, Csz);
    }

    // 1) QKV projection + fused RoPE/split/transpose epilogue
    {
        dim3 grid(3 * Csz / 128, M1 / 128);   // (24, 64)
        hmma_gemm_kernel<0><<<grid, 256>>>(xc, wq, bqkv, nullptr, tab);
    }

    // 2) HMMA causal flash attention -> g_yc
    {
        cudaFuncSetAttribute(attn_hmma_kernel, cudaFuncAttributeMaxDynamicSharedMemorySize, ATT_SMEM);
        dim3 grid(Tsz / 64, Bsz * Hsz);       // (32, 64)
        attn_hmma_kernel<<<grid, 128, ATT_SMEM>>>();
    }

    // 3) Output projection -> d_out
    {
        dim3 grid(Csz / 128, M1 / 128);       // (8, 64)
        hmma_gemm_kernel<1><<<grid, 256>>>(yc, wo, bout, out, tab);
    }
}

// round 6
// speedup vs baseline: 2.9252x; 1.3813x over previous
#include <cuda_runtime.h>
#include <cuda_bf16.h>
#include <math.h>
#include <stdint.h>

// Problem constants
#define Bsz 4
#define Tsz 2048
#define Csz 1024
#define Hsz 16
#define Dsz 64
#define M1 (Bsz * Tsz)        // 8192
#define K3 3072               // concatenated K: [hi | lo | hi]

// ---------------------------------------------------------------------------
// Device scratch (allocation-free)
// ---------------------------------------------------------------------------
__device__ __nv_bfloat16 g_qh[Bsz * Hsz * Tsz * Dsz];  // (B,H,T,D)
__device__ __nv_bfloat16 g_ql[Bsz * Hsz * Tsz * Dsz];
__device__ __nv_bfloat16 g_kh[Bsz * Hsz * Tsz * Dsz];
__device__ __nv_bfloat16 g_kl[Bsz * Hsz * Tsz * Dsz];
__device__ __nv_bfloat16 g_vth[Bsz * Hsz * Dsz * Tsz]; // (B,H,D,T) transposed
__device__ __nv_bfloat16 g_vtl[Bsz * Hsz * Dsz * Tsz];

__device__ __nv_bfloat16 g_xc[M1 * K3];          // x concat [Ah|Al|Ah]
__device__ __nv_bfloat16 g_yc[M1 * K3];          // attn out concat
__device__ __nv_bfloat16 g_wq[3 * Csz * K3];     // W_qkv^T concat [Bh|Bh|Bl]
__device__ __nv_bfloat16 g_wo[Csz * K3];         // W_out^T concat

// ---------------------------------------------------------------------------
__device__ __forceinline__ uint32_t smem_u32(const void* p) {
    uint32_t a;
    asm("{ .reg .u64 t; cvta.to.shared.u64 t, %1; cvt.u32.u64 %0, t; }" : "=r"(a) : "l"(p));
    return a;
}

__device__ __forceinline__ void split2(float v, __nv_bfloat16& hi, __nv_bfloat16& lo) {
    hi = __float2bfloat16(v);
    lo = __float2bfloat16(v - __bfloat162float(hi));
}

__device__ __forceinline__ void packsplit(float x, float y, uint32_t& h, uint32_t& l) {
    __nv_bfloat16 hx = __float2bfloat16(x), hy = __float2bfloat16(y);
    float lx = x - __bfloat162float(hx);
    float ly = y - __bfloat162float(hy);
    __nv_bfloat162 hv(hx, hy);
    __nv_bfloat162 lv = __floats2bfloat162_rn(lx, ly);
    h = *(uint32_t*)&hv;
    l = *(uint32_t*)&lv;
}

struct RopeTab { float inv[32]; };

// ---------------------------------------------------------------------------
// Conversions
// ---------------------------------------------------------------------------
__global__ __launch_bounds__(256)
void split_x_kernel(const float* __restrict__ in, __nv_bfloat16* __restrict__ outc)
{
    int i = (blockIdx.x * blockDim.x + threadIdx.x) * 4;
    if (i >= M1 * Csz) return;
    int m = i >> 10;
    int j = i & 1023;
    float4 v = *(const float4*)&in[i];
    __nv_bfloat16 h0, l0, h1, l1, h2, l2, h3, l3;
    split2(v.x, h0, l0); split2(v.y, h1, l1); split2(v.z, h2, l2); split2(v.w, h3, l3);
    __nv_bfloat162 hA(h0, h1), hB(h2, h3), lA(l0, l1), lB(l2, l3);
    __nv_bfloat16* row = outc + (size_t)m * K3;
    *(__nv_bfloat162*)&row[j]            = hA; *(__nv_bfloat162*)&row[j + 2]        = hB;
    *(__nv_bfloat162*)&row[1024 + j]     = lA; *(__nv_bfloat162*)&row[1024 + j + 2] = lB;
    *(__nv_bfloat162*)&row[2048 + j]     = hA; *(__nv_bfloat162*)&row[2048 + j + 2] = hB;
}

__global__ __launch_bounds__(256)
void transpose_split_kernel(const float* __restrict__ W, __nv_bfloat16* __restrict__ Wt, int N)
{
    __shared__ float ts[32][33];
    int k0 = blockIdx.y * 32, n0 = blockIdx.x * 32;
    int ty = threadIdx.x >> 5, tx = threadIdx.x & 31;
#pragma unroll
    for (int r = 0; r < 4; r++) {
        int row = ty + r * 8;
        ts[row][tx] = W[(size_t)(k0 + row) * N + n0 + tx];
    }
    __syncthreads();
#pragma unroll
    for (int r = 0; r < 4; r++) {
        int row = ty + r * 8;
        float v = ts[tx][row];
        __nv_bfloat16 h, l; split2(v, h, l);
        __nv_bfloat16* dst = Wt + (size_t)(n0 + row) * K3 + k0 + tx;
        dst[0]    = h;
        dst[1024] = h;
        dst[2048] = l;
    }
}

// ---------------------------------------------------------------------------
// HMMA / async macros
// ---------------------------------------------------------------------------
#define LDM_X4(r0, r1, r2, r3, addr) \
    asm volatile("ldmatrix.sync.aligned.m8n8.x4.shared.b16 {%0,%1,%2,%3}, [%4];" \
                 : "=r"(r0), "=r"(r1), "=r"(r2), "=r"(r3) : "r"(addr))

#define MMA16816(c0, c1, c2, c3, a0, a1, a2, a3, b0, b1) \
    asm volatile("mma.sync.aligned.m16n8k16.row.col.f32.bf16.bf16.f32 " \
                 "{%0,%1,%2,%3}, {%4,%5,%6,%7}, {%8,%9}, {%0,%1,%2,%3};" \
                 : "+f"(c0), "+f"(c1), "+f"(c2), "+f"(c3) \
                 : "r"(a0), "r"(a1), "r"(a2), "r"(a3), "r"(b0), "r"(b1))

#define CP16(sa, gp) \
    asm volatile("cp.async.cg.shared.global [%0], [%1], 16;" :: "r"(sa), "l"(gp))
#define CP_COMMIT() asm volatile("cp.async.commit_group;" ::: "memory")
#define CP_WAITG(n) asm volatile("cp.async.wait_group %0;" :: "n"(n) : "memory")

// swizzled offset within a 128B-row tile: logical (row, 16B-chunk c)
#define SWOFF(row, c) ((row) * 128 + (((c) ^ ((row) & 7)) * 16))

// ---------------------------------------------------------------------------
// HMMA GEMM: BM=128 BN=128 BK=64, 3-stage cp.async, swizzled smem.
// 256 thr (8 warps 4x2), warp tile 32x64.
// MODE 0: fused RoPE + split -> q/k (B,H,T,D), v -> transposed (B,H,D,T)
// MODE 1: row-major fp32 -> Cout
// ---------------------------------------------------------------------------
#define STAGEB 32768            // A tile 16KB + B tile 16KB
#define GEMM_SMEM (3 * STAGEB)  // 98304
#define TRS 272                 // trans row stride bytes (136 bf16)

template <int MODE>
__global__ __launch_bounds__(256, 2)
void hmma_gemm_kernel(const __nv_bfloat16* __restrict__ A, const __nv_bfloat16* __restrict__ Bt,
                      const float* __restrict__ bias, float* __restrict__ Cout,
                      RopeTab tab)
{
    extern __shared__ char smem_all[];

    const int tid = threadIdx.x;
    const int lane = tid & 31;
    const int wid = tid >> 5;
    const int wm = wid >> 1;            // 0..3
    const int wn = wid & 1;             // 0..1
    const int m0 = blockIdx.y * 128;
    const int n0 = blockIdx.x * 128;
    const uint32_t sbase = smem_u32(smem_all);
    const uint32_t lrow = lane & 15;
    const int nk = K3 / 64;             // 48

    auto issue_stage = [&](int kt) {
        if (kt < nk) {
            const uint32_t abuf = sbase + (kt % 3) * STAGEB;
            const uint32_t bbuf = abuf + 16384;
            const __nv_bfloat16* Ab = A + (size_t)m0 * K3 + kt * 64;
            const __nv_bfloat16* Bb = Bt + (size_t)n0 * K3 + kt * 64;
#pragma unroll
            for (int i = 0; i < 4; i++) {
                int chunk = tid + i * 256;      // 0..1023
                int row = chunk >> 3, c = chunk & 7;
                uint32_t off = SWOFF(row, c);
                CP16(abuf + off, Ab + (size_t)row * K3 + c * 8);
                CP16(bbuf + off, Bb + (size_t)row * K3 + c * 8);
            }
        }
        CP_COMMIT();
    };

    issue_stage(0);
    issue_stage(1);

    float acc[2][8][4];
#pragma unroll
    for (int i = 0; i < 2; i++)
#pragma unroll
        for (int j = 0; j < 8; j++)
#pragma unroll
            for (int q = 0; q < 4; q++) acc[i][j][q] = 0.f;

    for (int kt = 0; kt < nk; kt++) {
        CP_WAITG(1);
        __syncthreads();
        issue_stage(kt + 2);

        const uint32_t aBase = sbase + (kt % 3) * STAGEB;
        const uint32_t bBase = aBase + 16384;

#pragma unroll
        for (int ks = 0; ks < 4; ks++) {
            const uint32_t cc = ks * 2 + (lane >> 4);
            uint32_t af[2][4];
#pragma unroll
            for (int i = 0; i < 2; i++) {
                int row = wm * 32 + i * 16 + lrow;
                LDM_X4(af[i][0], af[i][1], af[i][2], af[i][3], aBase + SWOFF(row, cc));
            }
            uint32_t bf[4][4];
#pragma unroll
            for (int j2 = 0; j2 < 4; j2++) {
                int row = wn * 64 + j2 * 16 + lrow;
                LDM_X4(bf[j2][0], bf[j2][1], bf[j2][2], bf[j2][3], bBase + SWOFF(row, cc));
            }
#pragma unroll
            for (int i = 0; i < 2; i++)
#pragma unroll
                for (int j = 0; j < 8; j++) {
                    int j2 = j >> 1, o = j & 1;
                    MMA16816(acc[i][j][0], acc[i][j][1], acc[i][j][2], acc[i][j][3],
                             af[i][0], af[i][1], af[i][2], af[i][3],
                             bf[j2][o], bf[j2][o + 2]);
                }
        }
    }

    // ---------------- Epilogue ----------------
    if (MODE == 1) {
        const int mwb = m0 + wm * 32 + (lane >> 2);
        const int nwb = n0 + wn * 64 + 2 * (lane & 3);
#pragma unroll
        for (int i = 0; i < 2; i++)
#pragma unroll
            for (int j = 0; j < 8; j++) {
                int n = nwb + j * 8;
                float bx = bias[n], by = bias[n + 1];
#pragma unroll
                for (int half = 0; half < 2; half++) {
                    int m = mwb + i * 16 + half * 8;
                    *(float2*)&Cout[(size_t)m * Csz + n] =
                        make_float2(acc[i][j][half * 2] + bx, acc[i][j][half * 2 + 1] + by);
                }
            }
        return;
    }

    // MODE 0
    const int which = n0 >> 10;
    if (which < 2) {
        __nv_bfloat16* GH = (which == 0) ? g_qh : g_kh;
        __nv_bfloat16* GL = (which == 0) ? g_ql : g_kl;
        const int b = m0 >> 11;
        const int hh = ((n0 + wn * 64) & 1023) >> 6;
        const int bh = b * Hsz + hh;
        const int dbase = 2 * (lane & 3);
#pragma unroll
        for (int i = 0; i < 2; i++) {
#pragma unroll
            for (int half = 0; half < 2; half++) {
                int m = m0 + wm * 32 + (lane >> 2) + i * 16 + half * 8;
                int t = m & (Tsz - 1);
                size_t baseo = ((size_t)bh * Tsz + t) * Dsz;
#pragma unroll
                for (int j = 0; j < 4; j++) {
                    int n = n0 + wn * 64 + dbase + j * 8;
                    int d = n & 63;
                    float lowx  = acc[i][j][half * 2]     + bias[n];
                    float lowy  = acc[i][j][half * 2 + 1] + bias[n + 1];
                    float highx = acc[i][j + 4][half * 2]     + bias[n + 32];
                    float highy = acc[i][j + 4][half * 2 + 1] + bias[n + 33];
                    float c0f, s0f, c1f, s1f;
                    sincosf((float)t * tab.inv[d],     &s0f, &c0f);
                    sincosf((float)t * tab.inv[d + 1], &s1f, &c1f);
                    float nlx = lowx * c0f - highx * s0f;
                    float nhx = highx * c0f + lowx * s0f;
                    float nly = lowy * c1f - highy * s1f;
                    float nhy = highy * c1f + lowy * s1f;
                    __nv_bfloat16 hlx, llx, hly, lly, hhx, lhx, hhy, lhy;
                    split2(nlx, hlx, llx); split2(nly, hly, lly);
                    split2(nhx, hhx, lhx); split2(nhy, hhy, lhy);
                    *(__nv_bfloat162*)&GH[baseo + d]      = __nv_bfloat162(hlx, hly);
                    *(__nv_bfloat162*)&GL[baseo + d]      = __nv_bfloat162(llx, lly);
                    *(__nv_bfloat162*)&GH[baseo + d + 32] = __nv_bfloat162(hhx, hhy);
                    *(__nv_bfloat162*)&GL[baseo + d + 32] = __nv_bfloat162(lhx, lhy);
                }
            }
        }
    } else {
        // v: smem transpose, store split bf16 to (B,H,D,T)
        const int b = m0 >> 11;
        const int t0 = m0 & (Tsz - 1);
        __nv_bfloat16* trs = (__nv_bfloat16*)smem_all;
#pragma unroll
        for (int pass = 0; pass < 2; pass++) {
            __syncthreads();
#pragma unroll
            for (int i = 0; i < 2; i++)
#pragma unroll
                for (int half = 0; half < 2; half++) {
                    int ml = wm * 32 + (lane >> 2) + i * 16 + half * 8;
#pragma unroll
                    for (int j = 0; j < 8; j++) {
                        int nl = wn * 64 + 2 * (lane & 3) + j * 8;
                        float vx = acc[i][j][half * 2]     + bias[n0 + nl];
                        float vy = acc[i][j][half * 2 + 1] + bias[n0 + nl + 1];
                        __nv_bfloat16 hx, lx, hy, ly;
                        split2(vx, hx, lx); split2(vy, hy, ly);
                        trs[nl * 136 + ml]       = pass ? lx : hx;
                        trs[(nl + 1) * 136 + ml] = pass ? ly : hy;
                    }
                }
            __syncthreads();
            __nv_bfloat16* dstArr = pass ? g_vtl : g_vth;
#pragma unroll
            for (int rr = 0; rr < 8; rr++) {
                int row = (tid >> 4) + rr * 16;
                int chunk = tid & 15;
                int n = n0 + row;
                int hh = (n & 1023) >> 6;
                int d = n & 63;
                float4 v = *(float4*)((char*)trs + row * TRS + chunk * 16);
                *(float4*)&dstArr[((size_t)(b * Hsz + hh) * Dsz + d) * Tsz + t0 + chunk * 8] = v;
            }
        }
    }
}

// ---------------------------------------------------------------------------
// HMMA flash attention, causal. BM=128 (8 warps x 16 rows), BN=64, D=64.
// Swizzled smem, double-buffered cp.async K/V, bf16x3 on both matmuls.
// ---------------------------------------------------------------------------
#define ATT_SMEM (32768 + 2 * 32768)   // Q(hi,lo) + 2 KV stages = 98304

__global__ __launch_bounds__(256, 2)
void attn_hmma_kernel()
{
    extern __shared__ char asmem[];

    const int tid = threadIdx.x;
    const int lane = tid & 31;
    const int wid = tid >> 5;              // 0..7
    const int q0 = (int)(gridDim.x - 1 - blockIdx.x) * 128;  // heavy tiles first
    const int bh = blockIdx.y;
    const uint32_t sb = smem_u32(asmem);
    const uint32_t qhB = sb, qlB = sb + 16384;
    const uint32_t lrow = lane & 15;
    const int nt = q0 / 64 + 2;

    // issue Q(hi,lo) loads (committed with KV stage 0 below)
    {
        const size_t qg = ((size_t)bh * Tsz + q0) * Dsz;
#pragma unroll
        for (int i = 0; i < 4; i++) {
            int chunk = tid + i * 256;      // 0..1023
            int row = chunk >> 3, c = chunk & 7;
            uint32_t off = SWOFF(row, c);
            CP16(qhB + off, g_qh + qg + (size_t)row * Dsz + c * 8);
            CP16(qlB + off, g_ql + qg + (size_t)row * Dsz + c * 8);
        }
    }

    auto issue_kv = [&](int jt) {
        if (jt < nt) {
            const int js = jt * 64;
            const uint32_t base = sb + 32768 + (jt & 1) * 32768;
            const size_t kg = ((size_t)bh * Tsz + js) * Dsz;
            const size_t vg = (size_t)bh * Dsz * Tsz + js;
#pragma unroll
            for (int i = 0; i < 2; i++) {
                int chunk = tid + i * 256;  // 0..511
                int row = chunk >> 3, c = chunk & 7;
                uint32_t off = SWOFF(row, c);
                CP16(base + off,         g_kh + kg + (size_t)row * Dsz + c * 8);
                CP16(base + 8192 + off,  g_kl + kg + (size_t)row * Dsz + c * 8);
                CP16(base + 16384 + off, g_vth + vg + (size_t)row * Tsz + c * 8);
                CP16(base + 24576 + off, g_vtl + vg + (size_t)row * Tsz + c * 8);
            }
        }
        CP_COMMIT();
    };

    issue_kv(0);   // group 0 = Q + KV0

    float mrow[2] = { -INFINITY, -INFINITY };
    float lsum[2] = { 0.f, 0.f };
    float oa[8][4];
#pragma unroll
    for (int j = 0; j < 8; j++)
#pragma unroll
        for (int q = 0; q < 4; q++) oa[j][q] = 0.f;

    for (int jt = 0; jt < nt; jt++) {
        __syncthreads();                   // all warps done reading buf (jt+1)&1
        issue_kv(jt + 1);
        CP_WAITG(1);
        __syncthreads();

        const int js = jt * 64;
        const uint32_t kvb = sb + 32768 + (jt & 1) * 32768;
        const uint32_t khB = kvb, klB = kvb + 8192;
        const uint32_t vhB = kvb + 16384, vlB = kvb + 24576;

        // S = Qh Kh^T + Ql Kh^T + Qh Kl^T
        float s[8][4];
#pragma unroll
        for (int j = 0; j < 8; j++)
#pragma unroll
            for (int q = 0; q < 4; q++) s[j][q] = 0.f;

#pragma unroll
        for (int ks = 0; ks < 4; ks++) {
            const uint32_t cc = ks * 2 + (lane >> 4);
            uint32_t qhf[4], qlf[4];
            {
                int row = wid * 16 + lrow;
                LDM_X4(qhf[0], qhf[1], qhf[2], qhf[3], qhB + SWOFF(row, cc));
                LDM_X4(qlf[0], qlf[1], qlf[2], qlf[3], qlB + SWOFF(row, cc));
            }
#pragma unroll
            for (int j2 = 0; j2 < 4; j2++) {
                int row = j2 * 16 + lrow;
                uint32_t off = SWOFF(row, cc);
                uint32_t khf[4], klf[4];
                LDM_X4(khf[0], khf[1], khf[2], khf[3], khB + off);
                LDM_X4(klf[0], klf[1], klf[2], klf[3], klB + off);
#pragma unroll
                for (int o = 0; o < 2; o++) {
                    int j = 2 * j2 + o;
                    MMA16816(s[j][0], s[j][1], s[j][2], s[j][3],
                             qhf[0], qhf[1], qhf[2], qhf[3], khf[o], khf[o + 2]);
                    MMA16816(s[j][0], s[j][1], s[j][2], s[j][3],
                             qlf[0], qlf[1], qlf[2], qlf[3], khf[o], khf[o + 2]);
                    MMA16816(s[j][0], s[j][1], s[j][2], s[j][3],
                             qhf[0], qhf[1], qhf[2], qhf[3], klf[o], klf[o + 2]);
                }
            }
        }

        // Causal mask (only tiles touching/past the diagonal)
        if (js >= q0) {
#pragma unroll
            for (int j = 0; j < 8; j++)
#pragma unroll
                for (int q = 0; q < 4; q++) {
                    int col = js + j * 8 + 2 * (lane & 3) + (q & 1);
                    int row = q0 + wid * 16 + (lane >> 2) + (q >> 1) * 8;
                    if (col > row) s[j][q] = -INFINITY;
                }
        }

        // Online softmax (rows in quads; reduce via shfl_xor 1,2)
#pragma unroll
        for (int h = 0; h < 2; h++) {
            float mx = -INFINITY;
#pragma unroll
            for (int j = 0; j < 8; j++)
                mx = fmaxf(mx, fmaxf(s[j][2 * h], s[j][2 * h + 1]));
            mx = fmaxf(mx, __shfl_xor_sync(0xffffffffu, mx, 1));
            mx = fmaxf(mx, __shfl_xor_sync(0xffffffffu, mx, 2));
            float nm = fmaxf(mrow[h], mx);
            float alpha = __expf(mrow[h] - nm);
            float sum = 0.f;
#pragma unroll
            for (int j = 0; j < 8; j++) {
                float p0 = __expf(s[j][2 * h] - nm);
                float p1 = __expf(s[j][2 * h + 1] - nm);
                s[j][2 * h] = p0; s[j][2 * h + 1] = p1;
                sum += p0 + p1;
            }
            sum += __shfl_xor_sync(0xffffffffu, sum, 1);
            sum += __shfl_xor_sync(0xffffffffu, sum, 2);
            lsum[h] = lsum[h] * alpha + sum;
            mrow[h] = nm;
#pragma unroll
            for (int j = 0; j < 8; j++) {
                oa[j][2 * h] *= alpha;
                oa[j][2 * h + 1] *= alpha;
            }
        }

        // O += Ph Vh + Pl Vh + Ph Vl
#pragma unroll
        for (int kt2 = 0; kt2 < 4; kt2++) {
            uint32_t pah[4], pal[4];
            packsplit(s[2 * kt2][0],     s[2 * kt2][1],     pah[0], pal[0]);
            packsplit(s[2 * kt2][2],     s[2 * kt2][3],     pah[1], pal[1]);
            packsplit(s[2 * kt2 + 1][0], s[2 * kt2 + 1][1], pah[2], pal[2]);
            packsplit(s[2 * kt2 + 1][2], s[2 * kt2 + 1][3], pah[3], pal[3]);
            const uint32_t cc = kt2 * 2 + (lane >> 4);
#pragma unroll
            for (int j2 = 0; j2 < 4; j2++) {
                int row = j2 * 16 + lrow;
                uint32_t off = SWOFF(row, cc);
                uint32_t vhf[4], vlf[4];
                LDM_X4(vhf[0], vhf[1], vhf[2], vhf[3], vhB + off);
                LDM_X4(vlf[0], vlf[1], vlf[2], vlf[3], vlB + off);
#pragma unroll
                for (int o = 0; o < 2; o++) {
                    int j = 2 * j2 + o;
                    MMA16816(oa[j][0], oa[j][1], oa[j][2], oa[j][3],
                             pah[0], pah[1], pah[2], pah[3], vhf[o], vhf[o + 2]);
                    MMA16816(oa[j][0], oa[j][1], oa[j][2], oa[j][3],
                             pal[0], pal[1], pal[2], pal[3], vhf[o], vhf[o + 2]);
                    MMA16816(oa[j][0], oa[j][1], oa[j][2], oa[j][3],
                             pah[0], pah[1], pah[2], pah[3], vlf[o], vlf[o + 2]);
                }
            }
        }
    }

    // Epilogue: y = O / l -> g_yc concat [hi|lo|hi]
    {
        const int b = bh >> 4, hh = bh & 15;
#pragma unroll
        for (int h = 0; h < 2; h++) {
            int t = q0 + wid * 16 + (lane >> 2) + h * 8;
            float invl = 1.f / lsum[h];
            __nv_bfloat16* yrow = g_yc + ((size_t)b * Tsz + t) * K3 + hh * Dsz;
#pragma unroll
            for (int j = 0; j < 8; j++) {
                int d = j * 8 + 2 * (lane & 3);
                float y0 = oa[j][2 * h] * invl;
                float y1 = oa[j][2 * h + 1] * invl;
                __nv_bfloat16 h0, l0, h1, l1;
                split2(y0, h0, l0); split2(y1, h1, l1);
                *(__nv_bfloat162*)&yrow[d]        = __nv_bfloat162(h0, h1);
                *(__nv_bfloat162*)&yrow[d + 1024] = __nv_bfloat162(l0, l1);
                *(__nv_bfloat162*)&yrow[d + 2048] = __nv_bfloat162(h0, h1);
            }
        }
    }
}

// ---------------------------------------------------------------------------
extern "C" void kernel_launch(void* const* d_in, const int* in_sizes, int n_in,
                              void* d_out, int out_size)
{
    const float* x    = (const float*)d_in[0];
    const float* Wqkv = (const float*)d_in[1];
    const float* bqkv = (const float*)d_in[2];
    const float* Wout = (const float*)d_in[3];
    const float* bout = (const float*)d_in[4];
    float* out = (float*)d_out;

    __nv_bfloat16 *xc, *yc, *wq, *wo;
    cudaGetSymbolAddress((void**)&xc, g_xc);
    cudaGetSymbolAddress((void**)&yc, g_yc);
    cudaGetSymbolAddress((void**)&wq, g_wq);
    cudaGetSymbolAddress((void**)&wo, g_wo);

    RopeTab tab;
    for (int i = 0; i < 32; i++)
        tab.inv[i] = (float)exp(-(double)(2 * i) / 64.0 * log(10000.0));

    // 0) conversions
    {
        int n = M1 * Csz;
        split_x_kernel<<<(n / 4 + 255) / 256, 256>>>(x, xc);
        dim3 g1(3 * Csz / 32, Csz / 32);
        transpose_split_kernel<<<g1, 256>>>(Wqkv, wq, 3 * Csz);
        dim3 g2(Csz / 32, Csz / 32);
        transpose_split_kernel<<<g2, 256>>>(Wout, wo, Csz);
    }

    // 1) QKV projection + fused RoPE/split/transpose epilogue
    {
        cudaFuncSetAttribute(hmma_gemm_kernel<0>, cudaFuncAttributeMaxDynamicSharedMemorySize, GEMM_SMEM);
        dim3 grid(3 * Csz / 128, M1 / 128);   // (24, 64)
        hmma_gemm_kernel<0><<<grid, 256, GEMM_SMEM>>>(xc, wq, bqkv, nullptr, tab);
    }

    // 2) HMMA causal flash attention (BM=128) -> g_yc
    {
        cudaFuncSetAttribute(attn_hmma_kernel, cudaFuncAttributeMaxDynamicSharedMemorySize, ATT_SMEM);
        dim3 grid(Tsz / 128, Bsz * Hsz);      // (16, 64)
        attn_hmma_kernel<<<grid, 256, ATT_SMEM>>>();
    }

    // 3) Output projection -> d_out
    {
        cudaFuncSetAttribute(hmma_gemm_kernel<1>, cudaFuncAttributeMaxDynamicSharedMemorySize, GEMM_SMEM);
        dim3 grid(Csz / 128, M1 / 128);       // (8, 64)
        hmma_gemm_kernel<1><<<grid, 256, GEMM_SMEM>>>(yc, wo, bout, out, tab);
    }
}

// round 7
// speedup vs baseline: 3.2622x; 1.1152x over previous
#include <cuda_runtime.h>
#include <cuda_bf16.h>
#include <cuda_fp16.h>
#include <math.h>
#include <stdint.h>

// Problem constants
#define Bsz 4
#define Tsz 2048
#define Csz 1024
#define Hsz 16
#define Dsz 64
#define M1 (Bsz * Tsz)        // 8192
#define K3 3072               // QKV concatenated K: [hi | lo | hi] (bf16x3)
#define K2 2048               // outproj concatenated K: [yh | yl] (fp16x2)

// ---------------------------------------------------------------------------
// Device scratch (allocation-free)
// ---------------------------------------------------------------------------
__device__ __nv_bfloat16 g_qh[Bsz * Hsz * Tsz * Dsz];  // (B,H,T,D)
__device__ __nv_bfloat16 g_ql[Bsz * Hsz * Tsz * Dsz];
__device__ __nv_bfloat16 g_kh[Bsz * Hsz * Tsz * Dsz];
__device__ __nv_bfloat16 g_kl[Bsz * Hsz * Tsz * Dsz];
__device__ __half        g_vt[Bsz * Hsz * Dsz * Tsz];  // (B,H,D,T) fp16

__device__ __nv_bfloat16 g_xc[M1 * K3];          // x concat [Ah|Al|Ah]
__device__ __half        g_yc[M1 * K2];          // attn out concat [yh|yl] fp16
__device__ __nv_bfloat16 g_wq[3 * Csz * K3];     // W_qkv^T concat [Bh|Bh|Bl]
__device__ __half        g_wo[Csz * K2];         // W_out^T concat [Wh|Wh] fp16

// ---------------------------------------------------------------------------
__device__ __forceinline__ uint32_t smem_u32(const void* p) {
    uint32_t a;
    asm("{ .reg .u64 t; cvta.to.shared.u64 t, %1; cvt.u32.u64 %0, t; }" : "=r"(a) : "l"(p));
    return a;
}

__device__ __forceinline__ void split2(float v, __nv_bfloat16& hi, __nv_bfloat16& lo) {
    hi = __float2bfloat16(v);
    lo = __float2bfloat16(v - __bfloat162float(hi));
}
__device__ __forceinline__ void split2h(float v, __half& hi, __half& lo) {
    hi = __float2half(v);
    lo = __float2half(v - __half2float(hi));
}

// P split into fp16 hi/lo pairs (packed)
__device__ __forceinline__ void packsplit_h(float x, float y, uint32_t& h, uint32_t& l) {
    __half hx = __float2half(x), hy = __float2half(y);
    float lx = x - __half2float(hx);
    float ly = y - __half2float(hy);
    __half2 hv(hx, hy);
    __half2 lv(__float2half(lx), __float2half(ly));
    h = *(uint32_t*)&hv;
    l = *(uint32_t*)&lv;
}

struct RopeTab { float inv[32]; };

// ---------------------------------------------------------------------------
// Conversions
// ---------------------------------------------------------------------------
__global__ __launch_bounds__(256)
void split_x_kernel(const float* __restrict__ in, __nv_bfloat16* __restrict__ outc)
{
    int i = (blockIdx.x * blockDim.x + threadIdx.x) * 4;
    if (i >= M1 * Csz) return;
    int m = i >> 10;
    int j = i & 1023;
    float4 v = *(const float4*)&in[i];
    __nv_bfloat16 h0, l0, h1, l1, h2, l2, h3, l3;
    split2(v.x, h0, l0); split2(v.y, h1, l1); split2(v.z, h2, l2); split2(v.w, h3, l3);
    __nv_bfloat162 hA(h0, h1), hB(h2, h3), lA(l0, l1), lB(l2, l3);
    __nv_bfloat16* row = outc + (size_t)m * K3;
    *(__nv_bfloat162*)&row[j]            = hA; *(__nv_bfloat162*)&row[j + 2]        = hB;
    *(__nv_bfloat162*)&row[1024 + j]     = lA; *(__nv_bfloat162*)&row[1024 + j + 2] = lB;
    *(__nv_bfloat162*)&row[2048 + j]     = hA; *(__nv_bfloat162*)&row[2048 + j + 2] = hB;
}

// W_qkv [1024][N] -> Wt bf16 [N][3072] = [hi | hi | lo]
__global__ __launch_bounds__(256)
void transpose_split_kernel(const float* __restrict__ W, __nv_bfloat16* __restrict__ Wt, int N)
{
    __shared__ float ts[32][33];
    int k0 = blockIdx.y * 32, n0 = blockIdx.x * 32;
    int ty = threadIdx.x >> 5, tx = threadIdx.x & 31;
#pragma unroll
    for (int r = 0; r < 4; r++) {
        int row = ty + r * 8;
        ts[row][tx] = W[(size_t)(k0 + row) * N + n0 + tx];
    }
    __syncthreads();
#pragma unroll
    for (int r = 0; r < 4; r++) {
        int row = ty + r * 8;
        float v = ts[tx][row];
        __nv_bfloat16 h, l; split2(v, h, l);
        __nv_bfloat16* dst = Wt + (size_t)(n0 + row) * K3 + k0 + tx;
        dst[0]    = h;
        dst[1024] = h;
        dst[2048] = l;
    }
}

// W_out [1024][1024] -> Wt fp16 [N][2048] = [hi | hi]
__global__ __launch_bounds__(256)
void transpose_h_kernel(const float* __restrict__ W, __half* __restrict__ Wt, int N)
{
    __shared__ float ts[32][33];
    int k0 = blockIdx.y * 32, n0 = blockIdx.x * 32;
    int ty = threadIdx.x >> 5, tx = threadIdx.x & 31;
#pragma unroll
    for (int r = 0; r < 4; r++) {
        int row = ty + r * 8;
        ts[row][tx] = W[(size_t)(k0 + row) * N + n0 + tx];
    }
    __syncthreads();
#pragma unroll
    for (int r = 0; r < 4; r++) {
        int row = ty + r * 8;
        __half h = __float2half(ts[tx][row]);
        __half* dst = Wt + (size_t)(n0 + row) * K2 + k0 + tx;
        dst[0]    = h;
        dst[1024] = h;
    }
}

// ---------------------------------------------------------------------------
// HMMA / async macros
// ---------------------------------------------------------------------------
#define LDM_X4(r0, r1, r2, r3, addr) \
    asm volatile("ldmatrix.sync.aligned.m8n8.x4.shared.b16 {%0,%1,%2,%3}, [%4];" \
                 : "=r"(r0), "=r"(r1), "=r"(r2), "=r"(r3) : "r"(addr))

#define MMA16816(c0, c1, c2, c3, a0, a1, a2, a3, b0, b1) \
    asm volatile("mma.sync.aligned.m16n8k16.row.col.f32.bf16.bf16.f32 " \
                 "{%0,%1,%2,%3}, {%4,%5,%6,%7}, {%8,%9}, {%0,%1,%2,%3};" \
                 : "+f"(c0), "+f"(c1), "+f"(c2), "+f"(c3) \
                 : "r"(a0), "r"(a1), "r"(a2), "r"(a3), "r"(b0), "r"(b1))

#define MMA16816H(c0, c1, c2, c3, a0, a1, a2, a3, b0, b1) \
    asm volatile("mma.sync.aligned.m16n8k16.row.col.f32.f16.f16.f32 " \
                 "{%0,%1,%2,%3}, {%4,%5,%6,%7}, {%8,%9}, {%0,%1,%2,%3};" \
                 : "+f"(c0), "+f"(c1), "+f"(c2), "+f"(c3) \
                 : "r"(a0), "r"(a1), "r"(a2), "r"(a3), "r"(b0), "r"(b1))

#define CP16(sa, gp) \
    asm volatile("cp.async.cg.shared.global [%0], [%1], 16;" :: "r"(sa), "l"(gp))
#define CP_COMMIT() asm volatile("cp.async.commit_group;" ::: "memory")
#define CP_WAITG(n) asm volatile("cp.async.wait_group %0;" :: "n"(n) : "memory")

// swizzled offset within a 128B-row tile: logical (row, 16B-chunk c)
#define SWOFF(row, c) ((row) * 128 + (((c) ^ ((row) & 7)) * 16))

// ---------------------------------------------------------------------------
// HMMA GEMM: BM=128 BN=128 BK=64, 3-stage cp.async, swizzled smem.
// 256 thr (8 warps 4x2), warp tile 32x64.
// MODE 0: bf16, KLEN=3072, fused RoPE/split epilogue -> q/k (B,H,T,D), v -> (B,H,D,T) fp16
// MODE 1: fp16, KLEN=2048, row-major fp32 -> Cout
// ---------------------------------------------------------------------------
#define STAGEB 32768            // A tile 16KB + B tile 16KB
#define GEMM_SMEM (3 * STAGEB)  // 98304
#define TRS 272                 // trans row stride bytes (136 halves)

template <int MODE, int KLEN>
__global__ __launch_bounds__(256, 2)
void hmma_gemm_kernel(const uint16_t* __restrict__ A, const uint16_t* __restrict__ Bt,
                      const float* __restrict__ bias, float* __restrict__ Cout,
                      RopeTab tab)
{
    extern __shared__ char smem_all[];

    const int tid = threadIdx.x;
    const int lane = tid & 31;
    const int wid = tid >> 5;
    const int wm = wid >> 1;            // 0..3
    const int wn = wid & 1;             // 0..1
    const int m0 = blockIdx.y * 128;
    const int n0 = blockIdx.x * 128;
    const uint32_t sbase = smem_u32(smem_all);
    const uint32_t lrow = lane & 15;
    const int nk = KLEN / 64;

    auto issue_stage = [&](int kt) {
        if (kt < nk) {
            const uint32_t abuf = sbase + (kt % 3) * STAGEB;
            const uint32_t bbuf = abuf + 16384;
            const uint16_t* Ab = A + (size_t)m0 * KLEN + kt * 64;
            const uint16_t* Bb = Bt + (size_t)n0 * KLEN + kt * 64;
#pragma unroll
            for (int i = 0; i < 4; i++) {
                int chunk = tid + i * 256;      // 0..1023
                int row = chunk >> 3, c = chunk & 7;
                uint32_t off = SWOFF(row, c);
                CP16(abuf + off, Ab + (size_t)row * KLEN + c * 8);
                CP16(bbuf + off, Bb + (size_t)row * KLEN + c * 8);
            }
        }
        CP_COMMIT();
    };

    issue_stage(0);
    issue_stage(1);

    float acc[2][8][4];
#pragma unroll
    for (int i = 0; i < 2; i++)
#pragma unroll
        for (int j = 0; j < 8; j++)
#pragma unroll
            for (int q = 0; q < 4; q++) acc[i][j][q] = 0.f;

    for (int kt = 0; kt < nk; kt++) {
        CP_WAITG(1);
        __syncthreads();

        const uint32_t aBase = sbase + (kt % 3) * STAGEB;
        const uint32_t bBase = aBase + 16384;

#pragma unroll
        for (int ks = 0; ks < 4; ks++) {
            const uint32_t cc = ks * 2 + (lane >> 4);
            uint32_t af[2][4];
#pragma unroll
            for (int i = 0; i < 2; i++) {
                int row = wm * 32 + i * 16 + lrow;
                LDM_X4(af[i][0], af[i][1], af[i][2], af[i][3], aBase + SWOFF(row, cc));
            }
            uint32_t bf[4][4];
#pragma unroll
            for (int j2 = 0; j2 < 4; j2++) {
                int row = wn * 64 + j2 * 16 + lrow;
                LDM_X4(bf[j2][0], bf[j2][1], bf[j2][2], bf[j2][3], bBase + SWOFF(row, cc));
            }
            if (ks == 0) issue_stage(kt + 2);   // overlap cp issue with MMAs
#pragma unroll
            for (int i = 0; i < 2; i++)
#pragma unroll
                for (int j = 0; j < 8; j++) {
                    int j2 = j >> 1, o = j & 1;
                    if (MODE == 0) {
                        MMA16816(acc[i][j][0], acc[i][j][1], acc[i][j][2], acc[i][j][3],
                                 af[i][0], af[i][1], af[i][2], af[i][3],
                                 bf[j2][o], bf[j2][o + 2]);
                    } else {
                        MMA16816H(acc[i][j][0], acc[i][j][1], acc[i][j][2], acc[i][j][3],
                                  af[i][0], af[i][1], af[i][2], af[i][3],
                                  bf[j2][o], bf[j2][o + 2]);
                    }
                }
        }
    }

    // ---------------- Epilogue ----------------
    if (MODE == 1) {
        const int mwb = m0 + wm * 32 + (lane >> 2);
        const int nwb = n0 + wn * 64 + 2 * (lane & 3);
#pragma unroll
        for (int i = 0; i < 2; i++)
#pragma unroll
            for (int j = 0; j < 8; j++) {
                int n = nwb + j * 8;
                float bx = bias[n], by = bias[n + 1];
#pragma unroll
                for (int half2i = 0; half2i < 2; half2i++) {
                    int m = mwb + i * 16 + half2i * 8;
                    *(float2*)&Cout[(size_t)m * Csz + n] =
                        make_float2(acc[i][j][half2i * 2] + bx, acc[i][j][half2i * 2 + 1] + by);
                }
            }
        return;
    }

    // MODE 0
    const int which = n0 >> 10;
    if (which < 2) {
        __nv_bfloat16* GH = (which == 0) ? g_qh : g_kh;
        __nv_bfloat16* GL = (which == 0) ? g_ql : g_kl;
        const int b = m0 >> 11;
        const int hh = ((n0 + wn * 64) & 1023) >> 6;
        const int bh = b * Hsz + hh;
        const int dbase = 2 * (lane & 3);
#pragma unroll
        for (int i = 0; i < 2; i++) {
#pragma unroll
            for (int half2i = 0; half2i < 2; half2i++) {
                int m = m0 + wm * 32 + (lane >> 2) + i * 16 + half2i * 8;
                int t = m & (Tsz - 1);
                size_t baseo = ((size_t)bh * Tsz + t) * Dsz;
#pragma unroll
                for (int j = 0; j < 4; j++) {
                    int n = n0 + wn * 64 + dbase + j * 8;
                    int d = n & 63;
                    float lowx  = acc[i][j][half2i * 2]     + bias[n];
                    float lowy  = acc[i][j][half2i * 2 + 1] + bias[n + 1];
                    float highx = acc[i][j + 4][half2i * 2]     + bias[n + 32];
                    float highy = acc[i][j + 4][half2i * 2 + 1] + bias[n + 33];
                    float c0f, s0f, c1f, s1f;
                    sincosf((float)t * tab.inv[d],     &s0f, &c0f);
                    sincosf((float)t * tab.inv[d + 1], &s1f, &c1f);
                    float nlx = lowx * c0f - highx * s0f;
                    float nhx = highx * c0f + lowx * s0f;
                    float nly = lowy * c1f - highy * s1f;
                    float nhy = highy * c1f + lowy * s1f;
                    __nv_bfloat16 hlx, llx, hly, lly, hhx, lhx, hhy, lhy;
                    split2(nlx, hlx, llx); split2(nly, hly, lly);
                    split2(nhx, hhx, lhx); split2(nhy, hhy, lhy);
                    *(__nv_bfloat162*)&GH[baseo + d]      = __nv_bfloat162(hlx, hly);
                    *(__nv_bfloat162*)&GL[baseo + d]      = __nv_bfloat162(llx, lly);
                    *(__nv_bfloat162*)&GH[baseo + d + 32] = __nv_bfloat162(hhx, hhy);
                    *(__nv_bfloat162*)&GL[baseo + d + 32] = __nv_bfloat162(lhx, lhy);
                }
            }
        }
    } else {
        // v: smem transpose, store fp16 to (B,H,D,T)
        const int b = m0 >> 11;
        const int t0 = m0 & (Tsz - 1);
        __half* trs = (__half*)smem_all;
        __syncthreads();
#pragma unroll
        for (int i = 0; i < 2; i++)
#pragma unroll
            for (int half2i = 0; half2i < 2; half2i++) {
                int ml = wm * 32 + (lane >> 2) + i * 16 + half2i * 8;
#pragma unroll
                for (int j = 0; j < 8; j++) {
                    int nl = wn * 64 + 2 * (lane & 3) + j * 8;
                    float vx = acc[i][j][half2i * 2]     + bias[n0 + nl];
                    float vy = acc[i][j][half2i * 2 + 1] + bias[n0 + nl + 1];
                    trs[nl * 136 + ml]       = __float2half(vx);
                    trs[(nl + 1) * 136 + ml] = __float2half(vy);
                }
            }
        __syncthreads();
#pragma unroll
        for (int rr = 0; rr < 8; rr++) {
            int row = (tid >> 4) + rr * 16;
            int chunk = tid & 15;
            int n = n0 + row;
            int hh = (n & 1023) >> 6;
            int d = n & 63;
            float4 v = *(float4*)((char*)trs + row * TRS + chunk * 16);
            *(float4*)&g_vt[((size_t)(b * Hsz + hh) * Dsz + d) * Tsz + t0 + chunk * 8] = v;
        }
    }
}

// ---------------------------------------------------------------------------
// HMMA flash attention, causal. BM=128 (8 warps x 16 rows), BN=64, D=64.
// S: bf16x3 (Qh/Ql x Kh/Kl). PV: fp16x2 (Ph+Pl) x Vh. 3-stage KV, 1 barrier/iter.
// ---------------------------------------------------------------------------
#define KVSTAGE 24576                       // kh 8K + kl 8K + vh 8K
#define ATT_SMEM (32768 + 3 * KVSTAGE)      // Q(hi,lo) + 3 KV stages = 106496

__global__ __launch_bounds__(256, 2)
void attn_hmma_kernel()
{
    extern __shared__ char asmem[];

    const int tid = threadIdx.x;
    const int lane = tid & 31;
    const int wid = tid >> 5;              // 0..7
    const int q0 = (int)(gridDim.x - 1 - blockIdx.x) * 128;  // heavy tiles first
    const int bh = blockIdx.y;
    const uint32_t sb = smem_u32(asmem);
    const uint32_t qhB = sb, qlB = sb + 16384;
    const uint32_t lrow = lane & 15;
    const int nt = q0 / 64 + 2;

    // issue Q(hi,lo) loads (committed with KV stage 0 below)
    {
        const size_t qg = ((size_t)bh * Tsz + q0) * Dsz;
#pragma unroll
        for (int i = 0; i < 4; i++) {
            int chunk = tid + i * 256;      // 0..1023
            int row = chunk >> 3, c = chunk & 7;
            uint32_t off = SWOFF(row, c);
            CP16(qhB + off, g_qh + qg + (size_t)row * Dsz + c * 8);
            CP16(qlB + off, g_ql + qg + (size_t)row * Dsz + c * 8);
        }
    }

    auto issue_kv = [&](int jt) {
        if (jt < nt) {
            const int js = jt * 64;
            const uint32_t base = sb + 32768 + (jt % 3) * KVSTAGE;
            const size_t kg = ((size_t)bh * Tsz + js) * Dsz;
            const size_t vg = (size_t)bh * Dsz * Tsz + js;
#pragma unroll
            for (int i = 0; i < 2; i++) {
                int chunk = tid + i * 256;  // 0..511
                int row = chunk >> 3, c = chunk & 7;
                uint32_t off = SWOFF(row, c);
                CP16(base + off,         g_kh + kg + (size_t)row * Dsz + c * 8);
                CP16(base + 8192 + off,  g_kl + kg + (size_t)row * Dsz + c * 8);
                CP16(base + 16384 + off, g_vt + vg + (size_t)row * Tsz + c * 8);
            }
        }
        CP_COMMIT();
    };

    issue_kv(0);   // group 0 = Q + KV0
    issue_kv(1);   // group 1

    float mrow[2] = { -INFINITY, -INFINITY };
    float lsum[2] = { 0.f, 0.f };
    float oa[8][4];
#pragma unroll
    for (int j = 0; j < 8; j++)
#pragma unroll
        for (int q = 0; q < 4; q++) oa[j][q] = 0.f;

    for (int jt = 0; jt < nt; jt++) {
        CP_WAITG(1);
        __syncthreads();       // stage jt visible to all; stage buffers (jt+2)%3 free

        const int js = jt * 64;
        const uint32_t kvb = sb + 32768 + (jt % 3) * KVSTAGE;
        const uint32_t khB = kvb, klB = kvb + 8192;
        const uint32_t vhB = kvb + 16384;

        // S = Qh Kh^T + Ql Kh^T + Qh Kl^T
        float s[8][4];
#pragma unroll
        for (int j = 0; j < 8; j++)
#pragma unroll
            for (int q = 0; q < 4; q++) s[j][q] = 0.f;

#pragma unroll
        for (int ks = 0; ks < 4; ks++) {
            const uint32_t cc = ks * 2 + (lane >> 4);
            uint32_t qhf[4], qlf[4];
            {
                int row = wid * 16 + lrow;
                LDM_X4(qhf[0], qhf[1], qhf[2], qhf[3], qhB + SWOFF(row, cc));
                LDM_X4(qlf[0], qlf[1], qlf[2], qlf[3], qlB + SWOFF(row, cc));
            }
            if (ks == 0) issue_kv(jt + 2);   // overlap cp issue with compute
#pragma unroll
            for (int j2 = 0; j2 < 4; j2++) {
                int row = j2 * 16 + lrow;
                uint32_t off = SWOFF(row, cc);
                uint32_t khf[4], klf[4];
                LDM_X4(khf[0], khf[1], khf[2], khf[3], khB + off);
                LDM_X4(klf[0], klf[1], klf[2], klf[3], klB + off);
#pragma unroll
                for (int o = 0; o < 2; o++) {
                    int j = 2 * j2 + o;
                    MMA16816(s[j][0], s[j][1], s[j][2], s[j][3],
                             qhf[0], qhf[1], qhf[2], qhf[3], khf[o], khf[o + 2]);
                    MMA16816(s[j][0], s[j][1], s[j][2], s[j][3],
                             qlf[0], qlf[1], qlf[2], qlf[3], khf[o], khf[o + 2]);
                    MMA16816(s[j][0], s[j][1], s[j][2], s[j][3],
                             qhf[0], qhf[1], qhf[2], qhf[3], klf[o], klf[o + 2]);
                }
            }
        }

        // Causal mask (tiles touching the diagonal)
        if (js >= q0) {
#pragma unroll
            for (int j = 0; j < 8; j++)
#pragma unroll
                for (int q = 0; q < 4; q++) {
                    int col = js + j * 8 + 2 * (lane & 3) + (q & 1);
                    int row = q0 + wid * 16 + (lane >> 2) + (q >> 1) * 8;
                    if (col > row) s[j][q] = -INFINITY;
                }
        }

        // Online softmax (rows in quads; reduce via shfl_xor 1,2)
#pragma unroll
        for (int h = 0; h < 2; h++) {
            float mx = -INFINITY;
#pragma unroll
            for (int j = 0; j < 8; j++)
                mx = fmaxf(mx, fmaxf(s[j][2 * h], s[j][2 * h + 1]));
            mx = fmaxf(mx, __shfl_xor_sync(0xffffffffu, mx, 1));
            mx = fmaxf(mx, __shfl_xor_sync(0xffffffffu, mx, 2));
            float nm = fmaxf(mrow[h], mx);
            float alpha = __expf(mrow[h] - nm);
            float sum = 0.f;
#pragma unroll
            for (int j = 0; j < 8; j++) {
                float p0 = __expf(s[j][2 * h] - nm);
                float p1 = __expf(s[j][2 * h + 1] - nm);
                s[j][2 * h] = p0; s[j][2 * h + 1] = p1;
                sum += p0 + p1;
            }
            sum += __shfl_xor_sync(0xffffffffu, sum, 1);
            sum += __shfl_xor_sync(0xffffffffu, sum, 2);
            lsum[h] = lsum[h] * alpha + sum;
            mrow[h] = nm;
#pragma unroll
            for (int j = 0; j < 8; j++) {
                oa[j][2 * h] *= alpha;
                oa[j][2 * h + 1] *= alpha;
            }
        }

        // O += (Ph + Pl) Vh   (fp16 2-term)
#pragma unroll
        for (int kt2 = 0; kt2 < 4; kt2++) {
            uint32_t pah[4], pal[4];
            packsplit_h(s[2 * kt2][0],     s[2 * kt2][1],     pah[0], pal[0]);
            packsplit_h(s[2 * kt2][2],     s[2 * kt2][3],     pah[1], pal[1]);
            packsplit_h(s[2 * kt2 + 1][0], s[2 * kt2 + 1][1], pah[2], pal[2]);
            packsplit_h(s[2 * kt2 + 1][2], s[2 * kt2 + 1][3], pah[3], pal[3]);
            const uint32_t cc = kt2 * 2 + (lane >> 4);
#pragma unroll
            for (int j2 = 0; j2 < 4; j2++) {
                int row = j2 * 16 + lrow;
                uint32_t off = SWOFF(row, cc);
                uint32_t vhf[4];
                LDM_X4(vhf[0], vhf[1], vhf[2], vhf[3], vhB + off);
#pragma unroll
                for (int o = 0; o < 2; o++) {
                    int j = 2 * j2 + o;
                    MMA16816H(oa[j][0], oa[j][1], oa[j][2], oa[j][3],
                              pah[0], pah[1], pah[2], pah[3], vhf[o], vhf[o + 2]);
                    MMA16816H(oa[j][0], oa[j][1], oa[j][2], oa[j][3],
                              pal[0], pal[1], pal[2], pal[3], vhf[o], vhf[o + 2]);
                }
            }
        }
    }

    // Epilogue: y = O / l -> g_yc concat [yh|yl] fp16
    {
        const int b = bh >> 4, hh = bh & 15;
#pragma unroll
        for (int h = 0; h < 2; h++) {
            int t = q0 + wid * 16 + (lane >> 2) + h * 8;
            float invl = 1.f / lsum[h];
            __half* yrow = g_yc + ((size_t)b * Tsz + t) * K2 + hh * Dsz;
#pragma unroll
            for (int j = 0; j < 8; j++) {
                int d = j * 8 + 2 * (lane & 3);
                float y0 = oa[j][2 * h] * invl;
                float y1 = oa[j][2 * h + 1] * invl;
                __half h0, l0, h1, l1;
                split2h(y0, h0, l0); split2h(y1, h1, l1);
                *(__half2*)&yrow[d]        = __half2(h0, h1);
                *(__half2*)&yrow[d + 1024] = __half2(l0, l1);
            }
        }
    }
}

// ---------------------------------------------------------------------------
extern "C" void kernel_launch(void* const* d_in, const int* in_sizes, int n_in,
                              void* d_out, int out_size)
{
    const float* x    = (const float*)d_in[0];
    const float* Wqkv = (const float*)d_in[1];
    const float* bqkv = (const float*)d_in[2];
    const float* Wout = (const float*)d_in[3];
    const float* bout = (const float*)d_in[4];
    float* out = (float*)d_out;

    __nv_bfloat16 *xc, *wq;
    __half *yc, *wo;
    cudaGetSymbolAddress((void**)&xc, g_xc);
    cudaGetSymbolAddress((void**)&yc, g_yc);
    cudaGetSymbolAddress((void**)&wq, g_wq);
    cudaGetSymbolAddress((void**)&wo, g_wo);

    RopeTab tab;
    for (int i = 0; i < 32; i++)
        tab.inv[i] = (float)exp(-(double)(2 * i) / 64.0 * log(10000.0));

    // 0) conversions
    {
        int n = M1 * Csz;
        split_x_kernel<<<(n / 4 + 255) / 256, 256>>>(x, xc);
        dim3 g1(3 * Csz / 32, Csz / 32);
        transpose_split_kernel<<<g1, 256>>>(Wqkv, wq, 3 * Csz);
        dim3 g2(Csz / 32, Csz / 32);
        transpose_h_kernel<<<g2, 256>>>(Wout, wo, Csz);
    }

    // 1) QKV projection (bf16x3) + fused RoPE/split/V-transpose epilogue
    {
        cudaFuncSetAttribute(hmma_gemm_kernel<0, K3>, cudaFuncAttributeMaxDynamicSharedMemorySize, GEMM_SMEM);
        dim3 grid(3 * Csz / 128, M1 / 128);   // (24, 64)
        hmma_gemm_kernel<0, K3><<<grid, 256, GEMM_SMEM>>>(
            (const uint16_t*)xc, (const uint16_t*)wq, bqkv, nullptr, tab);
    }

    // 2) HMMA causal flash attention (BM=128, 3-stage KV) -> g_yc
    {
        cudaFuncSetAttribute(attn_hmma_kernel, cudaFuncAttributeMaxDynamicSharedMemorySize, ATT_SMEM);
        dim3 grid(Tsz / 128, Bsz * Hsz);      // (16, 64)
        attn_hmma_kernel<<<grid, 256, ATT_SMEM>>>();
    }

    // 3) Output projection (fp16x2) -> d_out
    {
        cudaFuncSetAttribute(hmma_gemm_kernel<1, K2>, cudaFuncAttributeMaxDynamicSharedMemorySize, GEMM_SMEM);
        dim3 grid(Csz / 128, M1 / 128);       // (8, 64)
        hmma_gemm_kernel<1, K2><<<grid, 256, GEMM_SMEM>>>(
            (const uint16_t*)yc, (const uint16_t*)wo, bout, out, tab);
    }
}

// round 8
// speedup vs baseline: 3.4090x; 1.0450x over previous
#include <cuda_runtime.h>
#include <cuda_bf16.h>
#include <cuda_fp16.h>
#include <math.h>
#include <stdint.h>

// Problem constants
#define Bsz 4
#define Tsz 2048
#define Csz 1024
#define Hsz 16
#define Dsz 64
#define M1 (Bsz * Tsz)        // 8192
#define KD 1024               // real K for all GEMMs

// ---------------------------------------------------------------------------
// Device scratch (allocation-free)
// ---------------------------------------------------------------------------
__device__ __nv_bfloat16 g_qh[Bsz * Hsz * Tsz * Dsz];  // (B,H,T,D)
__device__ __nv_bfloat16 g_ql[Bsz * Hsz * Tsz * Dsz];
__device__ __nv_bfloat16 g_kh[Bsz * Hsz * Tsz * Dsz];
__device__ __nv_bfloat16 g_kl[Bsz * Hsz * Tsz * Dsz];
__device__ __half        g_vt[Bsz * Hsz * Dsz * Tsz];  // (B,H,D,T) fp16

__device__ __nv_bfloat16 g_xh[M1 * KD];      // x bf16 hi/lo
__device__ __nv_bfloat16 g_xl[M1 * KD];
__device__ __half        g_xhf[M1 * KD];     // x fp16 hi/lo (for V GEMM)
__device__ __half        g_xlf[M1 * KD];
__device__ __half        g_yh[M1 * KD];      // attn out fp16 hi/lo
__device__ __half        g_yl[M1 * KD];
__device__ __nv_bfloat16 g_wqkh[2 * Csz * KD]; // W_q|k^T bf16 hi/lo [2048][1024]
__device__ __nv_bfloat16 g_wqkl[2 * Csz * KD];
__device__ __half        g_wvh[Csz * KD];      // W_v^T fp16 [1024][1024]
__device__ __half        g_woh[Csz * KD];      // W_out^T fp16 [1024][1024]

// ---------------------------------------------------------------------------
__device__ __forceinline__ uint32_t smem_u32(const void* p) {
    uint32_t a;
    asm("{ .reg .u64 t; cvta.to.shared.u64 t, %1; cvt.u32.u64 %0, t; }" : "=r"(a) : "l"(p));
    return a;
}

__device__ __forceinline__ void split2(float v, __nv_bfloat16& hi, __nv_bfloat16& lo) {
    hi = __float2bfloat16(v);
    lo = __float2bfloat16(v - __bfloat162float(hi));
}
__device__ __forceinline__ void split2h(float v, __half& hi, __half& lo) {
    hi = __float2half(v);
    lo = __float2half(v - __half2float(hi));
}
__device__ __forceinline__ void packsplit_h(float x, float y, uint32_t& h, uint32_t& l) {
    __half hx = __float2half(x), hy = __float2half(y);
    float lx = x - __half2float(hx);
    float ly = y - __half2float(hy);
    __half2 hv(hx, hy);
    __half2 lv(__float2half(lx), __float2half(ly));
    h = *(uint32_t*)&hv;
    l = *(uint32_t*)&lv;
}

struct RopeTab { float inv[32]; };

// ---------------------------------------------------------------------------
// Conversions
// ---------------------------------------------------------------------------
__global__ __launch_bounds__(256)
void split_x_kernel(const float* __restrict__ in)
{
    int i = (blockIdx.x * blockDim.x + threadIdx.x) * 4;
    if (i >= M1 * KD) return;
    float4 v = *(const float4*)&in[i];
    float vv[4] = { v.x, v.y, v.z, v.w };
    __nv_bfloat16 bh[4], bl[4];
    __half fh[4], fl[4];
#pragma unroll
    for (int q = 0; q < 4; q++) {
        split2(vv[q], bh[q], bl[q]);
        split2h(vv[q], fh[q], fl[q]);
    }
    *(__nv_bfloat162*)&g_xh[i]     = __nv_bfloat162(bh[0], bh[1]);
    *(__nv_bfloat162*)&g_xh[i + 2] = __nv_bfloat162(bh[2], bh[3]);
    *(__nv_bfloat162*)&g_xl[i]     = __nv_bfloat162(bl[0], bl[1]);
    *(__nv_bfloat162*)&g_xl[i + 2] = __nv_bfloat162(bl[2], bl[3]);
    *(__half2*)&g_xhf[i]     = __half2(fh[0], fh[1]);
    *(__half2*)&g_xhf[i + 2] = __half2(fh[2], fh[3]);
    *(__half2*)&g_xlf[i]     = __half2(fl[0], fl[1]);
    *(__half2*)&g_xlf[i + 2] = __half2(fl[2], fl[3]);
}

// W_qkv [1024][3072] -> n<2048: wqkh/wqkl bf16 [n][1024]; n>=2048: wvh fp16
__global__ __launch_bounds__(256)
void transpose_wqkv_kernel(const float* __restrict__ W)
{
    __shared__ float ts[32][33];
    int k0 = blockIdx.y * 32, n0 = blockIdx.x * 32;
    int ty = threadIdx.x >> 5, tx = threadIdx.x & 31;
#pragma unroll
    for (int r = 0; r < 4; r++) {
        int row = ty + r * 8;
        ts[row][tx] = W[(size_t)(k0 + row) * (3 * Csz) + n0 + tx];
    }
    __syncthreads();
#pragma unroll
    for (int r = 0; r < 4; r++) {
        int row = ty + r * 8;
        int n = n0 + row;
        float v = ts[tx][row];
        if (n < 2048) {
            __nv_bfloat16 h, l; split2(v, h, l);
            g_wqkh[(size_t)n * KD + k0 + tx] = h;
            g_wqkl[(size_t)n * KD + k0 + tx] = l;
        } else {
            g_wvh[(size_t)(n - 2048) * KD + k0 + tx] = __float2half(v);
        }
    }
}

// W_out [1024][1024] -> woh fp16 [n][1024]
__global__ __launch_bounds__(256)
void transpose_wout_kernel(const float* __restrict__ W)
{
    __shared__ float ts[32][33];
    int k0 = blockIdx.y * 32, n0 = blockIdx.x * 32;
    int ty = threadIdx.x >> 5, tx = threadIdx.x & 31;
#pragma unroll
    for (int r = 0; r < 4; r++) {
        int row = ty + r * 8;
        ts[row][tx] = W[(size_t)(k0 + row) * Csz + n0 + tx];
    }
    __syncthreads();
#pragma unroll
    for (int r = 0; r < 4; r++) {
        int row = ty + r * 8;
        g_woh[(size_t)(n0 + row) * KD + k0 + tx] = __float2half(ts[tx][row]);
    }
}

// ---------------------------------------------------------------------------
// HMMA / async macros
// ---------------------------------------------------------------------------
#define LDM_X4(r0, r1, r2, r3, addr) \
    asm volatile("ldmatrix.sync.aligned.m8n8.x4.shared.b16 {%0,%1,%2,%3}, [%4];" \
                 : "=r"(r0), "=r"(r1), "=r"(r2), "=r"(r3) : "r"(addr))

#define MMA_BF(c0, c1, c2, c3, a0, a1, a2, a3, b0, b1) \
    asm volatile("mma.sync.aligned.m16n8k16.row.col.f32.bf16.bf16.f32 " \
                 "{%0,%1,%2,%3}, {%4,%5,%6,%7}, {%8,%9}, {%0,%1,%2,%3};" \
                 : "+f"(c0), "+f"(c1), "+f"(c2), "+f"(c3) \
                 : "r"(a0), "r"(a1), "r"(a2), "r"(a3), "r"(b0), "r"(b1))

#define MMA_FP(c0, c1, c2, c3, a0, a1, a2, a3, b0, b1) \
    asm volatile("mma.sync.aligned.m16n8k16.row.col.f32.f16.f16.f32 " \
                 "{%0,%1,%2,%3}, {%4,%5,%6,%7}, {%8,%9}, {%0,%1,%2,%3};" \
                 : "+f"(c0), "+f"(c1), "+f"(c2), "+f"(c3) \
                 : "r"(a0), "r"(a1), "r"(a2), "r"(a3), "r"(b0), "r"(b1))

#define CP16(sa, gp) \
    asm volatile("cp.async.cg.shared.global [%0], [%1], 16;" :: "r"(sa), "l"(gp))
#define CP_COMMIT() asm volatile("cp.async.commit_group;" ::: "memory")
#define CP_WAITG(n) asm volatile("cp.async.wait_group %0;" :: "n"(n) : "memory")

// 128B-row swizzle (attention tiles)
#define SWOFF(row, c) ((row) * 128 + (((c) ^ ((row) & 7)) * 16))
// 64B-row swizzle (GEMM BK=32 tiles): conflict-free for 16-row ldmatrix phases
#define SWOFF32(row, c) ((row) * 64 + ((((c) ^ ((row) & 3)) ^ (((row) >> 2) & 1)) * 16))

// ---------------------------------------------------------------------------
// Restructured GEMM: C(MxN) = (Ah+Al)(Bh[+Bl])^T + bias over real K=1024.
// BM=128 BN=128 BK=32, 3-stage cp.async. 256 thr (8 warps 4x2), warp 32x64.
// TERMS=3: bf16, combos AhBh+AlBh+AhBl.  TERMS=2: fp16, combos AhBh+AlBh.
// MODE 0: QK epilogue (RoPE + bf16 split, N=2048)
// MODE 1: V epilogue (fp16 transpose -> (B,H,D,T))
// MODE 2: row-major fp32 + bias -> Cout
// ---------------------------------------------------------------------------
#define TILE32 8192                       // 128 rows x 64B
#define TRS 272                           // trans row stride bytes (136 halves)

template <int TERMS, int MODE>
__global__ __launch_bounds__(256, 2)
void gemm_kernel(const uint16_t* __restrict__ Ah, const uint16_t* __restrict__ Al,
                 const uint16_t* __restrict__ Bh, const uint16_t* __restrict__ Bl,
                 const float* __restrict__ bias, float* __restrict__ Cout,
                 RopeTab tab)
{
    constexpr int STAGE = (TERMS == 3) ? 4 * TILE32 : 3 * TILE32;
    extern __shared__ char smem_all[];

    const int tid = threadIdx.x;
    const int lane = tid & 31;
    const int wid = tid >> 5;
    const int wm = wid >> 1;            // 0..3
    const int wn = wid & 1;             // 0..1
    const int m0 = blockIdx.y * 128;
    const int n0 = blockIdx.x * 128;
    const uint32_t sbase = smem_u32(smem_all);
    const uint32_t lrow = lane & 15;
    const int nk = KD / 32;             // 32

    auto issue_stage = [&](int kt) {
        if (kt < nk) {
            const uint32_t base = sbase + (kt % 3) * STAGE;
            const uint16_t* pAh = Ah + (size_t)m0 * KD + kt * 32;
            const uint16_t* pAl = Al + (size_t)m0 * KD + kt * 32;
            const uint16_t* pBh = Bh + (size_t)n0 * KD + kt * 32;
            const uint16_t* pBl = (TERMS == 3) ? Bl + (size_t)n0 * KD + kt * 32 : nullptr;
#pragma unroll
            for (int i = 0; i < 2; i++) {
                int chunk = tid + i * 256;      // 0..511
                int row = chunk >> 2, c = chunk & 3;
                uint32_t off = SWOFF32(row, c);
                const size_t g = (size_t)row * KD + c * 8;
                CP16(base + off,              pAh + g);
                CP16(base + TILE32 + off,     pAl + g);
                CP16(base + 2 * TILE32 + off, pBh + g);
                if (TERMS == 3) CP16(base + 3 * TILE32 + off, pBl + g);
            }
        }
        CP_COMMIT();
    };

    issue_stage(0);
    issue_stage(1);

    float acc[2][8][4];
#pragma unroll
    for (int i = 0; i < 2; i++)
#pragma unroll
        for (int j = 0; j < 8; j++)
#pragma unroll
            for (int q = 0; q < 4; q++) acc[i][j][q] = 0.f;

    for (int kt = 0; kt < nk; kt++) {
        CP_WAITG(1);
        __syncthreads();

        const uint32_t aBase  = sbase + (kt % 3) * STAGE;
        const uint32_t alBase = aBase + TILE32;
        const uint32_t bBase  = aBase + 2 * TILE32;
        const uint32_t blBase = aBase + 3 * TILE32;

#pragma unroll
        for (int ks = 0; ks < 2; ks++) {
            const uint32_t cc = ks * 2 + (lane >> 4);   // logical chunk 0..3
            uint32_t ahf[2][4], alf[2][4];
#pragma unroll
            for (int i = 0; i < 2; i++) {
                int row = wm * 32 + i * 16 + lrow;
                LDM_X4(ahf[i][0], ahf[i][1], ahf[i][2], ahf[i][3], aBase  + SWOFF32(row, cc));
                LDM_X4(alf[i][0], alf[i][1], alf[i][2], alf[i][3], alBase + SWOFF32(row, cc));
            }
            if (ks == 0) issue_stage(kt + 2);   // overlap cp issue with MMAs
#pragma unroll
            for (int j2 = 0; j2 < 4; j2++) {
                int row = wn * 64 + j2 * 16 + lrow;
                uint32_t bh4[4];
                LDM_X4(bh4[0], bh4[1], bh4[2], bh4[3], bBase + SWOFF32(row, cc));
#pragma unroll
                for (int o = 0; o < 2; o++) {
                    int j = 2 * j2 + o;
#pragma unroll
                    for (int i = 0; i < 2; i++) {
                        if (TERMS == 3) {
                            MMA_BF(acc[i][j][0], acc[i][j][1], acc[i][j][2], acc[i][j][3],
                                   ahf[i][0], ahf[i][1], ahf[i][2], ahf[i][3], bh4[o], bh4[o + 2]);
                            MMA_BF(acc[i][j][0], acc[i][j][1], acc[i][j][2], acc[i][j][3],
                                   alf[i][0], alf[i][1], alf[i][2], alf[i][3], bh4[o], bh4[o + 2]);
                        } else {
                            MMA_FP(acc[i][j][0], acc[i][j][1], acc[i][j][2], acc[i][j][3],
                                   ahf[i][0], ahf[i][1], ahf[i][2], ahf[i][3], bh4[o], bh4[o + 2]);
                            MMA_FP(acc[i][j][0], acc[i][j][1], acc[i][j][2], acc[i][j][3],
                                   alf[i][0], alf[i][1], alf[i][2], alf[i][3], bh4[o], bh4[o + 2]);
                        }
                    }
                }
                if (TERMS == 3) {
                    uint32_t bl4[4];
                    LDM_X4(bl4[0], bl4[1], bl4[2], bl4[3], blBase + SWOFF32(row, cc));
#pragma unroll
                    for (int o = 0; o < 2; o++) {
                        int j = 2 * j2 + o;
#pragma unroll
                        for (int i = 0; i < 2; i++)
                            MMA_BF(acc[i][j][0], acc[i][j][1], acc[i][j][2], acc[i][j][3],
                                   ahf[i][0], ahf[i][1], ahf[i][2], ahf[i][3], bl4[o], bl4[o + 2]);
                    }
                }
            }
        }
    }

    // ---------------- Epilogue ----------------
    if (MODE == 2) {
        const int mwb = m0 + wm * 32 + (lane >> 2);
        const int nwb = n0 + wn * 64 + 2 * (lane & 3);
#pragma unroll
        for (int i = 0; i < 2; i++)
#pragma unroll
            for (int j = 0; j < 8; j++) {
                int n = nwb + j * 8;
                float bx = bias[n], by = bias[n + 1];
#pragma unroll
                for (int hf = 0; hf < 2; hf++) {
                    int m = mwb + i * 16 + hf * 8;
                    *(float2*)&Cout[(size_t)m * Csz + n] =
                        make_float2(acc[i][j][hf * 2] + bx, acc[i][j][hf * 2 + 1] + by);
                }
            }
    } else if (MODE == 0) {
        const int which = n0 >> 10;          // 0=q, 1=k
        __nv_bfloat16* GH = (which == 0) ? g_qh : g_kh;
        __nv_bfloat16* GL = (which == 0) ? g_ql : g_kl;
        const int b = m0 >> 11;
        const int hh = ((n0 + wn * 64) & 1023) >> 6;
        const int bh = b * Hsz + hh;
        const int dbase = 2 * (lane & 3);
#pragma unroll
        for (int i = 0; i < 2; i++) {
#pragma unroll
            for (int hf = 0; hf < 2; hf++) {
                int m = m0 + wm * 32 + (lane >> 2) + i * 16 + hf * 8;
                int t = m & (Tsz - 1);
                size_t baseo = ((size_t)bh * Tsz + t) * Dsz;
#pragma unroll
                for (int j = 0; j < 4; j++) {
                    int n = n0 + wn * 64 + dbase + j * 8;
                    int d = n & 63;
                    float lowx  = acc[i][j][hf * 2]     + bias[n];
                    float lowy  = acc[i][j][hf * 2 + 1] + bias[n + 1];
                    float highx = acc[i][j + 4][hf * 2]     + bias[n + 32];
                    float highy = acc[i][j + 4][hf * 2 + 1] + bias[n + 33];
                    float c0f, s0f, c1f, s1f;
                    sincosf((float)t * tab.inv[d],     &s0f, &c0f);
                    sincosf((float)t * tab.inv[d + 1], &s1f, &c1f);
                    float nlx = lowx * c0f - highx * s0f;
                    float nhx = highx * c0f + lowx * s0f;
                    float nly = lowy * c1f - highy * s1f;
                    float nhy = highy * c1f + lowy * s1f;
                    __nv_bfloat16 hlx, llx, hly, lly, hhx, lhx, hhy, lhy;
                    split2(nlx, hlx, llx); split2(nly, hly, lly);
                    split2(nhx, hhx, lhx); split2(nhy, hhy, lhy);
                    *(__nv_bfloat162*)&GH[baseo + d]      = __nv_bfloat162(hlx, hly);
                    *(__nv_bfloat162*)&GL[baseo + d]      = __nv_bfloat162(llx, lly);
                    *(__nv_bfloat162*)&GH[baseo + d + 32] = __nv_bfloat162(hhx, hhy);
                    *(__nv_bfloat162*)&GL[baseo + d + 32] = __nv_bfloat162(lhx, lhy);
                }
            }
        }
    } else {
        // MODE 1: V epilogue — smem transpose, store fp16 to (B,H,D,T)
        const int b = m0 >> 11;
        const int t0 = m0 & (Tsz - 1);
        __half* trs = (__half*)smem_all;
        __syncthreads();
#pragma unroll
        for (int i = 0; i < 2; i++)
#pragma unroll
            for (int hf = 0; hf < 2; hf++) {
                int ml = wm * 32 + (lane >> 2) + i * 16 + hf * 8;
#pragma unroll
                for (int j = 0; j < 8; j++) {
                    int nl = wn * 64 + 2 * (lane & 3) + j * 8;
                    float vx = acc[i][j][hf * 2]     + bias[n0 + nl];
                    float vy = acc[i][j][hf * 2 + 1] + bias[n0 + nl + 1];
                    trs[nl * 136 + ml]       = __float2half(vx);
                    trs[(nl + 1) * 136 + ml] = __float2half(vy);
                }
            }
        __syncthreads();
#pragma unroll
        for (int rr = 0; rr < 8; rr++) {
            int row = (tid >> 4) + rr * 16;
            int chunk = tid & 15;
            int n = n0 + row;
            int hh = n >> 6;
            int d = n & 63;
            float4 v = *(float4*)((char*)trs + row * TRS + chunk * 16);
            *(float4*)&g_vt[((size_t)(b * Hsz + hh) * Dsz + d) * Tsz + t0 + chunk * 8] = v;
        }
    }
}

// ---------------------------------------------------------------------------
// HMMA flash attention, causal. BM=128 (8 warps x 16 rows), BN=64, D=64.
// S: bf16x3. PV: fp16 2-term. 3-stage KV, 1 barrier/iter.
// ---------------------------------------------------------------------------
#define KVSTAGE 24576
#define ATT_SMEM (32768 + 3 * KVSTAGE)      // 106496

__global__ __launch_bounds__(256, 2)
void attn_hmma_kernel()
{
    extern __shared__ char asmem[];

    const int tid = threadIdx.x;
    const int lane = tid & 31;
    const int wid = tid >> 5;              // 0..7
    const int q0 = (int)(gridDim.x - 1 - blockIdx.x) * 128;
    const int bh = blockIdx.y;
    const uint32_t sb = smem_u32(asmem);
    const uint32_t qhB = sb, qlB = sb + 16384;
    const uint32_t lrow = lane & 15;
    const int nt = q0 / 64 + 2;

    {
        const size_t qg = ((size_t)bh * Tsz + q0) * Dsz;
#pragma unroll
        for (int i = 0; i < 4; i++) {
            int chunk = tid + i * 256;
            int row = chunk >> 3, c = chunk & 7;
            uint32_t off = SWOFF(row, c);
            CP16(qhB + off, g_qh + qg + (size_t)row * Dsz + c * 8);
            CP16(qlB + off, g_ql + qg + (size_t)row * Dsz + c * 8);
        }
    }

    auto issue_kv = [&](int jt) {
        if (jt < nt) {
            const int js = jt * 64;
            const uint32_t base = sb + 32768 + (jt % 3) * KVSTAGE;
            const size_t kg = ((size_t)bh * Tsz + js) * Dsz;
            const size_t vg = (size_t)bh * Dsz * Tsz + js;
#pragma unroll
            for (int i = 0; i < 2; i++) {
                int chunk = tid + i * 256;
                int row = chunk >> 3, c = chunk & 7;
                uint32_t off = SWOFF(row, c);
                CP16(base + off,         g_kh + kg + (size_t)row * Dsz + c * 8);
                CP16(base + 8192 + off,  g_kl + kg + (size_t)row * Dsz + c * 8);
                CP16(base + 16384 + off, g_vt + vg + (size_t)row * Tsz + c * 8);
            }
        }
        CP_COMMIT();
    };

    issue_kv(0);
    issue_kv(1);

    float mrow[2] = { -INFINITY, -INFINITY };
    float lsum[2] = { 0.f, 0.f };
    float oa[8][4];
#pragma unroll
    for (int j = 0; j < 8; j++)
#pragma unroll
        for (int q = 0; q < 4; q++) oa[j][q] = 0.f;

    for (int jt = 0; jt < nt; jt++) {
        CP_WAITG(1);
        __syncthreads();

        const int js = jt * 64;
        const uint32_t kvb = sb + 32768 + (jt % 3) * KVSTAGE;
        const uint32_t khB = kvb, klB = kvb + 8192;
        const uint32_t vhB = kvb + 16384;

        float s[8][4];
#pragma unroll
        for (int j = 0; j < 8; j++)
#pragma unroll
            for (int q = 0; q < 4; q++) s[j][q] = 0.f;

#pragma unroll
        for (int ks = 0; ks < 4; ks++) {
            const uint32_t cc = ks * 2 + (lane >> 4);
            uint32_t qhf[4], qlf[4];
            {
                int row = wid * 16 + lrow;
                LDM_X4(qhf[0], qhf[1], qhf[2], qhf[3], qhB + SWOFF(row, cc));
                LDM_X4(qlf[0], qlf[1], qlf[2], qlf[3], qlB + SWOFF(row, cc));
            }
            if (ks == 0) issue_kv(jt + 2);
#pragma unroll
            for (int j2 = 0; j2 < 4; j2++) {
                int row = j2 * 16 + lrow;
                uint32_t off = SWOFF(row, cc);
                uint32_t khf[4], klf[4];
                LDM_X4(khf[0], khf[1], khf[2], khf[3], khB + off);
                LDM_X4(klf[0], klf[1], klf[2], klf[3], klB + off);
#pragma unroll
                for (int o = 0; o < 2; o++) {
                    int j = 2 * j2 + o;
                    MMA_BF(s[j][0], s[j][1], s[j][2], s[j][3],
                           qhf[0], qhf[1], qhf[2], qhf[3], khf[o], khf[o + 2]);
                    MMA_BF(s[j][0], s[j][1], s[j][2], s[j][3],
                           qlf[0], qlf[1], qlf[2], qlf[3], khf[o], khf[o + 2]);
                    MMA_BF(s[j][0], s[j][1], s[j][2], s[j][3],
                           qhf[0], qhf[1], qhf[2], qhf[3], klf[o], klf[o + 2]);
                }
            }
        }

        if (js >= q0) {
#pragma unroll
            for (int j = 0; j < 8; j++)
#pragma unroll
                for (int q = 0; q < 4; q++) {
                    int col = js + j * 8 + 2 * (lane & 3) + (q & 1);
                    int row = q0 + wid * 16 + (lane >> 2) + (q >> 1) * 8;
                    if (col > row) s[j][q] = -INFINITY;
                }
        }

#pragma unroll
        for (int h = 0; h < 2; h++) {
            float mx = -INFINITY;
#pragma unroll
            for (int j = 0; j < 8; j++)
                mx = fmaxf(mx, fmaxf(s[j][2 * h], s[j][2 * h + 1]));
            mx = fmaxf(mx, __shfl_xor_sync(0xffffffffu, mx, 1));
            mx = fmaxf(mx, __shfl_xor_sync(0xffffffffu, mx, 2));
            float nm = fmaxf(mrow[h], mx);
            float alpha = __expf(mrow[h] - nm);
            float sum = 0.f;
#pragma unroll
            for (int j = 0; j < 8; j++) {
                float p0 = __expf(s[j][2 * h] - nm);
                float p1 = __expf(s[j][2 * h + 1] - nm);
                s[j][2 * h] = p0; s[j][2 * h + 1] = p1;
                sum += p0 + p1;
            }
            sum += __shfl_xor_sync(0xffffffffu, sum, 1);
            sum += __shfl_xor_sync(0xffffffffu, sum, 2);
            lsum[h] = lsum[h] * alpha + sum;
            mrow[h] = nm;
#pragma unroll
            for (int j = 0; j < 8; j++) {
                oa[j][2 * h] *= alpha;
                oa[j][2 * h + 1] *= alpha;
            }
        }

#pragma unroll
        for (int kt2 = 0; kt2 < 4; kt2++) {
            uint32_t pah[4], pal[4];
            packsplit_h(s[2 * kt2][0],     s[2 * kt2][1],     pah[0], pal[0]);
            packsplit_h(s[2 * kt2][2],     s[2 * kt2][3],     pah[1], pal[1]);
            packsplit_h(s[2 * kt2 + 1][0], s[2 * kt2 + 1][1], pah[2], pal[2]);
            packsplit_h(s[2 * kt2 + 1][2], s[2 * kt2 + 1][3], pah[3], pal[3]);
            const uint32_t cc = kt2 * 2 + (lane >> 4);
#pragma unroll
            for (int j2 = 0; j2 < 4; j2++) {
                int row = j2 * 16 + lrow;
                uint32_t off = SWOFF(row, cc);
                uint32_t vhf[4];
                LDM_X4(vhf[0], vhf[1], vhf[2], vhf[3], vhB + off);
#pragma unroll
                for (int o = 0; o < 2; o++) {
                    int j = 2 * j2 + o;
                    MMA_FP(oa[j][0], oa[j][1], oa[j][2], oa[j][3],
                           pah[0], pah[1], pah[2], pah[3], vhf[o], vhf[o + 2]);
                    MMA_FP(oa[j][0], oa[j][1], oa[j][2], oa[j][3],
                           pal[0], pal[1], pal[2], pal[3], vhf[o], vhf[o + 2]);
                }
            }
        }
    }

    // Epilogue: y = O / l -> yh/yl fp16 [M][1024]
    {
        const int b = bh >> 4, hh = bh & 15;
#pragma unroll
        for (int h = 0; h < 2; h++) {
            int t = q0 + wid * 16 + (lane >> 2) + h * 8;
            float invl = 1.f / lsum[h];
            size_t rb = ((size_t)b * Tsz + t) * KD + hh * Dsz;
#pragma unroll
            for (int j = 0; j < 8; j++) {
                int d = j * 8 + 2 * (lane & 3);
                float y0 = oa[j][2 * h] * invl;
                float y1 = oa[j][2 * h + 1] * invl;
                __half h0, l0, h1, l1;
                split2h(y0, h0, l0); split2h(y1, h1, l1);
                *(__half2*)&g_yh[rb + d] = __half2(h0, h1);
                *(__half2*)&g_yl[rb + d] = __half2(l0, l1);
            }
        }
    }
}

// ---------------------------------------------------------------------------
extern "C" void kernel_launch(void* const* d_in, const int* in_sizes, int n_in,
                              void* d_out, int out_size)
{
    const float* x    = (const float*)d_in[0];
    const float* Wqkv = (const float*)d_in[1];
    const float* bqkv = (const float*)d_in[2];
    const float* Wout = (const float*)d_in[3];
    const float* bout = (const float*)d_in[4];
    float* out = (float*)d_out;

    void *xh, *xl, *xhf, *xlf, *yh, *yl, *wqkh, *wqkl, *wvh, *woh;
    cudaGetSymbolAddress(&xh,   g_xh);
    cudaGetSymbolAddress(&xl,   g_xl);
    cudaGetSymbolAddress(&xhf,  g_xhf);
    cudaGetSymbolAddress(&xlf,  g_xlf);
    cudaGetSymbolAddress(&yh,   g_yh);
    cudaGetSymbolAddress(&yl,   g_yl);
    cudaGetSymbolAddress(&wqkh, g_wqkh);
    cudaGetSymbolAddress(&wqkl, g_wqkl);
    cudaGetSymbolAddress(&wvh,  g_wvh);
    cudaGetSymbolAddress(&woh,  g_woh);

    RopeTab tab;
    for (int i = 0; i < 32; i++)
        tab.inv[i] = (float)exp(-(double)(2 * i) / 64.0 * log(10000.0));

    // 0) conversions
    {
        int n = M1 * KD;
        split_x_kernel<<<(n / 4 + 255) / 256, 256>>>(x);
        dim3 g1(3 * Csz / 32, Csz / 32);
        transpose_wqkv_kernel<<<g1, 256>>>(Wqkv);
        dim3 g2(Csz / 32, Csz / 32);
        transpose_wout_kernel<<<g2, 256>>>(Wout);
    }

    // 1a) QK projection (bf16x3) + fused RoPE/split epilogue
    {
        cudaFuncSetAttribute(gemm_kernel<3, 0>, cudaFuncAttributeMaxDynamicSharedMemorySize, 3 * 4 * TILE32);
        dim3 grid(2 * Csz / 128, M1 / 128);   // (16, 64)
        gemm_kernel<3, 0><<<grid, 256, 3 * 4 * TILE32>>>(
            (const uint16_t*)xh, (const uint16_t*)xl,
            (const uint16_t*)wqkh, (const uint16_t*)wqkl, bqkv, nullptr, tab);
    }
    // 1b) V projection (fp16x2) + transpose epilogue
    {
        cudaFuncSetAttribute(gemm_kernel<2, 1>, cudaFuncAttributeMaxDynamicSharedMemorySize, 3 * 3 * TILE32);
        dim3 grid(Csz / 128, M1 / 128);       // (8, 64)
        gemm_kernel<2, 1><<<grid, 256, 3 * 3 * TILE32>>>(
            (const uint16_t*)xhf, (const uint16_t*)xlf,
            (const uint16_t*)wvh, nullptr, bqkv + 2048, nullptr, tab);
    }

    // 2) HMMA causal flash attention -> yh/yl
    {
        cudaFuncSetAttribute(attn_hmma_kernel, cudaFuncAttributeMaxDynamicSharedMemorySize, ATT_SMEM);
        dim3 grid(Tsz / 128, Bsz * Hsz);      // (16, 64)
        attn_hmma_kernel<<<grid, 256, ATT_SMEM>>>();
    }

    // 3) Output projection (fp16x2) -> d_out
    {
        cudaFuncSetAttribute(gemm_kernel<2, 2>, cudaFuncAttributeMaxDynamicSharedMemorySize, 3 * 3 * TILE32);
        dim3 grid(Csz / 128, M1 / 128);       // (8, 64)
        gemm_kernel<2, 2><<<grid, 256, 3 * 3 * TILE32>>>(
            (const uint16_t*)yh, (const uint16_t*)yl,
            (const uint16_t*)woh, nullptr, bout, out, tab);
    }
}

// round 9
// speedup vs baseline: 3.8073x; 1.1168x over previous
#include <cuda_runtime.h>
#include <cuda_bf16.h>
#include <cuda_fp16.h>
#include <math.h>
#include <stdint.h>

// Problem constants
#define Bsz 4
#define Tsz 2048
#define Csz 1024
#define Hsz 16
#define Dsz 64
#define M1 (Bsz * Tsz)        // 8192
#define KD 1024               // real K for all GEMMs

// ---------------------------------------------------------------------------
// Device scratch (allocation-free)
// ---------------------------------------------------------------------------
__device__ __nv_bfloat16 g_qh[Bsz * Hsz * Tsz * Dsz];  // (B,H,T,D)  (scaled by log2e)
__device__ __nv_bfloat16 g_ql[Bsz * Hsz * Tsz * Dsz];
__device__ __nv_bfloat16 g_kh[Bsz * Hsz * Tsz * Dsz];
__device__ __nv_bfloat16 g_kl[Bsz * Hsz * Tsz * Dsz];
__device__ __half        g_vt[Bsz * Hsz * Dsz * Tsz];  // (B,H,D,T) fp16

__device__ __nv_bfloat16 g_xh[M1 * KD];      // x bf16 hi/lo
__device__ __nv_bfloat16 g_xl[M1 * KD];
__device__ __half        g_xhf[M1 * KD];     // x fp16 hi/lo (for V GEMM)
__device__ __half        g_xlf[M1 * KD];
__device__ __half        g_yh[M1 * KD];      // attn out fp16 hi/lo
__device__ __half        g_yl[M1 * KD];
__device__ __nv_bfloat16 g_wqkh[2 * Csz * KD]; // W_q|k^T bf16 hi/lo
__device__ __nv_bfloat16 g_wqkl[2 * Csz * KD];
__device__ __half        g_wvh[Csz * KD];      // W_v^T fp16
__device__ __half        g_woh[Csz * KD];      // W_out^T fp16

// ---------------------------------------------------------------------------
__device__ __forceinline__ uint32_t smem_u32(const void* p) {
    uint32_t a;
    asm("{ .reg .u64 t; cvta.to.shared.u64 t, %1; cvt.u32.u64 %0, t; }" : "=r"(a) : "l"(p));
    return a;
}
__device__ __forceinline__ float ex2f(float x) {
    float r; asm("ex2.approx.ftz.f32 %0, %1;" : "=f"(r) : "f"(x)); return r;
}
__device__ __forceinline__ void split2(float v, __nv_bfloat16& hi, __nv_bfloat16& lo) {
    hi = __float2bfloat16(v);
    lo = __float2bfloat16(v - __bfloat162float(hi));
}
__device__ __forceinline__ void split2h(float v, __half& hi, __half& lo) {
    hi = __float2half(v);
    lo = __float2half(v - __half2float(hi));
}

struct RopeTab { float inv[32]; };
#define LOG2E 1.44269504088896f

// ---------------------------------------------------------------------------
// Conversions
// ---------------------------------------------------------------------------
__global__ __launch_bounds__(256)
void split_x_kernel(const float* __restrict__ in)
{
    int i = (blockIdx.x * blockDim.x + threadIdx.x) * 4;
    if (i >= M1 * KD) return;
    float4 v = *(const float4*)&in[i];
    float vv[4] = { v.x, v.y, v.z, v.w };
    __nv_bfloat16 bh[4], bl[4];
    __half fh[4], fl[4];
#pragma unroll
    for (int q = 0; q < 4; q++) {
        split2(vv[q], bh[q], bl[q]);
        split2h(vv[q], fh[q], fl[q]);
    }
    *(__nv_bfloat162*)&g_xh[i]     = __nv_bfloat162(bh[0], bh[1]);
    *(__nv_bfloat162*)&g_xh[i + 2] = __nv_bfloat162(bh[2], bh[3]);
    *(__nv_bfloat162*)&g_xl[i]     = __nv_bfloat162(bl[0], bl[1]);
    *(__nv_bfloat162*)&g_xl[i + 2] = __nv_bfloat162(bl[2], bl[3]);
    *(__half2*)&g_xhf[i]     = __half2(fh[0], fh[1]);
    *(__half2*)&g_xhf[i + 2] = __half2(fh[2], fh[3]);
    *(__half2*)&g_xlf[i]     = __half2(fl[0], fl[1]);
    *(__half2*)&g_xlf[i + 2] = __half2(fl[2], fl[3]);
}

// W_qkv [1024][3072] -> n<2048: wqkh/wqkl bf16; n>=2048: wvh fp16
__global__ __launch_bounds__(256)
void transpose_wqkv_kernel(const float* __restrict__ W)
{
    __shared__ float ts[32][33];
    int k0 = blockIdx.y * 32, n0 = blockIdx.x * 32;
    int ty = threadIdx.x >> 5, tx = threadIdx.x & 31;
#pragma unroll
    for (int r = 0; r < 4; r++) {
        int row = ty + r * 8;
        ts[row][tx] = W[(size_t)(k0 + row) * (3 * Csz) + n0 + tx];
    }
    __syncthreads();
#pragma unroll
    for (int r = 0; r < 4; r++) {
        int row = ty + r * 8;
        int n = n0 + row;
        float v = ts[tx][row];
        if (n < 2048) {
            __nv_bfloat16 h, l; split2(v, h, l);
            g_wqkh[(size_t)n * KD + k0 + tx] = h;
            g_wqkl[(size_t)n * KD + k0 + tx] = l;
        } else {
            g_wvh[(size_t)(n - 2048) * KD + k0 + tx] = __float2half(v);
        }
    }
}

__global__ __launch_bounds__(256)
void transpose_wout_kernel(const float* __restrict__ W)
{
    __shared__ float ts[32][33];
    int k0 = blockIdx.y * 32, n0 = blockIdx.x * 32;
    int ty = threadIdx.x >> 5, tx = threadIdx.x & 31;
#pragma unroll
    for (int r = 0; r < 4; r++) {
        int row = ty + r * 8;
        ts[row][tx] = W[(size_t)(k0 + row) * Csz + n0 + tx];
    }
    __syncthreads();
#pragma unroll
    for (int r = 0; r < 4; r++) {
        int row = ty + r * 8;
        g_woh[(size_t)(n0 + row) * KD + k0 + tx] = __float2half(ts[tx][row]);
    }
}

// ---------------------------------------------------------------------------
// HMMA / async macros
// ---------------------------------------------------------------------------
#define LDM_X4(r0, r1, r2, r3, addr) \
    asm volatile("ldmatrix.sync.aligned.m8n8.x4.shared.b16 {%0,%1,%2,%3}, [%4];" \
                 : "=r"(r0), "=r"(r1), "=r"(r2), "=r"(r3) : "r"(addr))

#define MMA_BF(c0, c1, c2, c3, a0, a1, a2, a3, b0, b1) \
    asm volatile("mma.sync.aligned.m16n8k16.row.col.f32.bf16.bf16.f32 " \
                 "{%0,%1,%2,%3}, {%4,%5,%6,%7}, {%8,%9}, {%0,%1,%2,%3};" \
                 : "+f"(c0), "+f"(c1), "+f"(c2), "+f"(c3) \
                 : "r"(a0), "r"(a1), "r"(a2), "r"(a3), "r"(b0), "r"(b1))

#define MMA_FP(c0, c1, c2, c3, a0, a1, a2, a3, b0, b1) \
    asm volatile("mma.sync.aligned.m16n8k16.row.col.f32.f16.f16.f32 " \
                 "{%0,%1,%2,%3}, {%4,%5,%6,%7}, {%8,%9}, {%0,%1,%2,%3};" \
                 : "+f"(c0), "+f"(c1), "+f"(c2), "+f"(c3) \
                 : "r"(a0), "r"(a1), "r"(a2), "r"(a3), "r"(b0), "r"(b1))

#define CP16(sa, gp) \
    asm volatile("cp.async.cg.shared.global [%0], [%1], 16;" :: "r"(sa), "l"(gp))
#define CP_COMMIT() asm volatile("cp.async.commit_group;" ::: "memory")
#define CP_WAITG(n) asm volatile("cp.async.wait_group %0;" :: "n"(n) : "memory")

#define SWOFF(row, c) ((row) * 128 + (((c) ^ ((row) & 7)) * 16))
#define SWOFF32(row, c) ((row) * 64 + ((((c) ^ ((row) & 3)) ^ (((row) >> 2) & 1)) * 16))

#define TILE32 8192
#define TRS 272
#define QKV_SMEM (3 * 4 * TILE32)   // 98304 (QK path size; V path uses less)

// ---------------------------------------------------------------------------
// Merged QKV GEMM. grid (24, 64).
//   blockIdx.x < 16 : QK (bf16x3) + fused RoPE (+log2e on q) split epilogue
//   blockIdx.x >= 16: V  (fp16x2) + transpose epilogue -> (B,H,D,T)
// ---------------------------------------------------------------------------
__global__ __launch_bounds__(256, 2)
void qkv_gemm_kernel(const float* __restrict__ bqkv, RopeTab tab)
{
    extern __shared__ char smem_all[];

    const int tid = threadIdx.x;
    const int lane = tid & 31;
    const int wid = tid >> 5;
    const int wm = wid >> 1;
    const int wn = wid & 1;
    const int m0 = blockIdx.y * 128;
    const uint32_t sbase = smem_u32(smem_all);
    const uint32_t lrow = lane & 15;
    const int nk = KD / 32;             // 32

    float acc[2][8][4];
#pragma unroll
    for (int i = 0; i < 2; i++)
#pragma unroll
        for (int j = 0; j < 8; j++)
#pragma unroll
            for (int q = 0; q < 4; q++) acc[i][j][q] = 0.f;

    if (blockIdx.x < 16) {
        // ================= QK path: bf16 3-term =================
        const int n0 = blockIdx.x * 128;
        constexpr int STAGE = 4 * TILE32;

        auto issue_stage = [&](int kt) {
            if (kt < nk) {
                const uint32_t base = sbase + (kt % 3) * STAGE;
                const __nv_bfloat16* pAh = g_xh + (size_t)m0 * KD + kt * 32;
                const __nv_bfloat16* pAl = g_xl + (size_t)m0 * KD + kt * 32;
                const __nv_bfloat16* pBh = g_wqkh + (size_t)n0 * KD + kt * 32;
                const __nv_bfloat16* pBl = g_wqkl + (size_t)n0 * KD + kt * 32;
#pragma unroll
                for (int i = 0; i < 2; i++) {
                    int chunk = tid + i * 256;
                    int row = chunk >> 2, c = chunk & 3;
                    uint32_t off = SWOFF32(row, c);
                    const size_t g = (size_t)row * KD + c * 8;
                    CP16(base + off,              pAh + g);
                    CP16(base + TILE32 + off,     pAl + g);
                    CP16(base + 2 * TILE32 + off, pBh + g);
                    CP16(base + 3 * TILE32 + off, pBl + g);
                }
            }
            CP_COMMIT();
        };

        issue_stage(0);
        issue_stage(1);

        for (int kt = 0; kt < nk; kt++) {
            CP_WAITG(1);
            __syncthreads();
            const uint32_t aBase  = sbase + (kt % 3) * STAGE;
            const uint32_t alBase = aBase + TILE32;
            const uint32_t bBase  = aBase + 2 * TILE32;
            const uint32_t blBase = aBase + 3 * TILE32;
#pragma unroll
            for (int ks = 0; ks < 2; ks++) {
                const uint32_t cc = ks * 2 + (lane >> 4);
                uint32_t ahf[2][4], alf[2][4];
#pragma unroll
                for (int i = 0; i < 2; i++) {
                    int row = wm * 32 + i * 16 + lrow;
                    LDM_X4(ahf[i][0], ahf[i][1], ahf[i][2], ahf[i][3], aBase  + SWOFF32(row, cc));
                    LDM_X4(alf[i][0], alf[i][1], alf[i][2], alf[i][3], alBase + SWOFF32(row, cc));
                }
                if (ks == 0) issue_stage(kt + 2);
#pragma unroll
                for (int j2 = 0; j2 < 4; j2++) {
                    int row = wn * 64 + j2 * 16 + lrow;
                    uint32_t bh4[4];
                    LDM_X4(bh4[0], bh4[1], bh4[2], bh4[3], bBase + SWOFF32(row, cc));
#pragma unroll
                    for (int o = 0; o < 2; o++) {
                        int j = 2 * j2 + o;
#pragma unroll
                        for (int i = 0; i < 2; i++) {
                            MMA_BF(acc[i][j][0], acc[i][j][1], acc[i][j][2], acc[i][j][3],
                                   ahf[i][0], ahf[i][1], ahf[i][2], ahf[i][3], bh4[o], bh4[o + 2]);
                            MMA_BF(acc[i][j][0], acc[i][j][1], acc[i][j][2], acc[i][j][3],
                                   alf[i][0], alf[i][1], alf[i][2], alf[i][3], bh4[o], bh4[o + 2]);
                        }
                    }
                    uint32_t bl4[4];
                    LDM_X4(bl4[0], bl4[1], bl4[2], bl4[3], blBase + SWOFF32(row, cc));
#pragma unroll
                    for (int o = 0; o < 2; o++) {
                        int j = 2 * j2 + o;
#pragma unroll
                        for (int i = 0; i < 2; i++)
                            MMA_BF(acc[i][j][0], acc[i][j][1], acc[i][j][2], acc[i][j][3],
                                   ahf[i][0], ahf[i][1], ahf[i][2], ahf[i][3], bl4[o], bl4[o + 2]);
                    }
                }
            }
        }

        // Epilogue: RoPE + split; q additionally scaled by log2e
        const int which = n0 >> 10;          // 0=q, 1=k
        const float l2e = (which == 0) ? LOG2E : 1.f;
        __nv_bfloat16* GH = (which == 0) ? g_qh : g_kh;
        __nv_bfloat16* GL = (which == 0) ? g_ql : g_kl;
        const int b = m0 >> 11;
        const int hh = ((n0 + wn * 64) & 1023) >> 6;
        const int bh = b * Hsz + hh;
        const int dbase = 2 * (lane & 3);
#pragma unroll
        for (int i = 0; i < 2; i++) {
#pragma unroll
            for (int hf = 0; hf < 2; hf++) {
                int m = m0 + wm * 32 + (lane >> 2) + i * 16 + hf * 8;
                int t = m & (Tsz - 1);
                size_t baseo = ((size_t)bh * Tsz + t) * Dsz;
#pragma unroll
                for (int j = 0; j < 4; j++) {
                    int n = n0 + wn * 64 + dbase + j * 8;
                    int d = n & 63;
                    float lowx  = acc[i][j][hf * 2]     + bqkv[n];
                    float lowy  = acc[i][j][hf * 2 + 1] + bqkv[n + 1];
                    float highx = acc[i][j + 4][hf * 2]     + bqkv[n + 32];
                    float highy = acc[i][j + 4][hf * 2 + 1] + bqkv[n + 33];
                    float c0f, s0f, c1f, s1f;
                    sincosf((float)t * tab.inv[d],     &s0f, &c0f);
                    sincosf((float)t * tab.inv[d + 1], &s1f, &c1f);
                    float nlx = (lowx * c0f - highx * s0f) * l2e;
                    float nhx = (highx * c0f + lowx * s0f) * l2e;
                    float nly = (lowy * c1f - highy * s1f) * l2e;
                    float nhy = (highy * c1f + lowy * s1f) * l2e;
                    __nv_bfloat16 hlx, llx, hly, lly, hhx, lhx, hhy, lhy;
                    split2(nlx, hlx, llx); split2(nly, hly, lly);
                    split2(nhx, hhx, lhx); split2(nhy, hhy, lhy);
                    *(__nv_bfloat162*)&GH[baseo + d]      = __nv_bfloat162(hlx, hly);
                    *(__nv_bfloat162*)&GL[baseo + d]      = __nv_bfloat162(llx, lly);
                    *(__nv_bfloat162*)&GH[baseo + d + 32] = __nv_bfloat162(hhx, hhy);
                    *(__nv_bfloat162*)&GL[baseo + d + 32] = __nv_bfloat162(lhx, lhy);
                }
            }
        }
    } else {
        // ================= V path: fp16 2-term =================
        const int n0 = (blockIdx.x - 16) * 128;
        constexpr int STAGE = 3 * TILE32;

        auto issue_stage = [&](int kt) {
            if (kt < nk) {
                const uint32_t base = sbase + (kt % 3) * STAGE;
                const __half* pAh = g_xhf + (size_t)m0 * KD + kt * 32;
                const __half* pAl = g_xlf + (size_t)m0 * KD + kt * 32;
                const __half* pBh = g_wvh + (size_t)n0 * KD + kt * 32;
#pragma unroll
                for (int i = 0; i < 2; i++) {
                    int chunk = tid + i * 256;
                    int row = chunk >> 2, c = chunk & 3;
                    uint32_t off = SWOFF32(row, c);
                    const size_t g = (size_t)row * KD + c * 8;
                    CP16(base + off,              pAh + g);
                    CP16(base + TILE32 + off,     pAl + g);
                    CP16(base + 2 * TILE32 + off, pBh + g);
                }
            }
            CP_COMMIT();
        };

        issue_stage(0);
        issue_stage(1);

        for (int kt = 0; kt < nk; kt++) {
            CP_WAITG(1);
            __syncthreads();
            const uint32_t aBase  = sbase + (kt % 3) * STAGE;
            const uint32_t alBase = aBase + TILE32;
            const uint32_t bBase  = aBase + 2 * TILE32;
#pragma unroll
            for (int ks = 0; ks < 2; ks++) {
                const uint32_t cc = ks * 2 + (lane >> 4);
                uint32_t ahf[2][4], alf[2][4];
#pragma unroll
                for (int i = 0; i < 2; i++) {
                    int row = wm * 32 + i * 16 + lrow;
                    LDM_X4(ahf[i][0], ahf[i][1], ahf[i][2], ahf[i][3], aBase  + SWOFF32(row, cc));
                    LDM_X4(alf[i][0], alf[i][1], alf[i][2], alf[i][3], alBase + SWOFF32(row, cc));
                }
                if (ks == 0) issue_stage(kt + 2);
#pragma unroll
                for (int j2 = 0; j2 < 4; j2++) {
                    int row = wn * 64 + j2 * 16 + lrow;
                    uint32_t bh4[4];
                    LDM_X4(bh4[0], bh4[1], bh4[2], bh4[3], bBase + SWOFF32(row, cc));
#pragma unroll
                    for (int o = 0; o < 2; o++) {
                        int j = 2 * j2 + o;
#pragma unroll
                        for (int i = 0; i < 2; i++) {
                            MMA_FP(acc[i][j][0], acc[i][j][1], acc[i][j][2], acc[i][j][3],
                                   ahf[i][0], ahf[i][1], ahf[i][2], ahf[i][3], bh4[o], bh4[o + 2]);
                            MMA_FP(acc[i][j][0], acc[i][j][1], acc[i][j][2], acc[i][j][3],
                                   alf[i][0], alf[i][1], alf[i][2], alf[i][3], bh4[o], bh4[o + 2]);
                        }
                    }
                }
            }
        }

        // V epilogue: smem transpose -> g_vt (B,H,D,T) fp16
        const int b = m0 >> 11;
        const int t0 = m0 & (Tsz - 1);
        __half* trs = (__half*)smem_all;
        __syncthreads();
#pragma unroll
        for (int i = 0; i < 2; i++)
#pragma unroll
            for (int hf = 0; hf < 2; hf++) {
                int ml = wm * 32 + (lane >> 2) + i * 16 + hf * 8;
#pragma unroll
                for (int j = 0; j < 8; j++) {
                    int nl = wn * 64 + 2 * (lane & 3) + j * 8;
                    float vx = acc[i][j][hf * 2]     + bqkv[2048 + n0 + nl];
                    float vy = acc[i][j][hf * 2 + 1] + bqkv[2048 + n0 + nl + 1];
                    trs[nl * 136 + ml]       = __float2half(vx);
                    trs[(nl + 1) * 136 + ml] = __float2half(vy);
                }
            }
        __syncthreads();
#pragma unroll
        for (int rr = 0; rr < 8; rr++) {
            int row = (tid >> 4) + rr * 16;
            int chunk = tid & 15;
            int n = n0 + row;
            int hh = n >> 6;
            int d = n & 63;
            float4 v = *(float4*)((char*)trs + row * TRS + chunk * 16);
            *(float4*)&g_vt[((size_t)(b * Hsz + hh) * Dsz + d) * Tsz + t0 + chunk * 8] = v;
        }
    }
}

// ---------------------------------------------------------------------------
// Output projection: fp16 2-term, row-major fp32 + bias -> Cout
// ---------------------------------------------------------------------------
#define OUTP_SMEM (3 * 3 * TILE32)

__global__ __launch_bounds__(256, 2)
void outproj_kernel(const float* __restrict__ bias, float* __restrict__ Cout)
{
    extern __shared__ char smem_all[];
    const int tid = threadIdx.x;
    const int lane = tid & 31;
    const int wid = tid >> 5;
    const int wm = wid >> 1;
    const int wn = wid & 1;
    const int m0 = blockIdx.y * 128;
    const int n0 = blockIdx.x * 128;
    const uint32_t sbase = smem_u32(smem_all);
    const uint32_t lrow = lane & 15;
    const int nk = KD / 32;
    constexpr int STAGE = 3 * TILE32;

    auto issue_stage = [&](int kt) {
        if (kt < nk) {
            const uint32_t base = sbase + (kt % 3) * STAGE;
            const __half* pAh = g_yh + (size_t)m0 * KD + kt * 32;
            const __half* pAl = g_yl + (size_t)m0 * KD + kt * 32;
            const __half* pBh = g_woh + (size_t)n0 * KD + kt * 32;
#pragma unroll
            for (int i = 0; i < 2; i++) {
                int chunk = tid + i * 256;
                int row = chunk >> 2, c = chunk & 3;
                uint32_t off = SWOFF32(row, c);
                const size_t g = (size_t)row * KD + c * 8;
                CP16(base + off,              pAh + g);
                CP16(base + TILE32 + off,     pAl + g);
                CP16(base + 2 * TILE32 + off, pBh + g);
            }
        }
        CP_COMMIT();
    };

    issue_stage(0);
    issue_stage(1);

    float acc[2][8][4];
#pragma unroll
    for (int i = 0; i < 2; i++)
#pragma unroll
        for (int j = 0; j < 8; j++)
#pragma unroll
            for (int q = 0; q < 4; q++) acc[i][j][q] = 0.f;

    for (int kt = 0; kt < nk; kt++) {
        CP_WAITG(1);
        __syncthreads();
        const uint32_t aBase  = sbase + (kt % 3) * STAGE;
        const uint32_t alBase = aBase + TILE32;
        const uint32_t bBase  = aBase + 2 * TILE32;
#pragma unroll
        for (int ks = 0; ks < 2; ks++) {
            const uint32_t cc = ks * 2 + (lane >> 4);
            uint32_t ahf[2][4], alf[2][4];
#pragma unroll
            for (int i = 0; i < 2; i++) {
                int row = wm * 32 + i * 16 + lrow;
                LDM_X4(ahf[i][0], ahf[i][1], ahf[i][2], ahf[i][3], aBase  + SWOFF32(row, cc));
                LDM_X4(alf[i][0], alf[i][1], alf[i][2], alf[i][3], alBase + SWOFF32(row, cc));
            }
            if (ks == 0) issue_stage(kt + 2);
#pragma unroll
            for (int j2 = 0; j2 < 4; j2++) {
                int row = wn * 64 + j2 * 16 + lrow;
                uint32_t bh4[4];
                LDM_X4(bh4[0], bh4[1], bh4[2], bh4[3], bBase + SWOFF32(row, cc));
#pragma unroll
                for (int o = 0; o < 2; o++) {
                    int j = 2 * j2 + o;
#pragma unroll
                    for (int i = 0; i < 2; i++) {
                        MMA_FP(acc[i][j][0], acc[i][j][1], acc[i][j][2], acc[i][j][3],
                               ahf[i][0], ahf[i][1], ahf[i][2], ahf[i][3], bh4[o], bh4[o + 2]);
                        MMA_FP(acc[i][j][0], acc[i][j][1], acc[i][j][2], acc[i][j][3],
                               alf[i][0], alf[i][1], alf[i][2], alf[i][3], bh4[o], bh4[o + 2]);
                    }
                }
            }
        }
    }

    const int mwb = m0 + wm * 32 + (lane >> 2);
    const int nwb = n0 + wn * 64 + 2 * (lane & 3);
#pragma unroll
    for (int i = 0; i < 2; i++)
#pragma unroll
        for (int j = 0; j < 8; j++) {
            int n = nwb + j * 8;
            float bx = bias[n], by = bias[n + 1];
#pragma unroll
            for (int hf = 0; hf < 2; hf++) {
                int m = mwb + i * 16 + hf * 8;
                *(float2*)&Cout[(size_t)m * Csz + n] =
                    make_float2(acc[i][j][hf * 2] + bx, acc[i][j][hf * 2 + 1] + by);
            }
        }
}

// ---------------------------------------------------------------------------
// HMMA flash attention, causal. BM=128 (8 warps x 16 rows), BN=64, D=64.
// S: bf16x3 (q pre-scaled by log2e -> ex2 softmax). PV: fp16 single-term.
// 3-stage KV, 1 barrier/iter.
// ---------------------------------------------------------------------------
#define KVSTAGE 24576
#define ATT_SMEM (32768 + 3 * KVSTAGE)      // 106496

__global__ __launch_bounds__(256, 2)
void attn_hmma_kernel()
{
    extern __shared__ char asmem[];

    const int tid = threadIdx.x;
    const int lane = tid & 31;
    const int wid = tid >> 5;              // 0..7
    const int q0 = (int)(gridDim.x - 1 - blockIdx.x) * 128;
    const int bh = blockIdx.y;
    const uint32_t sb = smem_u32(asmem);
    const uint32_t qhB = sb, qlB = sb + 16384;
    const uint32_t lrow = lane & 15;
    const int nt = q0 / 64 + 2;

    {
        const size_t qg = ((size_t)bh * Tsz + q0) * Dsz;
#pragma unroll
        for (int i = 0; i < 4; i++) {
            int chunk = tid + i * 256;
            int row = chunk >> 3, c = chunk & 7;
            uint32_t off = SWOFF(row, c);
            CP16(qhB + off, g_qh + qg + (size_t)row * Dsz + c * 8);
            CP16(qlB + off, g_ql + qg + (size_t)row * Dsz + c * 8);
        }
    }

    auto issue_kv = [&](int jt) {
        if (jt < nt) {
            const int js = jt * 64;
            const uint32_t base = sb + 32768 + (jt % 3) * KVSTAGE;
            const size_t kg = ((size_t)bh * Tsz + js) * Dsz;
            const size_t vg = (size_t)bh * Dsz * Tsz + js;
#pragma unroll
            for (int i = 0; i < 2; i++) {
                int chunk = tid + i * 256;
                int row = chunk >> 3, c = chunk & 7;
                uint32_t off = SWOFF(row, c);
                CP16(base + off,         g_kh + kg + (size_t)row * Dsz + c * 8);
                CP16(base + 8192 + off,  g_kl + kg + (size_t)row * Dsz + c * 8);
                CP16(base + 16384 + off, g_vt + vg + (size_t)row * Tsz + c * 8);
            }
        }
        CP_COMMIT();
    };

    issue_kv(0);
    issue_kv(1);

    float mrow[2] = { -INFINITY, -INFINITY };
    float lsum[2] = { 0.f, 0.f };
    float oa[8][4];
#pragma unroll
    for (int j = 0; j < 8; j++)
#pragma unroll
        for (int q = 0; q < 4; q++) oa[j][q] = 0.f;

    for (int jt = 0; jt < nt; jt++) {
        CP_WAITG(1);
        __syncthreads();

        const int js = jt * 64;
        const uint32_t kvb = sb + 32768 + (jt % 3) * KVSTAGE;
        const uint32_t khB = kvb, klB = kvb + 8192;
        const uint32_t vhB = kvb + 16384;

        float s[8][4];
#pragma unroll
        for (int j = 0; j < 8; j++)
#pragma unroll
            for (int q = 0; q < 4; q++) s[j][q] = 0.f;

#pragma unroll
        for (int ks = 0; ks < 4; ks++) {
            const uint32_t cc = ks * 2 + (lane >> 4);
            uint32_t qhf[4], qlf[4];
            {
                int row = wid * 16 + lrow;
                LDM_X4(qhf[0], qhf[1], qhf[2], qhf[3], qhB + SWOFF(row, cc));
                LDM_X4(qlf[0], qlf[1], qlf[2], qlf[3], qlB + SWOFF(row, cc));
            }
            if (ks == 0) issue_kv(jt + 2);
#pragma unroll
            for (int j2 = 0; j2 < 4; j2++) {
                int row = j2 * 16 + lrow;
                uint32_t off = SWOFF(row, cc);
                uint32_t khf[4], klf[4];
                LDM_X4(khf[0], khf[1], khf[2], khf[3], khB + off);
                LDM_X4(klf[0], klf[1], klf[2], klf[3], klB + off);
#pragma unroll
                for (int o = 0; o < 2; o++) {
                    int j = 2 * j2 + o;
                    MMA_BF(s[j][0], s[j][1], s[j][2], s[j][3],
                           qhf[0], qhf[1], qhf[2], qhf[3], khf[o], khf[o + 2]);
                    MMA_BF(s[j][0], s[j][1], s[j][2], s[j][3],
                           qlf[0], qlf[1], qlf[2], qlf[3], khf[o], khf[o + 2]);
                    MMA_BF(s[j][0], s[j][1], s[j][2], s[j][3],
                           qhf[0], qhf[1], qhf[2], qhf[3], klf[o], klf[o + 2]);
                }
            }
        }

        if (js >= q0) {
#pragma unroll
            for (int j = 0; j < 8; j++)
#pragma unroll
                for (int q = 0; q < 4; q++) {
                    int col = js + j * 8 + 2 * (lane & 3) + (q & 1);
                    int row = q0 + wid * 16 + (lane >> 2) + (q >> 1) * 8;
                    if (col > row) s[j][q] = -INFINITY;
                }
        }

        // Online softmax in log2 domain (q pre-scaled by log2e)
#pragma unroll
        for (int h = 0; h < 2; h++) {
            float mx = -INFINITY;
#pragma unroll
            for (int j = 0; j < 8; j++)
                mx = fmaxf(mx, fmaxf(s[j][2 * h], s[j][2 * h + 1]));
            mx = fmaxf(mx, __shfl_xor_sync(0xffffffffu, mx, 1));
            mx = fmaxf(mx, __shfl_xor_sync(0xffffffffu, mx, 2));
            float nm = fmaxf(mrow[h], mx);
            float alpha = ex2f(mrow[h] - nm);
            float sum = 0.f;
#pragma unroll
            for (int j = 0; j < 8; j++) {
                float p0 = ex2f(s[j][2 * h] - nm);
                float p1 = ex2f(s[j][2 * h + 1] - nm);
                s[j][2 * h] = p0; s[j][2 * h + 1] = p1;
                sum += p0 + p1;
            }
            sum += __shfl_xor_sync(0xffffffffu, sum, 1);
            sum += __shfl_xor_sync(0xffffffffu, sum, 2);
            lsum[h] = lsum[h] * alpha + sum;
            mrow[h] = nm;
#pragma unroll
            for (int j = 0; j < 8; j++) {
                oa[j][2 * h] *= alpha;
                oa[j][2 * h + 1] *= alpha;
            }
        }

        // O += P_fp16 * Vh   (single term)
#pragma unroll
        for (int kt2 = 0; kt2 < 4; kt2++) {
            uint32_t pa[4];
            {
                __half2 t0 = __floats2half2_rn(s[2 * kt2][0],     s[2 * kt2][1]);
                __half2 t1 = __floats2half2_rn(s[2 * kt2][2],     s[2 * kt2][3]);
                __half2 t2 = __floats2half2_rn(s[2 * kt2 + 1][0], s[2 * kt2 + 1][1]);
                __half2 t3 = __floats2half2_rn(s[2 * kt2 + 1][2], s[2 * kt2 + 1][3]);
                pa[0] = *(uint32_t*)&t0; pa[1] = *(uint32_t*)&t1;
                pa[2] = *(uint32_t*)&t2; pa[3] = *(uint32_t*)&t3;
            }
            const uint32_t cc = kt2 * 2 + (lane >> 4);
#pragma unroll
            for (int j2 = 0; j2 < 4; j2++) {
                int row = j2 * 16 + lrow;
                uint32_t off = SWOFF(row, cc);
                uint32_t vhf[4];
                LDM_X4(vhf[0], vhf[1], vhf[2], vhf[3], vhB + off);
#pragma unroll
                for (int o = 0; o < 2; o++) {
                    int j = 2 * j2 + o;
                    MMA_FP(oa[j][0], oa[j][1], oa[j][2], oa[j][3],
                           pa[0], pa[1], pa[2], pa[3], vhf[o], vhf[o + 2]);
                }
            }
        }
    }

    // Epilogue: y = O / l -> yh/yl fp16
    {
        const int b = bh >> 4, hh = bh & 15;
#pragma unroll
        for (int h = 0; h < 2; h++) {
            int t = q0 + wid * 16 + (lane >> 2) + h * 8;
            float invl = 1.f / lsum[h];
            size_t rb = ((size_t)b * Tsz + t) * KD + hh * Dsz;
#pragma unroll
            for (int j = 0; j < 8; j++) {
                int d = j * 8 + 2 * (lane & 3);
                float y0 = oa[j][2 * h] * invl;
                float y1 = oa[j][2 * h + 1] * invl;
                __half h0, l0, h1, l1;
                split2h(y0, h0, l0); split2h(y1, h1, l1);
                *(__half2*)&g_yh[rb + d] = __half2(h0, h1);
                *(__half2*)&g_yl[rb + d] = __half2(l0, l1);
            }
        }
    }
}

// ---------------------------------------------------------------------------
extern "C" void kernel_launch(void* const* d_in, const int* in_sizes, int n_in,
                              void* d_out, int out_size)
{
    const float* x    = (const float*)d_in[0];
    const float* Wqkv = (const float*)d_in[1];
    const float* bqkv = (const float*)d_in[2];
    const float* Wout = (const float*)d_in[3];
    const float* bout = (const float*)d_in[4];
    float* out = (float*)d_out;

    RopeTab tab;
    for (int i = 0; i < 32; i++)
        tab.inv[i] = (float)exp(-(double)(2 * i) / 64.0 * log(10000.0));

    // 0) conversions
    {
        int n = M1 * KD;
        split_x_kernel<<<(n / 4 + 255) / 256, 256>>>(x);
        dim3 g1(3 * Csz / 32, Csz / 32);
        transpose_wqkv_kernel<<<g1, 256>>>(Wqkv);
        dim3 g2(Csz / 32, Csz / 32);
        transpose_wout_kernel<<<g2, 256>>>(Wout);
    }

    // 1) Merged QKV projection (QK bf16x3 + V fp16x2) with fused epilogues
    {
        cudaFuncSetAttribute(qkv_gemm_kernel, cudaFuncAttributeMaxDynamicSharedMemorySize, QKV_SMEM);
        dim3 grid(24, M1 / 128);              // (24, 64)
        qkv_gemm_kernel<<<grid, 256, QKV_SMEM>>>(bqkv, tab);
    }

    // 2) HMMA causal flash attention -> yh/yl
    {
        cudaFuncSetAttribute(attn_hmma_kernel, cudaFuncAttributeMaxDynamicSharedMemorySize, ATT_SMEM);
        dim3 grid(Tsz / 128, Bsz * Hsz);      // (16, 64)
        attn_hmma_kernel<<<grid, 256, ATT_SMEM>>>();
    }

    // 3) Output projection (fp16x2) -> d_out
    {
        cudaFuncSetAttribute(outproj_kernel, cudaFuncAttributeMaxDynamicSharedMemorySize, OUTP_SMEM);
        dim3 grid(Csz / 128, M1 / 128);       // (8, 64)
        outproj_kernel<<<grid, 256, OUTP_SMEM>>>(bout, out);
    }
}

// round 10
// speedup vs baseline: 3.8117x; 1.0012x over previous
#include <cuda_runtime.h>
#include <cuda_bf16.h>
#include <cuda_fp16.h>
#include <math.h>
#include <stdint.h>

// Problem constants
#define Bsz 4
#define Tsz 2048
#define Csz 1024
#define Hsz 16
#define Dsz 64
#define M1 (Bsz * Tsz)        // 8192
#define KD 1024               // real K for all GEMMs

// ---------------------------------------------------------------------------
// Device scratch (allocation-free)
// ---------------------------------------------------------------------------
__device__ __nv_bfloat16 g_qh[Bsz * Hsz * Tsz * Dsz];  // (B,H,T,D)  (scaled by log2e)
__device__ __nv_bfloat16 g_ql[Bsz * Hsz * Tsz * Dsz];
__device__ __nv_bfloat16 g_kh[Bsz * Hsz * Tsz * Dsz];
__device__ __nv_bfloat16 g_kl[Bsz * Hsz * Tsz * Dsz];
__device__ __half        g_vt[Bsz * Hsz * Dsz * Tsz];  // (B,H,D,T) fp16

__device__ __nv_bfloat16 g_xh[M1 * KD];      // x bf16 hi/lo
__device__ __nv_bfloat16 g_xl[M1 * KD];
__device__ __half        g_xhf[M1 * KD];     // x fp16 hi/lo (for V GEMM)
__device__ __half        g_xlf[M1 * KD];
__device__ __half        g_yh[M1 * KD];      // attn out fp16 hi/lo
__device__ __half        g_yl[M1 * KD];
__device__ __nv_bfloat16 g_wqkh[2 * Csz * KD]; // W_q|k^T bf16 hi/lo
__device__ __nv_bfloat16 g_wqkl[2 * Csz * KD];
__device__ __half        g_wvh[Csz * KD];      // W_v^T fp16
__device__ __half        g_woh[Csz * KD];      // W_out^T fp16

// ---------------------------------------------------------------------------
__device__ __forceinline__ uint32_t smem_u32(const void* p) {
    uint32_t a;
    asm("{ .reg .u64 t; cvta.to.shared.u64 t, %1; cvt.u32.u64 %0, t; }" : "=r"(a) : "l"(p));
    return a;
}
__device__ __forceinline__ float ex2f(float x) {
    float r; asm("ex2.approx.ftz.f32 %0, %1;" : "=f"(r) : "f"(x)); return r;
}
__device__ __forceinline__ void split2(float v, __nv_bfloat16& hi, __nv_bfloat16& lo) {
    hi = __float2bfloat16(v);
    lo = __float2bfloat16(v - __bfloat162float(hi));
}
__device__ __forceinline__ void split2h(float v, __half& hi, __half& lo) {
    hi = __float2half(v);
    lo = __float2half(v - __half2float(hi));
}

struct RopeTab { float inv[32]; };
#define LOG2E 1.44269504088896f

// ---------------------------------------------------------------------------
// Conversions
// ---------------------------------------------------------------------------
__global__ __launch_bounds__(256)
void split_x_kernel(const float* __restrict__ in)
{
    int i = (blockIdx.x * blockDim.x + threadIdx.x) * 4;
    if (i >= M1 * KD) return;
    float4 v = *(const float4*)&in[i];
    float vv[4] = { v.x, v.y, v.z, v.w };
    __nv_bfloat16 bh[4], bl[4];
    __half fh[4], fl[4];
#pragma unroll
    for (int q = 0; q < 4; q++) {
        split2(vv[q], bh[q], bl[q]);
        split2h(vv[q], fh[q], fl[q]);
    }
    *(__nv_bfloat162*)&g_xh[i]     = __nv_bfloat162(bh[0], bh[1]);
    *(__nv_bfloat162*)&g_xh[i + 2] = __nv_bfloat162(bh[2], bh[3]);
    *(__nv_bfloat162*)&g_xl[i]     = __nv_bfloat162(bl[0], bl[1]);
    *(__nv_bfloat162*)&g_xl[i + 2] = __nv_bfloat162(bl[2], bl[3]);
    *(__half2*)&g_xhf[i]     = __half2(fh[0], fh[1]);
    *(__half2*)&g_xhf[i + 2] = __half2(fh[2], fh[3]);
    *(__half2*)&g_xlf[i]     = __half2(fl[0], fl[1]);
    *(__half2*)&g_xlf[i + 2] = __half2(fl[2], fl[3]);
}

// W_qkv [1024][3072] -> n<2048: wqkh/wqkl bf16; n>=2048: wvh fp16
__global__ __launch_bounds__(256)
void transpose_wqkv_kernel(const float* __restrict__ W)
{
    __shared__ float ts[32][33];
    int k0 = blockIdx.y * 32, n0 = blockIdx.x * 32;
    int ty = threadIdx.x >> 5, tx = threadIdx.x & 31;
#pragma unroll
    for (int r = 0; r < 4; r++) {
        int row = ty + r * 8;
        ts[row][tx] = W[(size_t)(k0 + row) * (3 * Csz) + n0 + tx];
    }
    __syncthreads();
#pragma unroll
    for (int r = 0; r < 4; r++) {
        int row = ty + r * 8;
        int n = n0 + row;
        float v = ts[tx][row];
        if (n < 2048) {
            __nv_bfloat16 h, l; split2(v, h, l);
            g_wqkh[(size_t)n * KD + k0 + tx] = h;
            g_wqkl[(size_t)n * KD + k0 + tx] = l;
        } else {
            g_wvh[(size_t)(n - 2048) * KD + k0 + tx] = __float2half(v);
        }
    }
}

__global__ __launch_bounds__(256)
void transpose_wout_kernel(const float* __restrict__ W)
{
    __shared__ float ts[32][33];
    int k0 = blockIdx.y * 32, n0 = blockIdx.x * 32;
    int ty = threadIdx.x >> 5, tx = threadIdx.x & 31;
#pragma unroll
    for (int r = 0; r < 4; r++) {
        int row = ty + r * 8;
        ts[row][tx] = W[(size_t)(k0 + row) * Csz + n0 + tx];
    }
    __syncthreads();
#pragma unroll
    for (int r = 0; r < 4; r++) {
        int row = ty + r * 8;
        g_woh[(size_t)(n0 + row) * KD + k0 + tx] = __float2half(ts[tx][row]);
    }
}

// ---------------------------------------------------------------------------
// HMMA / async macros
// ---------------------------------------------------------------------------
#define LDM_X4(r0, r1, r2, r3, addr) \
    asm volatile("ldmatrix.sync.aligned.m8n8.x4.shared.b16 {%0,%1,%2,%3}, [%4];" \
                 : "=r"(r0), "=r"(r1), "=r"(r2), "=r"(r3) : "r"(addr))

#define MMA_BF(c0, c1, c2, c3, a0, a1, a2, a3, b0, b1) \
    asm volatile("mma.sync.aligned.m16n8k16.row.col.f32.bf16.bf16.f32 " \
                 "{%0,%1,%2,%3}, {%4,%5,%6,%7}, {%8,%9}, {%0,%1,%2,%3};" \
                 : "+f"(c0), "+f"(c1), "+f"(c2), "+f"(c3) \
                 : "r"(a0), "r"(a1), "r"(a2), "r"(a3), "r"(b0), "r"(b1))

#define MMA_FP(c0, c1, c2, c3, a0, a1, a2, a3, b0, b1) \
    asm volatile("mma.sync.aligned.m16n8k16.row.col.f32.f16.f16.f32 " \
                 "{%0,%1,%2,%3}, {%4,%5,%6,%7}, {%8,%9}, {%0,%1,%2,%3};" \
                 : "+f"(c0), "+f"(c1), "+f"(c2), "+f"(c3) \
                 : "r"(a0), "r"(a1), "r"(a2), "r"(a3), "r"(b0), "r"(b1))

#define CP16(sa, gp) \
    asm volatile("cp.async.cg.shared.global [%0], [%1], 16;" :: "r"(sa), "l"(gp))
#define CP_COMMIT() asm volatile("cp.async.commit_group;" ::: "memory")
#define CP_WAITG(n) asm volatile("cp.async.wait_group %0;" :: "n"(n) : "memory")

#define SWOFF(row, c) ((row) * 128 + (((c) ^ ((row) & 7)) * 16))
#define SWOFF32(row, c) ((row) * 64 + ((((c) ^ ((row) & 3)) ^ (((row) >> 2) & 1)) * 16))

#define TILE32 8192
#define TRS 272
#define QKV_SMEM (3 * 4 * TILE32)   // 98304

// ---------------------------------------------------------------------------
// Merged QKV GEMM. grid (24, 64).
//   blockIdx.x < 16 : QK (bf16x3) + fused RoPE (+log2e on q) split epilogue
//   blockIdx.x >= 16: V  (fp16x2) + transpose epilogue -> (B,H,D,T)
// Term-major MMA ordering: same-accumulator spacing 4.
// ---------------------------------------------------------------------------
__global__ __launch_bounds__(256, 2)
void qkv_gemm_kernel(const float* __restrict__ bqkv, RopeTab tab)
{
    extern __shared__ char smem_all[];

    const int tid = threadIdx.x;
    const int lane = tid & 31;
    const int wid = tid >> 5;
    const int wm = wid >> 1;
    const int wn = wid & 1;
    const int m0 = blockIdx.y * 128;
    const uint32_t sbase = smem_u32(smem_all);
    const uint32_t lrow = lane & 15;
    const int nk = KD / 32;             // 32

    float acc[2][8][4];
#pragma unroll
    for (int i = 0; i < 2; i++)
#pragma unroll
        for (int j = 0; j < 8; j++)
#pragma unroll
            for (int q = 0; q < 4; q++) acc[i][j][q] = 0.f;

    if (blockIdx.x < 16) {
        // ================= QK path: bf16 3-term =================
        const int n0 = blockIdx.x * 128;
        constexpr int STAGE = 4 * TILE32;

        auto issue_stage = [&](int kt) {
            if (kt < nk) {
                const uint32_t base = sbase + (kt % 3) * STAGE;
                const __nv_bfloat16* pAh = g_xh + (size_t)m0 * KD + kt * 32;
                const __nv_bfloat16* pAl = g_xl + (size_t)m0 * KD + kt * 32;
                const __nv_bfloat16* pBh = g_wqkh + (size_t)n0 * KD + kt * 32;
                const __nv_bfloat16* pBl = g_wqkl + (size_t)n0 * KD + kt * 32;
#pragma unroll
                for (int i = 0; i < 2; i++) {
                    int chunk = tid + i * 256;
                    int row = chunk >> 2, c = chunk & 3;
                    uint32_t off = SWOFF32(row, c);
                    const size_t g = (size_t)row * KD + c * 8;
                    CP16(base + off,              pAh + g);
                    CP16(base + TILE32 + off,     pAl + g);
                    CP16(base + 2 * TILE32 + off, pBh + g);
                    CP16(base + 3 * TILE32 + off, pBl + g);
                }
            }
            CP_COMMIT();
        };

        issue_stage(0);
        issue_stage(1);

        for (int kt = 0; kt < nk; kt++) {
            CP_WAITG(1);
            __syncthreads();
            const uint32_t aBase  = sbase + (kt % 3) * STAGE;
            const uint32_t alBase = aBase + TILE32;
            const uint32_t bBase  = aBase + 2 * TILE32;
            const uint32_t blBase = aBase + 3 * TILE32;
#pragma unroll
            for (int ks = 0; ks < 2; ks++) {
                const uint32_t cc = ks * 2 + (lane >> 4);
                uint32_t ahf[2][4], alf[2][4];
#pragma unroll
                for (int i = 0; i < 2; i++) {
                    int row = wm * 32 + i * 16 + lrow;
                    LDM_X4(ahf[i][0], ahf[i][1], ahf[i][2], ahf[i][3], aBase  + SWOFF32(row, cc));
                    LDM_X4(alf[i][0], alf[i][1], alf[i][2], alf[i][3], alBase + SWOFF32(row, cc));
                }
                if (ks == 0) issue_stage(kt + 2);
#pragma unroll
                for (int j2 = 0; j2 < 4; j2++) {
                    int row = wn * 64 + j2 * 16 + lrow;
                    uint32_t bh4[4], bl4[4];
                    LDM_X4(bh4[0], bh4[1], bh4[2], bh4[3], bBase  + SWOFF32(row, cc));
                    LDM_X4(bl4[0], bl4[1], bl4[2], bl4[3], blBase + SWOFF32(row, cc));
                    // term hh (4 independent accs)
#pragma unroll
                    for (int o = 0; o < 2; o++)
#pragma unroll
                        for (int i = 0; i < 2; i++) {
                            int j = 2 * j2 + o;
                            MMA_BF(acc[i][j][0], acc[i][j][1], acc[i][j][2], acc[i][j][3],
                                   ahf[i][0], ahf[i][1], ahf[i][2], ahf[i][3], bh4[o], bh4[o + 2]);
                        }
                    // term lh
#pragma unroll
                    for (int o = 0; o < 2; o++)
#pragma unroll
                        for (int i = 0; i < 2; i++) {
                            int j = 2 * j2 + o;
                            MMA_BF(acc[i][j][0], acc[i][j][1], acc[i][j][2], acc[i][j][3],
                                   alf[i][0], alf[i][1], alf[i][2], alf[i][3], bh4[o], bh4[o + 2]);
                        }
                    // term hl
#pragma unroll
                    for (int o = 0; o < 2; o++)
#pragma unroll
                        for (int i = 0; i < 2; i++) {
                            int j = 2 * j2 + o;
                            MMA_BF(acc[i][j][0], acc[i][j][1], acc[i][j][2], acc[i][j][3],
                                   ahf[i][0], ahf[i][1], ahf[i][2], ahf[i][3], bl4[o], bl4[o + 2]);
                        }
                }
            }
        }

        // Epilogue: RoPE + split; q additionally scaled by log2e
        const int which = n0 >> 10;          // 0=q, 1=k
        const float l2e = (which == 0) ? LOG2E : 1.f;
        __nv_bfloat16* GH = (which == 0) ? g_qh : g_kh;
        __nv_bfloat16* GL = (which == 0) ? g_ql : g_kl;
        const int b = m0 >> 11;
        const int hh = ((n0 + wn * 64) & 1023) >> 6;
        const int bh = b * Hsz + hh;
        const int dbase = 2 * (lane & 3);
#pragma unroll
        for (int i = 0; i < 2; i++) {
#pragma unroll
            for (int hf = 0; hf < 2; hf++) {
                int m = m0 + wm * 32 + (lane >> 2) + i * 16 + hf * 8;
                int t = m & (Tsz - 1);
                size_t baseo = ((size_t)bh * Tsz + t) * Dsz;
#pragma unroll
                for (int j = 0; j < 4; j++) {
                    int n = n0 + wn * 64 + dbase + j * 8;
                    int d = n & 63;
                    float lowx  = acc[i][j][hf * 2]     + bqkv[n];
                    float lowy  = acc[i][j][hf * 2 + 1] + bqkv[n + 1];
                    float highx = acc[i][j + 4][hf * 2]     + bqkv[n + 32];
                    float highy = acc[i][j + 4][hf * 2 + 1] + bqkv[n + 33];
                    float c0f, s0f, c1f, s1f;
                    sincosf((float)t * tab.inv[d],     &s0f, &c0f);
                    sincosf((float)t * tab.inv[d + 1], &s1f, &c1f);
                    float nlx = (lowx * c0f - highx * s0f) * l2e;
                    float nhx = (highx * c0f + lowx * s0f) * l2e;
                    float nly = (lowy * c1f - highy * s1f) * l2e;
                    float nhy = (highy * c1f + lowy * s1f) * l2e;
                    __nv_bfloat16 hlx, llx, hly, lly, hhx, lhx, hhy, lhy;
                    split2(nlx, hlx, llx); split2(nly, hly, lly);
                    split2(nhx, hhx, lhx); split2(nhy, hhy, lhy);
                    *(__nv_bfloat162*)&GH[baseo + d]      = __nv_bfloat162(hlx, hly);
                    *(__nv_bfloat162*)&GL[baseo + d]      = __nv_bfloat162(llx, lly);
                    *(__nv_bfloat162*)&GH[baseo + d + 32] = __nv_bfloat162(hhx, hhy);
                    *(__nv_bfloat162*)&GL[baseo + d + 32] = __nv_bfloat162(lhx, lhy);
                }
            }
        }
    } else {
        // ================= V path: fp16 2-term =================
        const int n0 = (blockIdx.x - 16) * 128;
        constexpr int STAGE = 3 * TILE32;

        auto issue_stage = [&](int kt) {
            if (kt < nk) {
                const uint32_t base = sbase + (kt % 3) * STAGE;
                const __half* pAh = g_xhf + (size_t)m0 * KD + kt * 32;
                const __half* pAl = g_xlf + (size_t)m0 * KD + kt * 32;
                const __half* pBh = g_wvh + (size_t)n0 * KD + kt * 32;
#pragma unroll
                for (int i = 0; i < 2; i++) {
                    int chunk = tid + i * 256;
                    int row = chunk >> 2, c = chunk & 3;
                    uint32_t off = SWOFF32(row, c);
                    const size_t g = (size_t)row * KD + c * 8;
                    CP16(base + off,              pAh + g);
                    CP16(base + TILE32 + off,     pAl + g);
                    CP16(base + 2 * TILE32 + off, pBh + g);
                }
            }
            CP_COMMIT();
        };

        issue_stage(0);
        issue_stage(1);

        for (int kt = 0; kt < nk; kt++) {
            CP_WAITG(1);
            __syncthreads();
            const uint32_t aBase  = sbase + (kt % 3) * STAGE;
            const uint32_t alBase = aBase + TILE32;
            const uint32_t bBase  = aBase + 2 * TILE32;
#pragma unroll
            for (int ks = 0; ks < 2; ks++) {
                const uint32_t cc = ks * 2 + (lane >> 4);
                uint32_t ahf[2][4], alf[2][4];
#pragma unroll
                for (int i = 0; i < 2; i++) {
                    int row = wm * 32 + i * 16 + lrow;
                    LDM_X4(ahf[i][0], ahf[i][1], ahf[i][2], ahf[i][3], aBase  + SWOFF32(row, cc));
                    LDM_X4(alf[i][0], alf[i][1], alf[i][2], alf[i][3], alBase + SWOFF32(row, cc));
                }
                if (ks == 0) issue_stage(kt + 2);
#pragma unroll
                for (int j2 = 0; j2 < 4; j2++) {
                    int row = wn * 64 + j2 * 16 + lrow;
                    uint32_t bh4[4];
                    LDM_X4(bh4[0], bh4[1], bh4[2], bh4[3], bBase + SWOFF32(row, cc));
                    // term hh
#pragma unroll
                    for (int o = 0; o < 2; o++)
#pragma unroll
                        for (int i = 0; i < 2; i++) {
                            int j = 2 * j2 + o;
                            MMA_FP(acc[i][j][0], acc[i][j][1], acc[i][j][2], acc[i][j][3],
                                   ahf[i][0], ahf[i][1], ahf[i][2], ahf[i][3], bh4[o], bh4[o + 2]);
                        }
                    // term lh
#pragma unroll
                    for (int o = 0; o < 2; o++)
#pragma unroll
                        for (int i = 0; i < 2; i++) {
                            int j = 2 * j2 + o;
                            MMA_FP(acc[i][j][0], acc[i][j][1], acc[i][j][2], acc[i][j][3],
                                   alf[i][0], alf[i][1], alf[i][2], alf[i][3], bh4[o], bh4[o + 2]);
                        }
                }
            }
        }

        // V epilogue: smem transpose -> g_vt (B,H,D,T) fp16
        const int b = m0 >> 11;
        const int t0 = m0 & (Tsz - 1);
        __half* trs = (__half*)smem_all;
        __syncthreads();
#pragma unroll
        for (int i = 0; i < 2; i++)
#pragma unroll
            for (int hf = 0; hf < 2; hf++) {
                int ml = wm * 32 + (lane >> 2) + i * 16 + hf * 8;
#pragma unroll
                for (int j = 0; j < 8; j++) {
                    int nl = wn * 64 + 2 * (lane & 3) + j * 8;
                    float vx = acc[i][j][hf * 2]     + bqkv[2048 + n0 + nl];
                    float vy = acc[i][j][hf * 2 + 1] + bqkv[2048 + n0 + nl + 1];
                    trs[nl * 136 + ml]       = __float2half(vx);
                    trs[(nl + 1) * 136 + ml] = __float2half(vy);
                }
            }
        __syncthreads();
#pragma unroll
        for (int rr = 0; rr < 8; rr++) {
            int row = (tid >> 4) + rr * 16;
            int chunk = tid & 15;
            int n = n0 + row;
            int hh = n >> 6;
            int d = n & 63;
            float4 v = *(float4*)((char*)trs + row * TRS + chunk * 16);
            *(float4*)&g_vt[((size_t)(b * Hsz + hh) * Dsz + d) * Tsz + t0 + chunk * 8] = v;
        }
    }
}

// ---------------------------------------------------------------------------
// Output projection: fp16 2-term, term-major ordering
// ---------------------------------------------------------------------------
#define OUTP_SMEM (3 * 3 * TILE32)

__global__ __launch_bounds__(256, 2)
void outproj_kernel(const float* __restrict__ bias, float* __restrict__ Cout)
{
    extern __shared__ char smem_all[];
    const int tid = threadIdx.x;
    const int lane = tid & 31;
    const int wid = tid >> 5;
    const int wm = wid >> 1;
    const int wn = wid & 1;
    const int m0 = blockIdx.y * 128;
    const int n0 = blockIdx.x * 128;
    const uint32_t sbase = smem_u32(smem_all);
    const uint32_t lrow = lane & 15;
    const int nk = KD / 32;
    constexpr int STAGE = 3 * TILE32;

    auto issue_stage = [&](int kt) {
        if (kt < nk) {
            const uint32_t base = sbase + (kt % 3) * STAGE;
            const __half* pAh = g_yh + (size_t)m0 * KD + kt * 32;
            const __half* pAl = g_yl + (size_t)m0 * KD + kt * 32;
            const __half* pBh = g_woh + (size_t)n0 * KD + kt * 32;
#pragma unroll
            for (int i = 0; i < 2; i++) {
                int chunk = tid + i * 256;
                int row = chunk >> 2, c = chunk & 3;
                uint32_t off = SWOFF32(row, c);
                const size_t g = (size_t)row * KD + c * 8;
                CP16(base + off,              pAh + g);
                CP16(base + TILE32 + off,     pAl + g);
                CP16(base + 2 * TILE32 + off, pBh + g);
            }
        }
        CP_COMMIT();
    };

    issue_stage(0);
    issue_stage(1);

    float acc[2][8][4];
#pragma unroll
    for (int i = 0; i < 2; i++)
#pragma unroll
        for (int j = 0; j < 8; j++)
#pragma unroll
            for (int q = 0; q < 4; q++) acc[i][j][q] = 0.f;

    for (int kt = 0; kt < nk; kt++) {
        CP_WAITG(1);
        __syncthreads();
        const uint32_t aBase  = sbase + (kt % 3) * STAGE;
        const uint32_t alBase = aBase + TILE32;
        const uint32_t bBase  = aBase + 2 * TILE32;
#pragma unroll
        for (int ks = 0; ks < 2; ks++) {
            const uint32_t cc = ks * 2 + (lane >> 4);
            uint32_t ahf[2][4], alf[2][4];
#pragma unroll
            for (int i = 0; i < 2; i++) {
                int row = wm * 32 + i * 16 + lrow;
                LDM_X4(ahf[i][0], ahf[i][1], ahf[i][2], ahf[i][3], aBase  + SWOFF32(row, cc));
                LDM_X4(alf[i][0], alf[i][1], alf[i][2], alf[i][3], alBase + SWOFF32(row, cc));
            }
            if (ks == 0) issue_stage(kt + 2);
#pragma unroll
            for (int j2 = 0; j2 < 4; j2++) {
                int row = wn * 64 + j2 * 16 + lrow;
                uint32_t bh4[4];
                LDM_X4(bh4[0], bh4[1], bh4[2], bh4[3], bBase + SWOFF32(row, cc));
#pragma unroll
                for (int o = 0; o < 2; o++)
#pragma unroll
                    for (int i = 0; i < 2; i++) {
                        int j = 2 * j2 + o;
                        MMA_FP(acc[i][j][0], acc[i][j][1], acc[i][j][2], acc[i][j][3],
                               ahf[i][0], ahf[i][1], ahf[i][2], ahf[i][3], bh4[o], bh4[o + 2]);
                    }
#pragma unroll
                for (int o = 0; o < 2; o++)
#pragma unroll
                    for (int i = 0; i < 2; i++) {
                        int j = 2 * j2 + o;
                        MMA_FP(acc[i][j][0], acc[i][j][1], acc[i][j][2], acc[i][j][3],
                               alf[i][0], alf[i][1], alf[i][2], alf[i][3], bh4[o], bh4[o + 2]);
                    }
            }
        }
    }

    const int mwb = m0 + wm * 32 + (lane >> 2);
    const int nwb = n0 + wn * 64 + 2 * (lane & 3);
#pragma unroll
    for (int i = 0; i < 2; i++)
#pragma unroll
        for (int j = 0; j < 8; j++) {
            int n = nwb + j * 8;
            float bx = bias[n], by = bias[n + 1];
#pragma unroll
            for (int hf = 0; hf < 2; hf++) {
                int m = mwb + i * 16 + hf * 8;
                *(float2*)&Cout[(size_t)m * Csz + n] =
                    make_float2(acc[i][j][hf * 2] + bx, acc[i][j][hf * 2 + 1] + by);
            }
        }
}

// ---------------------------------------------------------------------------
// HMMA flash attention, causal. BM=128 (8 warps x 16 rows), BN=64, D=64.
// S: bf16x3 term-major (j2 pairs). PV: fp16 single-term. 3-stage KV.
// ---------------------------------------------------------------------------
#define KVSTAGE 24576
#define ATT_SMEM (32768 + 3 * KVSTAGE)      // 106496

__global__ __launch_bounds__(256, 2)
void attn_hmma_kernel()
{
    extern __shared__ char asmem[];

    const int tid = threadIdx.x;
    const int lane = tid & 31;
    const int wid = tid >> 5;              // 0..7
    const int q0 = (int)(gridDim.x - 1 - blockIdx.x) * 128;
    const int bh = blockIdx.y;
    const uint32_t sb = smem_u32(asmem);
    const uint32_t qhB = sb, qlB = sb + 16384;
    const uint32_t lrow = lane & 15;
    const int nt = q0 / 64 + 2;

    {
        const size_t qg = ((size_t)bh * Tsz + q0) * Dsz;
#pragma unroll
        for (int i = 0; i < 4; i++) {
            int chunk = tid + i * 256;
            int row = chunk >> 3, c = chunk & 7;
            uint32_t off = SWOFF(row, c);
            CP16(qhB + off, g_qh + qg + (size_t)row * Dsz + c * 8);
            CP16(qlB + off, g_ql + qg + (size_t)row * Dsz + c * 8);
        }
    }

    auto issue_kv = [&](int jt) {
        if (jt < nt) {
            const int js = jt * 64;
            const uint32_t base = sb + 32768 + (jt % 3) * KVSTAGE;
            const size_t kg = ((size_t)bh * Tsz + js) * Dsz;
            const size_t vg = (size_t)bh * Dsz * Tsz + js;
#pragma unroll
            for (int i = 0; i < 2; i++) {
                int chunk = tid + i * 256;
                int row = chunk >> 3, c = chunk & 7;
                uint32_t off = SWOFF(row, c);
                CP16(base + off,         g_kh + kg + (size_t)row * Dsz + c * 8);
                CP16(base + 8192 + off,  g_kl + kg + (size_t)row * Dsz + c * 8);
                CP16(base + 16384 + off, g_vt + vg + (size_t)row * Tsz + c * 8);
            }
        }
        CP_COMMIT();
    };

    issue_kv(0);
    issue_kv(1);

    float mrow[2] = { -INFINITY, -INFINITY };
    float lsum[2] = { 0.f, 0.f };
    float oa[8][4];
#pragma unroll
    for (int j = 0; j < 8; j++)
#pragma unroll
        for (int q = 0; q < 4; q++) oa[j][q] = 0.f;

    for (int jt = 0; jt < nt; jt++) {
        CP_WAITG(1);
        __syncthreads();

        const int js = jt * 64;
        const uint32_t kvb = sb + 32768 + (jt % 3) * KVSTAGE;
        const uint32_t khB = kvb, klB = kvb + 8192;
        const uint32_t vhB = kvb + 16384;

        float s[8][4];
#pragma unroll
        for (int j = 0; j < 8; j++)
#pragma unroll
            for (int q = 0; q < 4; q++) s[j][q] = 0.f;

#pragma unroll
        for (int ks = 0; ks < 4; ks++) {
            const uint32_t cc = ks * 2 + (lane >> 4);
            uint32_t qhf[4], qlf[4];
            {
                int row = wid * 16 + lrow;
                LDM_X4(qhf[0], qhf[1], qhf[2], qhf[3], qhB + SWOFF(row, cc));
                LDM_X4(qlf[0], qlf[1], qlf[2], qlf[3], qlB + SWOFF(row, cc));
            }
            if (ks == 0) issue_kv(jt + 2);
            // j2 pairs: term-major, same-acc spacing 4
#pragma unroll
            for (int jp = 0; jp < 2; jp++) {
                uint32_t khf[2][4], klf[2][4];
#pragma unroll
                for (int u = 0; u < 2; u++) {
                    int row = (jp * 2 + u) * 16 + lrow;
                    uint32_t off = SWOFF(row, cc);
                    LDM_X4(khf[u][0], khf[u][1], khf[u][2], khf[u][3], khB + off);
                    LDM_X4(klf[u][0], klf[u][1], klf[u][2], klf[u][3], klB + off);
                }
                // term hh
#pragma unroll
                for (int u = 0; u < 2; u++)
#pragma unroll
                    for (int o = 0; o < 2; o++) {
                        int j = 2 * (jp * 2 + u) + o;
                        MMA_BF(s[j][0], s[j][1], s[j][2], s[j][3],
                               qhf[0], qhf[1], qhf[2], qhf[3], khf[u][o], khf[u][o + 2]);
                    }
                // term lh
#pragma unroll
                for (int u = 0; u < 2; u++)
#pragma unroll
                    for (int o = 0; o < 2; o++) {
                        int j = 2 * (jp * 2 + u) + o;
                        MMA_BF(s[j][0], s[j][1], s[j][2], s[j][3],
                               qlf[0], qlf[1], qlf[2], qlf[3], khf[u][o], khf[u][o + 2]);
                    }
                // term hl
#pragma unroll
                for (int u = 0; u < 2; u++)
#pragma unroll
                    for (int o = 0; o < 2; o++) {
                        int j = 2 * (jp * 2 + u) + o;
                        MMA_BF(s[j][0], s[j][1], s[j][2], s[j][3],
                               qhf[0], qhf[1], qhf[2], qhf[3], klf[u][o], klf[u][o + 2]);
                    }
            }
        }

        if (js >= q0) {
#pragma unroll
            for (int j = 0; j < 8; j++)
#pragma unroll
                for (int q = 0; q < 4; q++) {
                    int col = js + j * 8 + 2 * (lane & 3) + (q & 1);
                    int row = q0 + wid * 16 + (lane >> 2) + (q >> 1) * 8;
                    if (col > row) s[j][q] = -INFINITY;
                }
        }

        // Online softmax in log2 domain (q pre-scaled by log2e)
#pragma unroll
        for (int h = 0; h < 2; h++) {
            float mx = -INFINITY;
#pragma unroll
            for (int j = 0; j < 8; j++)
                mx = fmaxf(mx, fmaxf(s[j][2 * h], s[j][2 * h + 1]));
            mx = fmaxf(mx, __shfl_xor_sync(0xffffffffu, mx, 1));
            mx = fmaxf(mx, __shfl_xor_sync(0xffffffffu, mx, 2));
            float nm = fmaxf(mrow[h], mx);
            float alpha = ex2f(mrow[h] - nm);
            float sum = 0.f;
#pragma unroll
            for (int j = 0; j < 8; j++) {
                float p0 = ex2f(s[j][2 * h] - nm);
                float p1 = ex2f(s[j][2 * h + 1] - nm);
                s[j][2 * h] = p0; s[j][2 * h + 1] = p1;
                sum += p0 + p1;
            }
            sum += __shfl_xor_sync(0xffffffffu, sum, 1);
            sum += __shfl_xor_sync(0xffffffffu, sum, 2);
            lsum[h] = lsum[h] * alpha + sum;
            mrow[h] = nm;
#pragma unroll
            for (int j = 0; j < 8; j++) {
                oa[j][2 * h] *= alpha;
                oa[j][2 * h + 1] *= alpha;
            }
        }

        // O += P_fp16 * Vh   (single term)
#pragma unroll
        for (int kt2 = 0; kt2 < 4; kt2++) {
            uint32_t pa[4];
            {
                __half2 t0 = __floats2half2_rn(s[2 * kt2][0],     s[2 * kt2][1]);
                __half2 t1 = __floats2half2_rn(s[2 * kt2][2],     s[2 * kt2][3]);
                __half2 t2 = __floats2half2_rn(s[2 * kt2 + 1][0], s[2 * kt2 + 1][1]);
                __half2 t3 = __floats2half2_rn(s[2 * kt2 + 1][2], s[2 * kt2 + 1][3]);
                pa[0] = *(uint32_t*)&t0; pa[1] = *(uint32_t*)&t1;
                pa[2] = *(uint32_t*)&t2; pa[3] = *(uint32_t*)&t3;
            }
            const uint32_t cc = kt2 * 2 + (lane >> 4);
#pragma unroll
            for (int j2 = 0; j2 < 4; j2++) {
                int row = j2 * 16 + lrow;
                uint32_t off = SWOFF(row, cc);
                uint32_t vhf[4];
                LDM_X4(vhf[0], vhf[1], vhf[2], vhf[3], vhB + off);
#pragma unroll
                for (int o = 0; o < 2; o++) {
                    int j = 2 * j2 + o;
                    MMA_FP(oa[j][0], oa[j][1], oa[j][2], oa[j][3],
                           pa[0], pa[1], pa[2], pa[3], vhf[o], vhf[o + 2]);
                }
            }
        }
    }

    // Epilogue: y = O / l -> yh/yl fp16
    {
        const int b = bh >> 4, hh = bh & 15;
#pragma unroll
        for (int h = 0; h < 2; h++) {
            int t = q0 + wid * 16 + (lane >> 2) + h * 8;
            float invl = 1.f / lsum[h];
            size_t rb = ((size_t)b * Tsz + t) * KD + hh * Dsz;
#pragma unroll
            for (int j = 0; j < 8; j++) {
                int d = j * 8 + 2 * (lane & 3);
                float y0 = oa[j][2 * h] * invl;
                float y1 = oa[j][2 * h + 1] * invl;
                __half h0, l0, h1, l1;
                split2h(y0, h0, l0); split2h(y1, h1, l1);
                *(__half2*)&g_yh[rb + d] = __half2(h0, h1);
                *(__half2*)&g_yl[rb + d] = __half2(l0, l1);
            }
        }
    }
}

// ---------------------------------------------------------------------------
extern "C" void kernel_launch(void* const* d_in, const int* in_sizes, int n_in,
                              void* d_out, int out_size)
{
    const float* x    = (const float*)d_in[0];
    const float* Wqkv = (const float*)d_in[1];
    const float* bqkv = (const float*)d_in[2];
    const float* Wout = (const float*)d_in[3];
    const float* bout = (const float*)d_in[4];
    float* out = (float*)d_out;

    RopeTab tab;
    for (int i = 0; i < 32; i++)
        tab.inv[i] = (float)exp(-(double)(2 * i) / 64.0 * log(10000.0));

    // 0) conversions
    {
        int n = M1 * KD;
        split_x_kernel<<<(n / 4 + 255) / 256, 256>>>(x);
        dim3 g1(3 * Csz / 32, Csz / 32);
        transpose_wqkv_kernel<<<g1, 256>>>(Wqkv);
        dim3 g2(Csz / 32, Csz / 32);
        transpose_wout_kernel<<<g2, 256>>>(Wout);
    }

    // 1) Merged QKV projection (QK bf16x3 + V fp16x2) with fused epilogues
    {
        cudaFuncSetAttribute(qkv_gemm_kernel, cudaFuncAttributeMaxDynamicSharedMemorySize, QKV_SMEM);
        dim3 grid(24, M1 / 128);              // (24, 64)
        qkv_gemm_kernel<<<grid, 256, QKV_SMEM>>>(bqkv, tab);
    }

    // 2) HMMA causal flash attention -> yh/yl
    {
        cudaFuncSetAttribute(attn_hmma_kernel, cudaFuncAttributeMaxDynamicSharedMemorySize, ATT_SMEM);
        dim3 grid(Tsz / 128, Bsz * Hsz);      // (16, 64)
        attn_hmma_kernel<<<grid, 256, ATT_SMEM>>>();
    }

    // 3) Output projection (fp16x2) -> d_out
    {
        cudaFuncSetAttribute(outproj_kernel, cudaFuncAttributeMaxDynamicSharedMemorySize, OUTP_SMEM);
        dim3 grid(Csz / 128, M1 / 128);       // (8, 64)
        outproj_kernel<<<grid, 256, OUTP_SMEM>>>(bout, out);
    }
}

// round 11
// speedup vs baseline: 4.3260x; 1.1349x over previous
#include <cuda_runtime.h>
#include <cuda_bf16.h>
#include <cuda_fp16.h>
#include <math.h>
#include <stdint.h>

// Problem constants
#define Bsz 4
#define Tsz 2048
#define Csz 1024
#define Hsz 16
#define Dsz 64
#define M1 (Bsz * Tsz)        // 8192
#define KD 1024               // real K for all GEMMs

// ---------------------------------------------------------------------------
// Device scratch (allocation-free)
// ---------------------------------------------------------------------------
__device__ __nv_bfloat16 g_qh[Bsz * Hsz * Tsz * Dsz];  // (B,H,T,D)  (scaled by log2e)
__device__ __nv_bfloat16 g_ql[Bsz * Hsz * Tsz * Dsz];
__device__ __nv_bfloat16 g_kh[Bsz * Hsz * Tsz * Dsz];
__device__ __nv_bfloat16 g_kl[Bsz * Hsz * Tsz * Dsz];
__device__ __half        g_vt[Bsz * Hsz * Dsz * Tsz];  // (B,H,D,T) fp16

__device__ __nv_bfloat16 g_xh[M1 * KD];      // x bf16 hi/lo (QK GEMM)
__device__ __nv_bfloat16 g_xl[M1 * KD];
__device__ __half        g_xhf[M1 * KD];     // x fp16 hi (V GEMM, single-term)
__device__ __half        g_yh[M1 * KD];      // attn out fp16 (single-term outproj)
__device__ __nv_bfloat16 g_wqkh[2 * Csz * KD]; // W_q|k^T bf16 hi/lo
__device__ __nv_bfloat16 g_wqkl[2 * Csz * KD];
__device__ __half        g_wvh[Csz * KD];      // W_v^T fp16
__device__ __half        g_woh[Csz * KD];      // W_out^T fp16

// ---------------------------------------------------------------------------
__device__ __forceinline__ uint32_t smem_u32(const void* p) {
    uint32_t a;
    asm("{ .reg .u64 t; cvta.to.shared.u64 t, %1; cvt.u32.u64 %0, t; }" : "=r"(a) : "l"(p));
    return a;
}
__device__ __forceinline__ float ex2f(float x) {
    float r; asm("ex2.approx.ftz.f32 %0, %1;" : "=f"(r) : "f"(x)); return r;
}
__device__ __forceinline__ void split2(float v, __nv_bfloat16& hi, __nv_bfloat16& lo) {
    hi = __float2bfloat16(v);
    lo = __float2bfloat16(v - __bfloat162float(hi));
}

struct RopeTab { float inv[32]; };
#define LOG2E 1.44269504088896f

// ---------------------------------------------------------------------------
// Conversions
// ---------------------------------------------------------------------------
__global__ __launch_bounds__(256)
void split_x_kernel(const float* __restrict__ in)
{
    int i = (blockIdx.x * blockDim.x + threadIdx.x) * 4;
    if (i >= M1 * KD) return;
    float4 v = *(const float4*)&in[i];
    float vv[4] = { v.x, v.y, v.z, v.w };
    __nv_bfloat16 bh[4], bl[4];
    __half fh[4];
#pragma unroll
    for (int q = 0; q < 4; q++) {
        split2(vv[q], bh[q], bl[q]);
        fh[q] = __float2half(vv[q]);
    }
    *(__nv_bfloat162*)&g_xh[i]     = __nv_bfloat162(bh[0], bh[1]);
    *(__nv_bfloat162*)&g_xh[i + 2] = __nv_bfloat162(bh[2], bh[3]);
    *(__nv_bfloat162*)&g_xl[i]     = __nv_bfloat162(bl[0], bl[1]);
    *(__nv_bfloat162*)&g_xl[i + 2] = __nv_bfloat162(bl[2], bl[3]);
    *(__half2*)&g_xhf[i]     = __half2(fh[0], fh[1]);
    *(__half2*)&g_xhf[i + 2] = __half2(fh[2], fh[3]);
}

// W_qkv [1024][3072] -> n<2048: wqkh/wqkl bf16; n>=2048: wvh fp16
__global__ __launch_bounds__(256)
void transpose_wqkv_kernel(const float* __restrict__ W)
{
    __shared__ float ts[32][33];
    int k0 = blockIdx.y * 32, n0 = blockIdx.x * 32;
    int ty = threadIdx.x >> 5, tx = threadIdx.x & 31;
#pragma unroll
    for (int r = 0; r < 4; r++) {
        int row = ty + r * 8;
        ts[row][tx] = W[(size_t)(k0 + row) * (3 * Csz) + n0 + tx];
    }
    __syncthreads();
#pragma unroll
    for (int r = 0; r < 4; r++) {
        int row = ty + r * 8;
        int n = n0 + row;
        float v = ts[tx][row];
        if (n < 2048) {
            __nv_bfloat16 h, l; split2(v, h, l);
            g_wqkh[(size_t)n * KD + k0 + tx] = h;
            g_wqkl[(size_t)n * KD + k0 + tx] = l;
        } else {
            g_wvh[(size_t)(n - 2048) * KD + k0 + tx] = __float2half(v);
        }
    }
}

__global__ __launch_bounds__(256)
void transpose_wout_kernel(const float* __restrict__ W)
{
    __shared__ float ts[32][33];
    int k0 = blockIdx.y * 32, n0 = blockIdx.x * 32;
    int ty = threadIdx.x >> 5, tx = threadIdx.x & 31;
#pragma unroll
    for (int r = 0; r < 4; r++) {
        int row = ty + r * 8;
        ts[row][tx] = W[(size_t)(k0 + row) * Csz + n0 + tx];
    }
    __syncthreads();
#pragma unroll
    for (int r = 0; r < 4; r++) {
        int row = ty + r * 8;
        g_woh[(size_t)(n0 + row) * KD + k0 + tx] = __float2half(ts[tx][row]);
    }
}

// ---------------------------------------------------------------------------
// HMMA / async macros
// ---------------------------------------------------------------------------
#define LDM_X4(r0, r1, r2, r3, addr) \
    asm volatile("ldmatrix.sync.aligned.m8n8.x4.shared.b16 {%0,%1,%2,%3}, [%4];" \
                 : "=r"(r0), "=r"(r1), "=r"(r2), "=r"(r3) : "r"(addr))

#define MMA_BF(c0, c1, c2, c3, a0, a1, a2, a3, b0, b1) \
    asm volatile("mma.sync.aligned.m16n8k16.row.col.f32.bf16.bf16.f32 " \
                 "{%0,%1,%2,%3}, {%4,%5,%6,%7}, {%8,%9}, {%0,%1,%2,%3};" \
                 : "+f"(c0), "+f"(c1), "+f"(c2), "+f"(c3) \
                 : "r"(a0), "r"(a1), "r"(a2), "r"(a3), "r"(b0), "r"(b1))

#define MMA_FP(c0, c1, c2, c3, a0, a1, a2, a3, b0, b1) \
    asm volatile("mma.sync.aligned.m16n8k16.row.col.f32.f16.f16.f32 " \
                 "{%0,%1,%2,%3}, {%4,%5,%6,%7}, {%8,%9}, {%0,%1,%2,%3};" \
                 : "+f"(c0), "+f"(c1), "+f"(c2), "+f"(c3) \
                 : "r"(a0), "r"(a1), "r"(a2), "r"(a3), "r"(b0), "r"(b1))

#define CP16(sa, gp) \
    asm volatile("cp.async.cg.shared.global [%0], [%1], 16;" :: "r"(sa), "l"(gp))
#define CP_COMMIT() asm volatile("cp.async.commit_group;" ::: "memory")
#define CP_WAITG(n) asm volatile("cp.async.wait_group %0;" :: "n"(n) : "memory")

#define SWOFF(row, c) ((row) * 128 + (((c) ^ ((row) & 7)) * 16))
#define SWOFF32(row, c) ((row) * 64 + ((((c) ^ ((row) & 3)) ^ (((row) >> 2) & 1)) * 16))

#define TILE32 8192
#define TRS 272
#define QKV_SMEM (3 * 4 * TILE32)   // 98304 (QK path; V path uses 2 buffers/stage)

// ---------------------------------------------------------------------------
// Merged QKV GEMM. grid (24, 64).
//   blockIdx.x < 16 : QK (bf16x3) + fused RoPE (+log2e on q) split epilogue
//   blockIdx.x >= 16: V  (fp16 single-term) + transpose epilogue -> (B,H,D,T)
// ---------------------------------------------------------------------------
__global__ __launch_bounds__(256, 2)
void qkv_gemm_kernel(const float* __restrict__ bqkv, RopeTab tab)
{
    extern __shared__ char smem_all[];

    const int tid = threadIdx.x;
    const int lane = tid & 31;
    const int wid = tid >> 5;
    const int wm = wid >> 1;
    const int wn = wid & 1;
    const int m0 = blockIdx.y * 128;
    const uint32_t sbase = smem_u32(smem_all);
    const uint32_t lrow = lane & 15;
    const int nk = KD / 32;             // 32

    float acc[2][8][4];
#pragma unroll
    for (int i = 0; i < 2; i++)
#pragma unroll
        for (int j = 0; j < 8; j++)
#pragma unroll
            for (int q = 0; q < 4; q++) acc[i][j][q] = 0.f;

    if (blockIdx.x < 16) {
        // ================= QK path: bf16 3-term =================
        const int n0 = blockIdx.x * 128;
        constexpr int STAGE = 4 * TILE32;

        auto issue_stage = [&](int kt) {
            if (kt < nk) {
                const uint32_t base = sbase + (kt % 3) * STAGE;
                const __nv_bfloat16* pAh = g_xh + (size_t)m0 * KD + kt * 32;
                const __nv_bfloat16* pAl = g_xl + (size_t)m0 * KD + kt * 32;
                const __nv_bfloat16* pBh = g_wqkh + (size_t)n0 * KD + kt * 32;
                const __nv_bfloat16* pBl = g_wqkl + (size_t)n0 * KD + kt * 32;
#pragma unroll
                for (int i = 0; i < 2; i++) {
                    int chunk = tid + i * 256;
                    int row = chunk >> 2, c = chunk & 3;
                    uint32_t off = SWOFF32(row, c);
                    const size_t g = (size_t)row * KD + c * 8;
                    CP16(base + off,              pAh + g);
                    CP16(base + TILE32 + off,     pAl + g);
                    CP16(base + 2 * TILE32 + off, pBh + g);
                    CP16(base + 3 * TILE32 + off, pBl + g);
                }
            }
            CP_COMMIT();
        };

        issue_stage(0);
        issue_stage(1);

        for (int kt = 0; kt < nk; kt++) {
            CP_WAITG(1);
            __syncthreads();
            const uint32_t aBase  = sbase + (kt % 3) * STAGE;
            const uint32_t alBase = aBase + TILE32;
            const uint32_t bBase  = aBase + 2 * TILE32;
            const uint32_t blBase = aBase + 3 * TILE32;
#pragma unroll
            for (int ks = 0; ks < 2; ks++) {
                const uint32_t cc = ks * 2 + (lane >> 4);
                uint32_t ahf[2][4], alf[2][4];
#pragma unroll
                for (int i = 0; i < 2; i++) {
                    int row = wm * 32 + i * 16 + lrow;
                    LDM_X4(ahf[i][0], ahf[i][1], ahf[i][2], ahf[i][3], aBase  + SWOFF32(row, cc));
                    LDM_X4(alf[i][0], alf[i][1], alf[i][2], alf[i][3], alBase + SWOFF32(row, cc));
                }
                if (ks == 0) issue_stage(kt + 2);
#pragma unroll
                for (int j2 = 0; j2 < 4; j2++) {
                    int row = wn * 64 + j2 * 16 + lrow;
                    uint32_t bh4[4], bl4[4];
                    LDM_X4(bh4[0], bh4[1], bh4[2], bh4[3], bBase  + SWOFF32(row, cc));
                    LDM_X4(bl4[0], bl4[1], bl4[2], bl4[3], blBase + SWOFF32(row, cc));
#pragma unroll
                    for (int o = 0; o < 2; o++)
#pragma unroll
                        for (int i = 0; i < 2; i++) {
                            int j = 2 * j2 + o;
                            MMA_BF(acc[i][j][0], acc[i][j][1], acc[i][j][2], acc[i][j][3],
                                   ahf[i][0], ahf[i][1], ahf[i][2], ahf[i][3], bh4[o], bh4[o + 2]);
                        }
#pragma unroll
                    for (int o = 0; o < 2; o++)
#pragma unroll
                        for (int i = 0; i < 2; i++) {
                            int j = 2 * j2 + o;
                            MMA_BF(acc[i][j][0], acc[i][j][1], acc[i][j][2], acc[i][j][3],
                                   alf[i][0], alf[i][1], alf[i][2], alf[i][3], bh4[o], bh4[o + 2]);
                        }
#pragma unroll
                    for (int o = 0; o < 2; o++)
#pragma unroll
                        for (int i = 0; i < 2; i++) {
                            int j = 2 * j2 + o;
                            MMA_BF(acc[i][j][0], acc[i][j][1], acc[i][j][2], acc[i][j][3],
                                   ahf[i][0], ahf[i][1], ahf[i][2], ahf[i][3], bl4[o], bl4[o + 2]);
                        }
                }
            }
        }

        // Epilogue: RoPE + split; q additionally scaled by log2e
        const int which = n0 >> 10;          // 0=q, 1=k
        const float l2e = (which == 0) ? LOG2E : 1.f;
        __nv_bfloat16* GH = (which == 0) ? g_qh : g_kh;
        __nv_bfloat16* GL = (which == 0) ? g_ql : g_kl;
        const int b = m0 >> 11;
        const int hh = ((n0 + wn * 64) & 1023) >> 6;
        const int bh = b * Hsz + hh;
        const int dbase = 2 * (lane & 3);
#pragma unroll
        for (int i = 0; i < 2; i++) {
#pragma unroll
            for (int hf = 0; hf < 2; hf++) {
                int m = m0 + wm * 32 + (lane >> 2) + i * 16 + hf * 8;
                int t = m & (Tsz - 1);
                size_t baseo = ((size_t)bh * Tsz + t) * Dsz;
#pragma unroll
                for (int j = 0; j < 4; j++) {
                    int n = n0 + wn * 64 + dbase + j * 8;
                    int d = n & 63;
                    float lowx  = acc[i][j][hf * 2]     + bqkv[n];
                    float lowy  = acc[i][j][hf * 2 + 1] + bqkv[n + 1];
                    float highx = acc[i][j + 4][hf * 2]     + bqkv[n + 32];
                    float highy = acc[i][j + 4][hf * 2 + 1] + bqkv[n + 33];
                    float c0f, s0f, c1f, s1f;
                    sincosf((float)t * tab.inv[d],     &s0f, &c0f);
                    sincosf((float)t * tab.inv[d + 1], &s1f, &c1f);
                    float nlx = (lowx * c0f - highx * s0f) * l2e;
                    float nhx = (highx * c0f + lowx * s0f) * l2e;
                    float nly = (lowy * c1f - highy * s1f) * l2e;
                    float nhy = (highy * c1f + lowy * s1f) * l2e;
                    __nv_bfloat16 hlx, llx, hly, lly, hhx, lhx, hhy, lhy;
                    split2(nlx, hlx, llx); split2(nly, hly, lly);
                    split2(nhx, hhx, lhx); split2(nhy, hhy, lhy);
                    *(__nv_bfloat162*)&GH[baseo + d]      = __nv_bfloat162(hlx, hly);
                    *(__nv_bfloat162*)&GL[baseo + d]      = __nv_bfloat162(llx, lly);
                    *(__nv_bfloat162*)&GH[baseo + d + 32] = __nv_bfloat162(hhx, hhy);
                    *(__nv_bfloat162*)&GL[baseo + d + 32] = __nv_bfloat162(lhx, lhy);
                }
            }
        }
    } else {
        // ================= V path: fp16 single-term =================
        const int n0 = (blockIdx.x - 16) * 128;
        constexpr int STAGE = 2 * TILE32;

        auto issue_stage = [&](int kt) {
            if (kt < nk) {
                const uint32_t base = sbase + (kt % 3) * STAGE;
                const __half* pAh = g_xhf + (size_t)m0 * KD + kt * 32;
                const __half* pBh = g_wvh + (size_t)n0 * KD + kt * 32;
#pragma unroll
                for (int i = 0; i < 2; i++) {
                    int chunk = tid + i * 256;
                    int row = chunk >> 2, c = chunk & 3;
                    uint32_t off = SWOFF32(row, c);
                    const size_t g = (size_t)row * KD + c * 8;
                    CP16(base + off,          pAh + g);
                    CP16(base + TILE32 + off, pBh + g);
                }
            }
            CP_COMMIT();
        };

        issue_stage(0);
        issue_stage(1);

        for (int kt = 0; kt < nk; kt++) {
            CP_WAITG(1);
            __syncthreads();
            const uint32_t aBase = sbase + (kt % 3) * STAGE;
            const uint32_t bBase = aBase + TILE32;
#pragma unroll
            for (int ks = 0; ks < 2; ks++) {
                const uint32_t cc = ks * 2 + (lane >> 4);
                uint32_t ahf[2][4];
#pragma unroll
                for (int i = 0; i < 2; i++) {
                    int row = wm * 32 + i * 16 + lrow;
                    LDM_X4(ahf[i][0], ahf[i][1], ahf[i][2], ahf[i][3], aBase + SWOFF32(row, cc));
                }
                if (ks == 0) issue_stage(kt + 2);
#pragma unroll
                for (int j2 = 0; j2 < 4; j2++) {
                    int row = wn * 64 + j2 * 16 + lrow;
                    uint32_t bh4[4];
                    LDM_X4(bh4[0], bh4[1], bh4[2], bh4[3], bBase + SWOFF32(row, cc));
#pragma unroll
                    for (int o = 0; o < 2; o++)
#pragma unroll
                        for (int i = 0; i < 2; i++) {
                            int j = 2 * j2 + o;
                            MMA_FP(acc[i][j][0], acc[i][j][1], acc[i][j][2], acc[i][j][3],
                                   ahf[i][0], ahf[i][1], ahf[i][2], ahf[i][3], bh4[o], bh4[o + 2]);
                        }
                }
            }
        }

        // V epilogue: smem transpose -> g_vt (B,H,D,T) fp16
        const int b = m0 >> 11;
        const int t0 = m0 & (Tsz - 1);
        __half* trs = (__half*)smem_all;
        __syncthreads();
#pragma unroll
        for (int i = 0; i < 2; i++)
#pragma unroll
            for (int hf = 0; hf < 2; hf++) {
                int ml = wm * 32 + (lane >> 2) + i * 16 + hf * 8;
#pragma unroll
                for (int j = 0; j < 8; j++) {
                    int nl = wn * 64 + 2 * (lane & 3) + j * 8;
                    float vx = acc[i][j][hf * 2]     + bqkv[2048 + n0 + nl];
                    float vy = acc[i][j][hf * 2 + 1] + bqkv[2048 + n0 + nl + 1];
                    trs[nl * 136 + ml]       = __float2half(vx);
                    trs[(nl + 1) * 136 + ml] = __float2half(vy);
                }
            }
        __syncthreads();
#pragma unroll
        for (int rr = 0; rr < 8; rr++) {
            int row = (tid >> 4) + rr * 16;
            int chunk = tid & 15;
            int n = n0 + row;
            int hh = n >> 6;
            int d = n & 63;
            float4 v = *(float4*)((char*)trs + row * TRS + chunk * 16);
            *(float4*)&g_vt[((size_t)(b * Hsz + hh) * Dsz + d) * Tsz + t0 + chunk * 8] = v;
        }
    }
}

// ---------------------------------------------------------------------------
// Output projection: fp16 single-term (yh @ Woh)
// ---------------------------------------------------------------------------
#define OUTP_SMEM (3 * 2 * TILE32)

__global__ __launch_bounds__(256, 2)
void outproj_kernel(const float* __restrict__ bias, float* __restrict__ Cout)
{
    extern __shared__ char smem_all[];
    const int tid = threadIdx.x;
    const int lane = tid & 31;
    const int wid = tid >> 5;
    const int wm = wid >> 1;
    const int wn = wid & 1;
    const int m0 = blockIdx.y * 128;
    const int n0 = blockIdx.x * 128;
    const uint32_t sbase = smem_u32(smem_all);
    const uint32_t lrow = lane & 15;
    const int nk = KD / 32;
    constexpr int STAGE = 2 * TILE32;

    auto issue_stage = [&](int kt) {
        if (kt < nk) {
            const uint32_t base = sbase + (kt % 3) * STAGE;
            const __half* pAh = g_yh + (size_t)m0 * KD + kt * 32;
            const __half* pBh = g_woh + (size_t)n0 * KD + kt * 32;
#pragma unroll
            for (int i = 0; i < 2; i++) {
                int chunk = tid + i * 256;
                int row = chunk >> 2, c = chunk & 3;
                uint32_t off = SWOFF32(row, c);
                const size_t g = (size_t)row * KD + c * 8;
                CP16(base + off,          pAh + g);
                CP16(base + TILE32 + off, pBh + g);
            }
        }
        CP_COMMIT();
    };

    issue_stage(0);
    issue_stage(1);

    float acc[2][8][4];
#pragma unroll
    for (int i = 0; i < 2; i++)
#pragma unroll
        for (int j = 0; j < 8; j++)
#pragma unroll
            for (int q = 0; q < 4; q++) acc[i][j][q] = 0.f;

    for (int kt = 0; kt < nk; kt++) {
        CP_WAITG(1);
        __syncthreads();
        const uint32_t aBase = sbase + (kt % 3) * STAGE;
        const uint32_t bBase = aBase + TILE32;
#pragma unroll
        for (int ks = 0; ks < 2; ks++) {
            const uint32_t cc = ks * 2 + (lane >> 4);
            uint32_t ahf[2][4];
#pragma unroll
            for (int i = 0; i < 2; i++) {
                int row = wm * 32 + i * 16 + lrow;
                LDM_X4(ahf[i][0], ahf[i][1], ahf[i][2], ahf[i][3], aBase + SWOFF32(row, cc));
            }
            if (ks == 0) issue_stage(kt + 2);
#pragma unroll
            for (int j2 = 0; j2 < 4; j2++) {
                int row = wn * 64 + j2 * 16 + lrow;
                uint32_t bh4[4];
                LDM_X4(bh4[0], bh4[1], bh4[2], bh4[3], bBase + SWOFF32(row, cc));
#pragma unroll
                for (int o = 0; o < 2; o++)
#pragma unroll
                    for (int i = 0; i < 2; i++) {
                        int j = 2 * j2 + o;
                        MMA_FP(acc[i][j][0], acc[i][j][1], acc[i][j][2], acc[i][j][3],
                               ahf[i][0], ahf[i][1], ahf[i][2], ahf[i][3], bh4[o], bh4[o + 2]);
                    }
            }
        }
    }

    const int mwb = m0 + wm * 32 + (lane >> 2);
    const int nwb = n0 + wn * 64 + 2 * (lane & 3);
#pragma unroll
    for (int i = 0; i < 2; i++)
#pragma unroll
        for (int j = 0; j < 8; j++) {
            int n = nwb + j * 8;
            float bx = bias[n], by = bias[n + 1];
#pragma unroll
            for (int hf = 0; hf < 2; hf++) {
                int m = mwb + i * 16 + hf * 8;
                *(float2*)&Cout[(size_t)m * Csz + n] =
                    make_float2(acc[i][j][hf * 2] + bx, acc[i][j][hf * 2 + 1] + by);
            }
        }
}

// ---------------------------------------------------------------------------
// HMMA flash attention, causal. BM=128 (8 warps x 16 rows), BN=64, D=64.
// S: bf16x3 (ex2 softmax). PV: fp16 single-term. 3-stage KV.
// ---------------------------------------------------------------------------
#define KVSTAGE 24576
#define ATT_SMEM (32768 + 3 * KVSTAGE)      // 106496

__global__ __launch_bounds__(256, 2)
void attn_hmma_kernel()
{
    extern __shared__ char asmem[];

    const int tid = threadIdx.x;
    const int lane = tid & 31;
    const int wid = tid >> 5;              // 0..7
    const int q0 = (int)(gridDim.x - 1 - blockIdx.x) * 128;
    const int bh = blockIdx.y;
    const uint32_t sb = smem_u32(asmem);
    const uint32_t qhB = sb, qlB = sb + 16384;
    const uint32_t lrow = lane & 15;
    const int nt = q0 / 64 + 2;

    {
        const size_t qg = ((size_t)bh * Tsz + q0) * Dsz;
#pragma unroll
        for (int i = 0; i < 4; i++) {
            int chunk = tid + i * 256;
            int row = chunk >> 3, c = chunk & 7;
            uint32_t off = SWOFF(row, c);
            CP16(qhB + off, g_qh + qg + (size_t)row * Dsz + c * 8);
            CP16(qlB + off, g_ql + qg + (size_t)row * Dsz + c * 8);
        }
    }

    auto issue_kv = [&](int jt) {
        if (jt < nt) {
            const int js = jt * 64;
            const uint32_t base = sb + 32768 + (jt % 3) * KVSTAGE;
            const size_t kg = ((size_t)bh * Tsz + js) * Dsz;
            const size_t vg = (size_t)bh * Dsz * Tsz + js;
#pragma unroll
            for (int i = 0; i < 2; i++) {
                int chunk = tid + i * 256;
                int row = chunk >> 3, c = chunk & 7;
                uint32_t off = SWOFF(row, c);
                CP16(base + off,         g_kh + kg + (size_t)row * Dsz + c * 8);
                CP16(base + 8192 + off,  g_kl + kg + (size_t)row * Dsz + c * 8);
                CP16(base + 16384 + off, g_vt + vg + (size_t)row * Tsz + c * 8);
            }
        }
        CP_COMMIT();
    };

    issue_kv(0);
    issue_kv(1);

    float mrow[2] = { -INFINITY, -INFINITY };
    float lsum[2] = { 0.f, 0.f };
    float oa[8][4];
#pragma unroll
    for (int j = 0; j < 8; j++)
#pragma unroll
        for (int q = 0; q < 4; q++) oa[j][q] = 0.f;

    for (int jt = 0; jt < nt; jt++) {
        CP_WAITG(1);
        __syncthreads();

        const int js = jt * 64;
        const uint32_t kvb = sb + 32768 + (jt % 3) * KVSTAGE;
        const uint32_t khB = kvb, klB = kvb + 8192;
        const uint32_t vhB = kvb + 16384;

        float s[8][4];
#pragma unroll
        for (int j = 0; j < 8; j++)
#pragma unroll
            for (int q = 0; q < 4; q++) s[j][q] = 0.f;

#pragma unroll
        for (int ks = 0; ks < 4; ks++) {
            const uint32_t cc = ks * 2 + (lane >> 4);
            uint32_t qhf[4], qlf[4];
            {
                int row = wid * 16 + lrow;
                LDM_X4(qhf[0], qhf[1], qhf[2], qhf[3], qhB + SWOFF(row, cc));
                LDM_X4(qlf[0], qlf[1], qlf[2], qlf[3], qlB + SWOFF(row, cc));
            }
            if (ks == 0) issue_kv(jt + 2);
#pragma unroll
            for (int jp = 0; jp < 2; jp++) {
                uint32_t khf[2][4], klf[2][4];
#pragma unroll
                for (int u = 0; u < 2; u++) {
                    int row = (jp * 2 + u) * 16 + lrow;
                    uint32_t off = SWOFF(row, cc);
                    LDM_X4(khf[u][0], khf[u][1], khf[u][2], khf[u][3], khB + off);
                    LDM_X4(klf[u][0], klf[u][1], klf[u][2], klf[u][3], klB + off);
                }
#pragma unroll
                for (int u = 0; u < 2; u++)
#pragma unroll
                    for (int o = 0; o < 2; o++) {
                        int j = 2 * (jp * 2 + u) + o;
                        MMA_BF(s[j][0], s[j][1], s[j][2], s[j][3],
                               qhf[0], qhf[1], qhf[2], qhf[3], khf[u][o], khf[u][o + 2]);
                    }
#pragma unroll
                for (int u = 0; u < 2; u++)
#pragma unroll
                    for (int o = 0; o < 2; o++) {
                        int j = 2 * (jp * 2 + u) + o;
                        MMA_BF(s[j][0], s[j][1], s[j][2], s[j][3],
                               qlf[0], qlf[1], qlf[2], qlf[3], khf[u][o], khf[u][o + 2]);
                    }
#pragma unroll
                for (int u = 0; u < 2; u++)
#pragma unroll
                    for (int o = 0; o < 2; o++) {
                        int j = 2 * (jp * 2 + u) + o;
                        MMA_BF(s[j][0], s[j][1], s[j][2], s[j][3],
                               qhf[0], qhf[1], qhf[2], qhf[3], klf[u][o], klf[u][o + 2]);
                    }
            }
        }

        if (js >= q0) {
#pragma unroll
            for (int j = 0; j < 8; j++)
#pragma unroll
                for (int q = 0; q < 4; q++) {
                    int col = js + j * 8 + 2 * (lane & 3) + (q & 1);
                    int row = q0 + wid * 16 + (lane >> 2) + (q >> 1) * 8;
                    if (col > row) s[j][q] = -INFINITY;
                }
        }

        // Online softmax in log2 domain (q pre-scaled by log2e)
#pragma unroll
        for (int h = 0; h < 2; h++) {
            float mx = -INFINITY;
#pragma unroll
            for (int j = 0; j < 8; j++)
                mx = fmaxf(mx, fmaxf(s[j][2 * h], s[j][2 * h + 1]));
            mx = fmaxf(mx, __shfl_xor_sync(0xffffffffu, mx, 1));
            mx = fmaxf(mx, __shfl_xor_sync(0xffffffffu, mx, 2));
            float nm = fmaxf(mrow[h], mx);
            float alpha = ex2f(mrow[h] - nm);
            float sum = 0.f;
#pragma unroll
            for (int j = 0; j < 8; j++) {
                float p0 = ex2f(s[j][2 * h] - nm);
                float p1 = ex2f(s[j][2 * h + 1] - nm);
                s[j][2 * h] = p0; s[j][2 * h + 1] = p1;
                sum += p0 + p1;
            }
            sum += __shfl_xor_sync(0xffffffffu, sum, 1);
            sum += __shfl_xor_sync(0xffffffffu, sum, 2);
            lsum[h] = lsum[h] * alpha + sum;
            mrow[h] = nm;
#pragma unroll
            for (int j = 0; j < 8; j++) {
                oa[j][2 * h] *= alpha;
                oa[j][2 * h + 1] *= alpha;
            }
        }

        // O += P_fp16 * Vh   (single term)
#pragma unroll
        for (int kt2 = 0; kt2 < 4; kt2++) {
            uint32_t pa[4];
            {
                __half2 t0 = __floats2half2_rn(s[2 * kt2][0],     s[2 * kt2][1]);
                __half2 t1 = __floats2half2_rn(s[2 * kt2][2],     s[2 * kt2][3]);
                __half2 t2 = __floats2half2_rn(s[2 * kt2 + 1][0], s[2 * kt2 + 1][1]);
                __half2 t3 = __floats2half2_rn(s[2 * kt2 + 1][2], s[2 * kt2 + 1][3]);
                pa[0] = *(uint32_t*)&t0; pa[1] = *(uint32_t*)&t1;
                pa[2] = *(uint32_t*)&t2; pa[3] = *(uint32_t*)&t3;
            }
            const uint32_t cc = kt2 * 2 + (lane >> 4);
#pragma unroll
            for (int j2 = 0; j2 < 4; j2++) {
                int row = j2 * 16 + lrow;
                uint32_t off = SWOFF(row, cc);
                uint32_t vhf[4];
                LDM_X4(vhf[0], vhf[1], vhf[2], vhf[3], vhB + off);
#pragma unroll
                for (int o = 0; o < 2; o++) {
                    int j = 2 * j2 + o;
                    MMA_FP(oa[j][0], oa[j][1], oa[j][2], oa[j][3],
                           pa[0], pa[1], pa[2], pa[3], vhf[o], vhf[o + 2]);
                }
            }
        }
    }

    // Epilogue: y = O / l -> yh fp16 (single-term outproj input)
    {
        const int b = bh >> 4, hh = bh & 15;
#pragma unroll
        for (int h = 0; h < 2; h++) {
            int t = q0 + wid * 16 + (lane >> 2) + h * 8;
            float invl = 1.f / lsum[h];
            size_t rb = ((size_t)b * Tsz + t) * KD + hh * Dsz;
#pragma unroll
            for (int j = 0; j < 8; j++) {
                int d = j * 8 + 2 * (lane & 3);
                float y0 = oa[j][2 * h] * invl;
                float y1 = oa[j][2 * h + 1] * invl;
                *(__half2*)&g_yh[rb + d] = __floats2half2_rn(y0, y1);
            }
        }
    }
}

// ---------------------------------------------------------------------------
extern "C" void kernel_launch(void* const* d_in, const int* in_sizes, int n_in,
                              void* d_out, int out_size)
{
    const float* x    = (const float*)d_in[0];
    const float* Wqkv = (const float*)d_in[1];
    const float* bqkv = (const float*)d_in[2];
    const float* Wout = (const float*)d_in[3];
    const float* bout = (const float*)d_in[4];
    float* out = (float*)d_out;

    RopeTab tab;
    for (int i = 0; i < 32; i++)
        tab.inv[i] = (float)exp(-(double)(2 * i) / 64.0 * log(10000.0));

    // 0) conversions
    {
        int n = M1 * KD;
        split_x_kernel<<<(n / 4 + 255) / 256, 256>>>(x);
        dim3 g1(3 * Csz / 32, Csz / 32);
        transpose_wqkv_kernel<<<g1, 256>>>(Wqkv);
        dim3 g2(Csz / 32, Csz / 32);
        transpose_wout_kernel<<<g2, 256>>>(Wout);
    }

    // 1) Merged QKV projection (QK bf16x3 + V fp16 single-term)
    {
        cudaFuncSetAttribute(qkv_gemm_kernel, cudaFuncAttributeMaxDynamicSharedMemorySize, QKV_SMEM);
        dim3 grid(24, M1 / 128);              // (24, 64)
        qkv_gemm_kernel<<<grid, 256, QKV_SMEM>>>(bqkv, tab);
    }

    // 2) HMMA causal flash attention -> yh
    {
        cudaFuncSetAttribute(attn_hmma_kernel, cudaFuncAttributeMaxDynamicSharedMemorySize, ATT_SMEM);
        dim3 grid(Tsz / 128, Bsz * Hsz);      // (16, 64)
        attn_hmma_kernel<<<grid, 256, ATT_SMEM>>>();
    }

    // 3) Output projection (fp16 single-term) -> d_out
    {
        cudaFuncSetAttribute(outproj_kernel, cudaFuncAttributeMaxDynamicSharedMemorySize, OUTP_SMEM);
        dim3 grid(Csz / 128, M1 / 128);       // (8, 64)
        outproj_kernel<<<grid, 256, OUTP_SMEM>>>(bout, out);
    }
}

// round 12
// speedup vs baseline: 4.4150x; 1.0206x over previous
#include <cuda_runtime.h>
#include <cuda_bf16.h>
#include <cuda_fp16.h>
#include <math.h>
#include <stdint.h>

// Problem constants
#define Bsz 4
#define Tsz 2048
#define Csz 1024
#define Hsz 16
#define Dsz 64
#define M1 (Bsz * Tsz)        // 8192
#define KD 1024               // real K for all GEMMs

// ---------------------------------------------------------------------------
// Device scratch (allocation-free)
// ---------------------------------------------------------------------------
__device__ __nv_bfloat16 g_qh[Bsz * Hsz * Tsz * Dsz];  // (B,H,T,D)  (scaled by log2e)
__device__ __nv_bfloat16 g_ql[Bsz * Hsz * Tsz * Dsz];
__device__ __nv_bfloat16 g_kh[Bsz * Hsz * Tsz * Dsz];
__device__ __nv_bfloat16 g_kl[Bsz * Hsz * Tsz * Dsz];
__device__ __half        g_vt[Bsz * Hsz * Dsz * Tsz];  // (B,H,D,T) fp16

__device__ __nv_bfloat16 g_xh[M1 * KD];      // x bf16 hi/lo (QK GEMM)
__device__ __nv_bfloat16 g_xl[M1 * KD];
__device__ __half        g_xhf[M1 * KD];     // x fp16 hi (V GEMM, single-term)
__device__ __half        g_yh[M1 * KD];      // attn out fp16 (single-term outproj)
__device__ __nv_bfloat16 g_wqkh[2 * Csz * KD]; // W_q|k^T bf16 hi/lo
__device__ __nv_bfloat16 g_wqkl[2 * Csz * KD];
__device__ __half        g_wvh[Csz * KD];      // W_v^T fp16
__device__ __half        g_woh[Csz * KD];      // W_out^T fp16

// ---------------------------------------------------------------------------
__device__ __forceinline__ uint32_t smem_u32(const void* p) {
    uint32_t a;
    asm("{ .reg .u64 t; cvta.to.shared.u64 t, %1; cvt.u32.u64 %0, t; }" : "=r"(a) : "l"(p));
    return a;
}
__device__ __forceinline__ float ex2f(float x) {
    float r; asm("ex2.approx.ftz.f32 %0, %1;" : "=f"(r) : "f"(x)); return r;
}
__device__ __forceinline__ void split2(float v, __nv_bfloat16& hi, __nv_bfloat16& lo) {
    hi = __float2bfloat16(v);
    lo = __float2bfloat16(v - __bfloat162float(hi));
}

struct RopeTab { float inv[32]; };
#define LOG2E 1.44269504088896f

// ---------------------------------------------------------------------------
// Merged conversion kernel (one launch):
//   blocks [0, 8192)           : split x
//   blocks [8192, 8192+3072)   : transpose W_qkv
//   blocks [11264, 11264+1024) : transpose W_out
// ---------------------------------------------------------------------------
#define NB_SPLITX 8192
#define NB_WQKV   3072   // 96 x 32
#define NB_WOUT   1024   // 32 x 32

__global__ __launch_bounds__(256)
void convert_kernel(const float* __restrict__ x, const float* __restrict__ Wqkv,
                    const float* __restrict__ Wout)
{
    int blk = blockIdx.x;
    if (blk < NB_SPLITX) {
        int i = (blk * 256 + threadIdx.x) * 4;
        float4 v = *(const float4*)&x[i];
        float vv[4] = { v.x, v.y, v.z, v.w };
        __nv_bfloat16 bh[4], bl[4];
        __half fh[4];
#pragma unroll
        for (int q = 0; q < 4; q++) {
            split2(vv[q], bh[q], bl[q]);
            fh[q] = __float2half(vv[q]);
        }
        *(__nv_bfloat162*)&g_xh[i]     = __nv_bfloat162(bh[0], bh[1]);
        *(__nv_bfloat162*)&g_xh[i + 2] = __nv_bfloat162(bh[2], bh[3]);
        *(__nv_bfloat162*)&g_xl[i]     = __nv_bfloat162(bl[0], bl[1]);
        *(__nv_bfloat162*)&g_xl[i + 2] = __nv_bfloat162(bl[2], bl[3]);
        *(__half2*)&g_xhf[i]     = __half2(fh[0], fh[1]);
        *(__half2*)&g_xhf[i + 2] = __half2(fh[2], fh[3]);
        return;
    }

    __shared__ float ts[32][33];
    int ty = threadIdx.x >> 5, tx = threadIdx.x & 31;

    if (blk < NB_SPLITX + NB_WQKV) {
        int b2 = blk - NB_SPLITX;
        int n0 = (b2 % 96) * 32, k0 = (b2 / 96) * 32;
#pragma unroll
        for (int r = 0; r < 4; r++) {
            int row = ty + r * 8;
            ts[row][tx] = Wqkv[(size_t)(k0 + row) * (3 * Csz) + n0 + tx];
        }
        __syncthreads();
#pragma unroll
        for (int r = 0; r < 4; r++) {
            int row = ty + r * 8;
            int n = n0 + row;
            float v = ts[tx][row];
            if (n < 2048) {
                __nv_bfloat16 h, l; split2(v, h, l);
                g_wqkh[(size_t)n * KD + k0 + tx] = h;
                g_wqkl[(size_t)n * KD + k0 + tx] = l;
            } else {
                g_wvh[(size_t)(n - 2048) * KD + k0 + tx] = __float2half(v);
            }
        }
    } else {
        int b2 = blk - NB_SPLITX - NB_WQKV;
        int n0 = (b2 % 32) * 32, k0 = (b2 / 32) * 32;
#pragma unroll
        for (int r = 0; r < 4; r++) {
            int row = ty + r * 8;
            ts[row][tx] = Wout[(size_t)(k0 + row) * Csz + n0 + tx];
        }
        __syncthreads();
#pragma unroll
        for (int r = 0; r < 4; r++) {
            int row = ty + r * 8;
            g_woh[(size_t)(n0 + row) * KD + k0 + tx] = __float2half(ts[tx][row]);
        }
    }
}

// ---------------------------------------------------------------------------
// HMMA / async macros
// ---------------------------------------------------------------------------
#define LDM_X4(r0, r1, r2, r3, addr) \
    asm volatile("ldmatrix.sync.aligned.m8n8.x4.shared.b16 {%0,%1,%2,%3}, [%4];" \
                 : "=r"(r0), "=r"(r1), "=r"(r2), "=r"(r3) : "r"(addr))

#define MMA_BF(c0, c1, c2, c3, a0, a1, a2, a3, b0, b1) \
    asm volatile("mma.sync.aligned.m16n8k16.row.col.f32.bf16.bf16.f32 " \
                 "{%0,%1,%2,%3}, {%4,%5,%6,%7}, {%8,%9}, {%0,%1,%2,%3};" \
                 : "+f"(c0), "+f"(c1), "+f"(c2), "+f"(c3) \
                 : "r"(a0), "r"(a1), "r"(a2), "r"(a3), "r"(b0), "r"(b1))

#define MMA_FP(c0, c1, c2, c3, a0, a1, a2, a3, b0, b1) \
    asm volatile("mma.sync.aligned.m16n8k16.row.col.f32.f16.f16.f32 " \
                 "{%0,%1,%2,%3}, {%4,%5,%6,%7}, {%8,%9}, {%0,%1,%2,%3};" \
                 : "+f"(c0), "+f"(c1), "+f"(c2), "+f"(c3) \
                 : "r"(a0), "r"(a1), "r"(a2), "r"(a3), "r"(b0), "r"(b1))

#define CP16(sa, gp) \
    asm volatile("cp.async.cg.shared.global [%0], [%1], 16;" :: "r"(sa), "l"(gp))
#define CP_COMMIT() asm volatile("cp.async.commit_group;" ::: "memory")
#define CP_WAITG(n) asm volatile("cp.async.wait_group %0;" :: "n"(n) : "memory")

#define SWOFF(row, c) ((row) * 128 + (((c) ^ ((row) & 7)) * 16))
#define SWOFF32(row, c) ((row) * 64 + ((((c) ^ ((row) & 3)) ^ (((row) >> 2) & 1)) * 16))

#define TILE32 8192
#define TRS 272
#define QKV_SMEM (3 * 4 * TILE32)   // 98304

// ---------------------------------------------------------------------------
// Merged QKV GEMM. grid (24, 64).
//   blockIdx.x < 16 : QK (bf16x3) + fused RoPE (+log2e on q) split epilogue
//   blockIdx.x >= 16: V  (fp16 single-term) + transpose epilogue -> (B,H,D,T)
// ---------------------------------------------------------------------------
__global__ __launch_bounds__(256, 2)
void qkv_gemm_kernel(const float* __restrict__ bqkv, RopeTab tab)
{
    extern __shared__ char smem_all[];

    const int tid = threadIdx.x;
    const int lane = tid & 31;
    const int wid = tid >> 5;
    const int wm = wid >> 1;
    const int wn = wid & 1;
    const int m0 = blockIdx.y * 128;
    const uint32_t sbase = smem_u32(smem_all);
    const uint32_t lrow = lane & 15;
    const int nk = KD / 32;             // 32

    float acc[2][8][4];
#pragma unroll
    for (int i = 0; i < 2; i++)
#pragma unroll
        for (int j = 0; j < 8; j++)
#pragma unroll
            for (int q = 0; q < 4; q++) acc[i][j][q] = 0.f;

    if (blockIdx.x < 16) {
        // ================= QK path: bf16 3-term =================
        const int n0 = blockIdx.x * 128;
        constexpr int STAGE = 4 * TILE32;

        auto issue_stage = [&](int kt) {
            if (kt < nk) {
                const uint32_t base = sbase + (kt % 3) * STAGE;
                const __nv_bfloat16* pAh = g_xh + (size_t)m0 * KD + kt * 32;
                const __nv_bfloat16* pAl = g_xl + (size_t)m0 * KD + kt * 32;
                const __nv_bfloat16* pBh = g_wqkh + (size_t)n0 * KD + kt * 32;
                const __nv_bfloat16* pBl = g_wqkl + (size_t)n0 * KD + kt * 32;
#pragma unroll
                for (int i = 0; i < 2; i++) {
                    int chunk = tid + i * 256;
                    int row = chunk >> 2, c = chunk & 3;
                    uint32_t off = SWOFF32(row, c);
                    const size_t g = (size_t)row * KD + c * 8;
                    CP16(base + off,              pAh + g);
                    CP16(base + TILE32 + off,     pAl + g);
                    CP16(base + 2 * TILE32 + off, pBh + g);
                    CP16(base + 3 * TILE32 + off, pBl + g);
                }
            }
            CP_COMMIT();
        };

        issue_stage(0);
        issue_stage(1);

        for (int kt = 0; kt < nk; kt++) {
            CP_WAITG(1);
            __syncthreads();
            const uint32_t aBase  = sbase + (kt % 3) * STAGE;
            const uint32_t alBase = aBase + TILE32;
            const uint32_t bBase  = aBase + 2 * TILE32;
            const uint32_t blBase = aBase + 3 * TILE32;
#pragma unroll
            for (int ks = 0; ks < 2; ks++) {
                const uint32_t cc = ks * 2 + (lane >> 4);
                uint32_t ahf[2][4], alf[2][4];
#pragma unroll
                for (int i = 0; i < 2; i++) {
                    int row = wm * 32 + i * 16 + lrow;
                    LDM_X4(ahf[i][0], ahf[i][1], ahf[i][2], ahf[i][3], aBase  + SWOFF32(row, cc));
                    LDM_X4(alf[i][0], alf[i][1], alf[i][2], alf[i][3], alBase + SWOFF32(row, cc));
                }
                if (ks == 0) issue_stage(kt + 2);
#pragma unroll
                for (int j2 = 0; j2 < 4; j2++) {
                    int row = wn * 64 + j2 * 16 + lrow;
                    uint32_t bh4[4], bl4[4];
                    LDM_X4(bh4[0], bh4[1], bh4[2], bh4[3], bBase  + SWOFF32(row, cc));
                    LDM_X4(bl4[0], bl4[1], bl4[2], bl4[3], blBase + SWOFF32(row, cc));
#pragma unroll
                    for (int o = 0; o < 2; o++)
#pragma unroll
                        for (int i = 0; i < 2; i++) {
                            int j = 2 * j2 + o;
                            MMA_BF(acc[i][j][0], acc[i][j][1], acc[i][j][2], acc[i][j][3],
                                   ahf[i][0], ahf[i][1], ahf[i][2], ahf[i][3], bh4[o], bh4[o + 2]);
                        }
#pragma unroll
                    for (int o = 0; o < 2; o++)
#pragma unroll
                        for (int i = 0; i < 2; i++) {
                            int j = 2 * j2 + o;
                            MMA_BF(acc[i][j][0], acc[i][j][1], acc[i][j][2], acc[i][j][3],
                                   alf[i][0], alf[i][1], alf[i][2], alf[i][3], bh4[o], bh4[o + 2]);
                        }
#pragma unroll
                    for (int o = 0; o < 2; o++)
#pragma unroll
                        for (int i = 0; i < 2; i++) {
                            int j = 2 * j2 + o;
                            MMA_BF(acc[i][j][0], acc[i][j][1], acc[i][j][2], acc[i][j][3],
                                   ahf[i][0], ahf[i][1], ahf[i][2], ahf[i][3], bl4[o], bl4[o + 2]);
                        }
                }
            }
        }

        // Epilogue: RoPE + split; q additionally scaled by log2e
        const int which = n0 >> 10;          // 0=q, 1=k
        const float l2e = (which == 0) ? LOG2E : 1.f;
        __nv_bfloat16* GH = (which == 0) ? g_qh : g_kh;
        __nv_bfloat16* GL = (which == 0) ? g_ql : g_kl;
        const int b = m0 >> 11;
        const int hh = ((n0 + wn * 64) & 1023) >> 6;
        const int bh = b * Hsz + hh;
        const int dbase = 2 * (lane & 3);
#pragma unroll
        for (int i = 0; i < 2; i++) {
#pragma unroll
            for (int hf = 0; hf < 2; hf++) {
                int m = m0 + wm * 32 + (lane >> 2) + i * 16 + hf * 8;
                int t = m & (Tsz - 1);
                size_t baseo = ((size_t)bh * Tsz + t) * Dsz;
#pragma unroll
                for (int j = 0; j < 4; j++) {
                    int n = n0 + wn * 64 + dbase + j * 8;
                    int d = n & 63;
                    float lowx  = acc[i][j][hf * 2]     + bqkv[n];
                    float lowy  = acc[i][j][hf * 2 + 1] + bqkv[n + 1];
                    float highx = acc[i][j + 4][hf * 2]     + bqkv[n + 32];
                    float highy = acc[i][j + 4][hf * 2 + 1] + bqkv[n + 33];
                    float c0f, s0f, c1f, s1f;
                    sincosf((float)t * tab.inv[d],     &s0f, &c0f);
                    sincosf((float)t * tab.inv[d + 1], &s1f, &c1f);
                    float nlx = (lowx * c0f - highx * s0f) * l2e;
                    float nhx = (highx * c0f + lowx * s0f) * l2e;
                    float nly = (lowy * c1f - highy * s1f) * l2e;
                    float nhy = (highy * c1f + lowy * s1f) * l2e;
                    __nv_bfloat16 hlx, llx, hly, lly, hhx, lhx, hhy, lhy;
                    split2(nlx, hlx, llx); split2(nly, hly, lly);
                    split2(nhx, hhx, lhx); split2(nhy, hhy, lhy);
                    *(__nv_bfloat162*)&GH[baseo + d]      = __nv_bfloat162(hlx, hly);
                    *(__nv_bfloat162*)&GL[baseo + d]      = __nv_bfloat162(llx, lly);
                    *(__nv_bfloat162*)&GH[baseo + d + 32] = __nv_bfloat162(hhx, hhy);
                    *(__nv_bfloat162*)&GL[baseo + d + 32] = __nv_bfloat162(lhx, lhy);
                }
            }
        }
    } else {
        // ================= V path: fp16 single-term =================
        const int n0 = (blockIdx.x - 16) * 128;
        constexpr int STAGE = 2 * TILE32;

        auto issue_stage = [&](int kt) {
            if (kt < nk) {
                const uint32_t base = sbase + (kt % 3) * STAGE;
                const __half* pAh = g_xhf + (size_t)m0 * KD + kt * 32;
                const __half* pBh = g_wvh + (size_t)n0 * KD + kt * 32;
#pragma unroll
                for (int i = 0; i < 2; i++) {
                    int chunk = tid + i * 256;
                    int row = chunk >> 2, c = chunk & 3;
                    uint32_t off = SWOFF32(row, c);
                    const size_t g = (size_t)row * KD + c * 8;
                    CP16(base + off,          pAh + g);
                    CP16(base + TILE32 + off, pBh + g);
                }
            }
            CP_COMMIT();
        };

        issue_stage(0);
        issue_stage(1);

        for (int kt = 0; kt < nk; kt++) {
            CP_WAITG(1);
            __syncthreads();
            const uint32_t aBase = sbase + (kt % 3) * STAGE;
            const uint32_t bBase = aBase + TILE32;
#pragma unroll
            for (int ks = 0; ks < 2; ks++) {
                const uint32_t cc = ks * 2 + (lane >> 4);
                uint32_t ahf[2][4];
#pragma unroll
                for (int i = 0; i < 2; i++) {
                    int row = wm * 32 + i * 16 + lrow;
                    LDM_X4(ahf[i][0], ahf[i][1], ahf[i][2], ahf[i][3], aBase + SWOFF32(row, cc));
                }
                if (ks == 0) issue_stage(kt + 2);
#pragma unroll
                for (int j2 = 0; j2 < 4; j2++) {
                    int row = wn * 64 + j2 * 16 + lrow;
                    uint32_t bh4[4];
                    LDM_X4(bh4[0], bh4[1], bh4[2], bh4[3], bBase + SWOFF32(row, cc));
#pragma unroll
                    for (int o = 0; o < 2; o++)
#pragma unroll
                        for (int i = 0; i < 2; i++) {
                            int j = 2 * j2 + o;
                            MMA_FP(acc[i][j][0], acc[i][j][1], acc[i][j][2], acc[i][j][3],
                                   ahf[i][0], ahf[i][1], ahf[i][2], ahf[i][3], bh4[o], bh4[o + 2]);
                        }
                }
            }
        }

        // V epilogue: smem transpose -> g_vt (B,H,D,T) fp16
        const int b = m0 >> 11;
        const int t0 = m0 & (Tsz - 1);
        __half* trs = (__half*)smem_all;
        __syncthreads();
#pragma unroll
        for (int i = 0; i < 2; i++)
#pragma unroll
            for (int hf = 0; hf < 2; hf++) {
                int ml = wm * 32 + (lane >> 2) + i * 16 + hf * 8;
#pragma unroll
                for (int j = 0; j < 8; j++) {
                    int nl = wn * 64 + 2 * (lane & 3) + j * 8;
                    float vx = acc[i][j][hf * 2]     + bqkv[2048 + n0 + nl];
                    float vy = acc[i][j][hf * 2 + 1] + bqkv[2048 + n0 + nl + 1];
                    trs[nl * 136 + ml]       = __float2half(vx);
                    trs[(nl + 1) * 136 + ml] = __float2half(vy);
                }
            }
        __syncthreads();
#pragma unroll
        for (int rr = 0; rr < 8; rr++) {
            int row = (tid >> 4) + rr * 16;
            int chunk = tid & 15;
            int n = n0 + row;
            int hh = n >> 6;
            int d = n & 63;
            float4 v = *(float4*)((char*)trs + row * TRS + chunk * 16);
            *(float4*)&g_vt[((size_t)(b * Hsz + hh) * Dsz + d) * Tsz + t0 + chunk * 8] = v;
        }
    }
}

// ---------------------------------------------------------------------------
// Output projection: fp16 single-term (yh @ Woh)
// ---------------------------------------------------------------------------
#define OUTP_SMEM (3 * 2 * TILE32)

__global__ __launch_bounds__(256, 2)
void outproj_kernel(const float* __restrict__ bias, float* __restrict__ Cout)
{
    extern __shared__ char smem_all[];
    const int tid = threadIdx.x;
    const int lane = tid & 31;
    const int wid = tid >> 5;
    const int wm = wid >> 1;
    const int wn = wid & 1;
    const int m0 = blockIdx.y * 128;
    const int n0 = blockIdx.x * 128;
    const uint32_t sbase = smem_u32(smem_all);
    const uint32_t lrow = lane & 15;
    const int nk = KD / 32;
    constexpr int STAGE = 2 * TILE32;

    auto issue_stage = [&](int kt) {
        if (kt < nk) {
            const uint32_t base = sbase + (kt % 3) * STAGE;
            const __half* pAh = g_yh + (size_t)m0 * KD + kt * 32;
            const __half* pBh = g_woh + (size_t)n0 * KD + kt * 32;
#pragma unroll
            for (int i = 0; i < 2; i++) {
                int chunk = tid + i * 256;
                int row = chunk >> 2, c = chunk & 3;
                uint32_t off = SWOFF32(row, c);
                const size_t g = (size_t)row * KD + c * 8;
                CP16(base + off,          pAh + g);
                CP16(base + TILE32 + off, pBh + g);
            }
        }
        CP_COMMIT();
    };

    issue_stage(0);
    issue_stage(1);

    float acc[2][8][4];
#pragma unroll
    for (int i = 0; i < 2; i++)
#pragma unroll
        for (int j = 0; j < 8; j++)
#pragma unroll
            for (int q = 0; q < 4; q++) acc[i][j][q] = 0.f;

    for (int kt = 0; kt < nk; kt++) {
        CP_WAITG(1);
        __syncthreads();
        const uint32_t aBase = sbase + (kt % 3) * STAGE;
        const uint32_t bBase = aBase + TILE32;
#pragma unroll
        for (int ks = 0; ks < 2; ks++) {
            const uint32_t cc = ks * 2 + (lane >> 4);
            uint32_t ahf[2][4];
#pragma unroll
            for (int i = 0; i < 2; i++) {
                int row = wm * 32 + i * 16 + lrow;
                LDM_X4(ahf[i][0], ahf[i][1], ahf[i][2], ahf[i][3], aBase + SWOFF32(row, cc));
            }
            if (ks == 0) issue_stage(kt + 2);
#pragma unroll
            for (int j2 = 0; j2 < 4; j2++) {
                int row = wn * 64 + j2 * 16 + lrow;
                uint32_t bh4[4];
                LDM_X4(bh4[0], bh4[1], bh4[2], bh4[3], bBase + SWOFF32(row, cc));
#pragma unroll
                for (int o = 0; o < 2; o++)
#pragma unroll
                    for (int i = 0; i < 2; i++) {
                        int j = 2 * j2 + o;
                        MMA_FP(acc[i][j][0], acc[i][j][1], acc[i][j][2], acc[i][j][3],
                               ahf[i][0], ahf[i][1], ahf[i][2], ahf[i][3], bh4[o], bh4[o + 2]);
                    }
            }
        }
    }

    const int mwb = m0 + wm * 32 + (lane >> 2);
    const int nwb = n0 + wn * 64 + 2 * (lane & 3);
#pragma unroll
    for (int i = 0; i < 2; i++)
#pragma unroll
        for (int j = 0; j < 8; j++) {
            int n = nwb + j * 8;
            float bx = bias[n], by = bias[n + 1];
#pragma unroll
            for (int hf = 0; hf < 2; hf++) {
                int m = mwb + i * 16 + hf * 8;
                *(float2*)&Cout[(size_t)m * Csz + n] =
                    make_float2(acc[i][j][hf * 2] + bx, acc[i][j][hf * 2 + 1] + by);
            }
        }
}

// ---------------------------------------------------------------------------
// HMMA flash attention, causal. BM=128 (8 warps x 16 rows), BN=64, D=64.
// S: bf16x3 (ex2 softmax). PV: fp16 single-term. 3-stage KV.
// Per-warp skip of fully-masked tiles; lsum reduced once in the epilogue.
// ---------------------------------------------------------------------------
#define KVSTAGE 24576
#define ATT_SMEM (32768 + 3 * KVSTAGE)      // 106496

__global__ __launch_bounds__(256, 2)
void attn_hmma_kernel()
{
    extern __shared__ char asmem[];

    const int tid = threadIdx.x;
    const int lane = tid & 31;
    const int wid = tid >> 5;              // 0..7
    const int q0 = (int)(gridDim.x - 1 - blockIdx.x) * 128;
    const int bh = blockIdx.y;
    const uint32_t sb = smem_u32(asmem);
    const uint32_t qhB = sb, qlB = sb + 16384;
    const uint32_t lrow = lane & 15;
    const int nt = q0 / 64 + 2;
    const int wrow_max = q0 + wid * 16 + 15;   // last q-row owned by this warp

    {
        const size_t qg = ((size_t)bh * Tsz + q0) * Dsz;
#pragma unroll
        for (int i = 0; i < 4; i++) {
            int chunk = tid + i * 256;
            int row = chunk >> 3, c = chunk & 7;
            uint32_t off = SWOFF(row, c);
            CP16(qhB + off, g_qh + qg + (size_t)row * Dsz + c * 8);
            CP16(qlB + off, g_ql + qg + (size_t)row * Dsz + c * 8);
        }
    }

    auto issue_kv = [&](int jt) {
        if (jt < nt) {
            const int js = jt * 64;
            const uint32_t base = sb + 32768 + (jt % 3) * KVSTAGE;
            const size_t kg = ((size_t)bh * Tsz + js) * Dsz;
            const size_t vg = (size_t)bh * Dsz * Tsz + js;
#pragma unroll
            for (int i = 0; i < 2; i++) {
                int chunk = tid + i * 256;
                int row = chunk >> 3, c = chunk & 7;
                uint32_t off = SWOFF(row, c);
                CP16(base + off,         g_kh + kg + (size_t)row * Dsz + c * 8);
                CP16(base + 8192 + off,  g_kl + kg + (size_t)row * Dsz + c * 8);
                CP16(base + 16384 + off, g_vt + vg + (size_t)row * Tsz + c * 8);
            }
        }
        CP_COMMIT();
    };

    issue_kv(0);
    issue_kv(1);

    float mrow[2] = { -INFINITY, -INFINITY };
    float lsum[2] = { 0.f, 0.f };             // per-thread partial (quad-reduced at end)
    float oa[8][4];
#pragma unroll
    for (int j = 0; j < 8; j++)
#pragma unroll
        for (int q = 0; q < 4; q++) oa[j][q] = 0.f;

    for (int jt = 0; jt < nt; jt++) {
        CP_WAITG(1);
        __syncthreads();
        issue_kv(jt + 2);                      // all threads participate

        const int js = jt * 64;
        if (js > wrow_max) continue;           // tile fully masked for this warp

        const uint32_t kvb = sb + 32768 + (jt % 3) * KVSTAGE;
        const uint32_t khB = kvb, klB = kvb + 8192;
        const uint32_t vhB = kvb + 16384;

        float s[8][4];
#pragma unroll
        for (int j = 0; j < 8; j++)
#pragma unroll
            for (int q = 0; q < 4; q++) s[j][q] = 0.f;

#pragma unroll
        for (int ks = 0; ks < 4; ks++) {
            const uint32_t cc = ks * 2 + (lane >> 4);
            uint32_t qhf[4], qlf[4];
            {
                int row = wid * 16 + lrow;
                LDM_X4(qhf[0], qhf[1], qhf[2], qhf[3], qhB + SWOFF(row, cc));
                LDM_X4(qlf[0], qlf[1], qlf[2], qlf[3], qlB + SWOFF(row, cc));
            }
#pragma unroll
            for (int jp = 0; jp < 2; jp++) {
                uint32_t khf[2][4], klf[2][4];
#pragma unroll
                for (int u = 0; u < 2; u++) {
                    int row = (jp * 2 + u) * 16 + lrow;
                    uint32_t off = SWOFF(row, cc);
                    LDM_X4(khf[u][0], khf[u][1], khf[u][2], khf[u][3], khB + off);
                    LDM_X4(klf[u][0], klf[u][1], klf[u][2], klf[u][3], klB + off);
                }
#pragma unroll
                for (int u = 0; u < 2; u++)
#pragma unroll
                    for (int o = 0; o < 2; o++) {
                        int j = 2 * (jp * 2 + u) + o;
                        MMA_BF(s[j][0], s[j][1], s[j][2], s[j][3],
                               qhf[0], qhf[1], qhf[2], qhf[3], khf[u][o], khf[u][o + 2]);
                    }
#pragma unroll
                for (int u = 0; u < 2; u++)
#pragma unroll
                    for (int o = 0; o < 2; o++) {
                        int j = 2 * (jp * 2 + u) + o;
                        MMA_BF(s[j][0], s[j][1], s[j][2], s[j][3],
                               qlf[0], qlf[1], qlf[2], qlf[3], khf[u][o], khf[u][o + 2]);
                    }
#pragma unroll
                for (int u = 0; u < 2; u++)
#pragma unroll
                    for (int o = 0; o < 2; o++) {
                        int j = 2 * (jp * 2 + u) + o;
                        MMA_BF(s[j][0], s[j][1], s[j][2], s[j][3],
                               qhf[0], qhf[1], qhf[2], qhf[3], klf[u][o], klf[u][o + 2]);
                    }
            }
        }

        if (js >= q0) {
#pragma unroll
            for (int j = 0; j < 8; j++)
#pragma unroll
                for (int q = 0; q < 4; q++) {
                    int col = js + j * 8 + 2 * (lane & 3) + (q & 1);
                    int row = q0 + wid * 16 + (lane >> 2) + (q >> 1) * 8;
                    if (col > row) s[j][q] = -INFINITY;
                }
        }

        // Online softmax in log2 domain (q pre-scaled by log2e)
#pragma unroll
        for (int h = 0; h < 2; h++) {
            float mx = -INFINITY;
#pragma unroll
            for (int j = 0; j < 8; j++)
                mx = fmaxf(mx, fmaxf(s[j][2 * h], s[j][2 * h + 1]));
            mx = fmaxf(mx, __shfl_xor_sync(0xffffffffu, mx, 1));
            mx = fmaxf(mx, __shfl_xor_sync(0xffffffffu, mx, 2));
            float nm = fmaxf(mrow[h], mx);
            float alpha = ex2f(mrow[h] - nm);
            float sum = 0.f;
#pragma unroll
            for (int j = 0; j < 8; j++) {
                float p0 = ex2f(s[j][2 * h] - nm);
                float p1 = ex2f(s[j][2 * h + 1] - nm);
                s[j][2 * h] = p0; s[j][2 * h + 1] = p1;
                sum += p0 + p1;
            }
            lsum[h] = lsum[h] * alpha + sum;   // per-thread partial
            mrow[h] = nm;
#pragma unroll
            for (int j = 0; j < 8; j++) {
                oa[j][2 * h] *= alpha;
                oa[j][2 * h + 1] *= alpha;
            }
        }

        // O += P_fp16 * Vh   (single term)
#pragma unroll
        for (int kt2 = 0; kt2 < 4; kt2++) {
            uint32_t pa[4];
            {
                __half2 t0 = __floats2half2_rn(s[2 * kt2][0],     s[2 * kt2][1]);
                __half2 t1 = __floats2half2_rn(s[2 * kt2][2],     s[2 * kt2][3]);
                __half2 t2 = __floats2half2_rn(s[2 * kt2 + 1][0], s[2 * kt2 + 1][1]);
                __half2 t3 = __floats2half2_rn(s[2 * kt2 + 1][2], s[2 * kt2 + 1][3]);
                pa[0] = *(uint32_t*)&t0; pa[1] = *(uint32_t*)&t1;
                pa[2] = *(uint32_t*)&t2; pa[3] = *(uint32_t*)&t3;
            }
            const uint32_t cc = kt2 * 2 + (lane >> 4);
#pragma unroll
            for (int j2 = 0; j2 < 4; j2++) {
                int row = j2 * 16 + lrow;
                uint32_t off = SWOFF(row, cc);
                uint32_t vhf[4];
                LDM_X4(vhf[0], vhf[1], vhf[2], vhf[3], vhB + off);
#pragma unroll
                for (int o = 0; o < 2; o++) {
                    int j = 2 * j2 + o;
                    MMA_FP(oa[j][0], oa[j][1], oa[j][2], oa[j][3],
                           pa[0], pa[1], pa[2], pa[3], vhf[o], vhf[o + 2]);
                }
            }
        }
    }

    // Epilogue: quad-reduce lsum, y = O / l -> yh fp16
    {
        const int b = bh >> 4, hh = bh & 15;
#pragma unroll
        for (int h = 0; h < 2; h++) {
            float lt = lsum[h];
            lt += __shfl_xor_sync(0xffffffffu, lt, 1);
            lt += __shfl_xor_sync(0xffffffffu, lt, 2);
            int t = q0 + wid * 16 + (lane >> 2) + h * 8;
            float invl = 1.f / lt;
            size_t rb = ((size_t)b * Tsz + t) * KD + hh * Dsz;
#pragma unroll
            for (int j = 0; j < 8; j++) {
                int d = j * 8 + 2 * (lane & 3);
                float y0 = oa[j][2 * h] * invl;
                float y1 = oa[j][2 * h + 1] * invl;
                *(__half2*)&g_yh[rb + d] = __floats2half2_rn(y0, y1);
            }
        }
    }
}

// ---------------------------------------------------------------------------
extern "C" void kernel_launch(void* const* d_in, const int* in_sizes, int n_in,
                              void* d_out, int out_size)
{
    const float* x    = (const float*)d_in[0];
    const float* Wqkv = (const float*)d_in[1];
    const float* bqkv = (const float*)d_in[2];
    const float* Wout = (const float*)d_in[3];
    const float* bout = (const float*)d_in[4];
    float* out = (float*)d_out;

    RopeTab tab;
    for (int i = 0; i < 32; i++)
        tab.inv[i] = (float)exp(-(double)(2 * i) / 64.0 * log(10000.0));

    // 0) merged conversions (one launch)
    convert_kernel<<<NB_SPLITX + NB_WQKV + NB_WOUT, 256>>>(x, Wqkv, Wout);

    // 1) Merged QKV projection (QK bf16x3 + V fp16 single-term)
    {
        cudaFuncSetAttribute(qkv_gemm_kernel, cudaFuncAttributeMaxDynamicSharedMemorySize, QKV_SMEM);
        dim3 grid(24, M1 / 128);              // (24, 64)
        qkv_gemm_kernel<<<grid, 256, QKV_SMEM>>>(bqkv, tab);
    }

    // 2) HMMA causal flash attention -> yh
    {
        cudaFuncSetAttribute(attn_hmma_kernel, cudaFuncAttributeMaxDynamicSharedMemorySize, ATT_SMEM);
        dim3 grid(Tsz / 128, Bsz * Hsz);      // (16, 64)
        attn_hmma_kernel<<<grid, 256, ATT_SMEM>>>();
    }

    // 3) Output projection (fp16 single-term) -> d_out
    {
        cudaFuncSetAttribute(outproj_kernel, cudaFuncAttributeMaxDynamicSharedMemorySize, OUTP_SMEM);
        dim3 grid(Csz / 128, M1 / 128);       // (8, 64)
        outproj_kernel<<<grid, 256, OUTP_SMEM>>>(bout, out);
    }
}